// round 7
// baseline (speedup 1.0000x reference)
#include <cuda_runtime.h>
#include <cuda_bf16.h>
#include <cstdint>

#define BATCH 8
#define MM 256
#define NN 256
#define CI 64
#define CO 64
#define KK 4
#define MODES 32

typedef unsigned long long u64;

// ---------------- scratch ----------------
__device__ float2 g_wy [BATCH*MODES*CI*CO];
__device__ float2 g_wx [BATCH*MODES*CI*CO];
__device__ float2 g_XfY[BATCH*MODES*MM*CI];
__device__ float2 g_XfX[BATCH*MODES*NN*CI];
__device__ float2 g_YfY[BATCH*MODES*MM*CO];
__device__ float2 g_YfX[BATCH*MODES*NN*CO];
__device__ float  g_xsum [(size_t)BATCH*MM*NN*CO];
__device__ float  g_xsum2[(size_t)BATCH*MM*NN*CO];

// MLP weight image
#define W_W1HI 0
#define W_W1LO 36864
#define W_W2HI 73728
#define W_W2LO 107520
#define W_TOT  141312
__device__ __align__(16) unsigned char g_Wimg[W_TOT];

// transform tables (split bf16, smem-image layout)
#define T_ST   520
#define T_LOB  33280
#define T_TOT  66560
__device__ __align__(16) unsigned char g_TY[T_TOT];
__device__ __align__(16) unsigned char g_TX[T_TOT];
#define S_ST   136
#define S_LOB  34816
#define S_TOT  69632
__device__ __align__(16) unsigned char g_SY[S_TOT];
__device__ __align__(16) unsigned char g_SX[S_TOT];

// ---------------- bf16 helpers ----------------
__device__ __forceinline__ void cvt_pair(float v0, float v1, uint32_t& hi, uint32_t& lo) {
    __nv_bfloat16 h0 = __float2bfloat16(v0), h1 = __float2bfloat16(v1);
    float r0 = v0 - __bfloat162float(h0);
    float r1 = v1 - __bfloat162float(h1);
    hi = (uint32_t)__bfloat16_as_ushort(h0) | ((uint32_t)__bfloat16_as_ushort(h1) << 16);
    lo = (uint32_t)__bfloat16_as_ushort(__float2bfloat16(r0))
       | ((uint32_t)__bfloat16_as_ushort(__float2bfloat16(r1)) << 16);
}
__device__ __forceinline__ void mma_bf16(float* d, const uint32_t* a, uint32_t b0, uint32_t b1) {
    asm volatile(
        "mma.sync.aligned.m16n8k16.row.col.f32.bf16.bf16.f32 "
        "{%0,%1,%2,%3},{%4,%5,%6,%7},{%8,%9},{%0,%1,%2,%3};"
        : "+f"(d[0]), "+f"(d[1]), "+f"(d[2]), "+f"(d[3])
        : "r"(a[0]), "r"(a[1]), "r"(a[2]), "r"(a[3]), "r"(b0), "r"(b1));
}
__device__ __forceinline__ void wr_split(unsigned char* phi, unsigned char* plo, float v) {
    __nv_bfloat16 h = __float2bfloat16(v);
    float r = v - __bfloat162float(h);
    *(unsigned short*)phi = __bfloat16_as_ushort(h);
    *(unsigned short*)plo = __bfloat16_as_ushort(__float2bfloat16(r));
}

// ---------------- K0: spectral weights ----------------
__global__ void k_weights(const float* __restrict__ att,
                          const float* __restrict__ fwy,
                          const float* __restrict__ fwx) {
    int gid = blockIdx.x * 256 + threadIdx.x;
    int o = gid & 63, i = (gid >> 6) & 63, f = (gid >> 12) & 31, b = gid >> 17;
    float a0 = att[b*KK+0], a1 = att[b*KK+1], a2 = att[b*KK+2], a3 = att[b*KK+3];
    const int ks = CI*CO*MODES*2;
    int base = ((i*CO + o)*MODES + f)*2;
    float yr, yi, xr, xi;
    yr = a0*fwy[base   ] + a1*fwy[base+ks   ] + a2*fwy[base+2*ks  ] + a3*fwy[base+3*ks  ];
    yi = a0*fwy[base+1 ] + a1*fwy[base+ks+1 ] + a2*fwy[base+2*ks+1] + a3*fwy[base+3*ks+1];
    xr = a0*fwx[base   ] + a1*fwx[base+ks   ] + a2*fwx[base+2*ks  ] + a3*fwx[base+3*ks  ];
    xi = a0*fwx[base+1 ] + a1*fwx[base+ks+1 ] + a2*fwx[base+2*ks+1] + a3*fwx[base+3*ks+1];
    g_wy[gid] = make_float2(yr, yi);
    g_wx[gid] = make_float2(xr, xi);
}

// ---------------- K0b: MLP weight image ----------------
__global__ void k_wprep(const float* __restrict__ w1, const float* __restrict__ w2) {
    int gid = blockIdx.x * 256 + threadIdx.x;
    if (gid < 16384) {
        int i = gid >> 8, j = gid & 255;
        uint32_t off = (uint32_t)j*144 + (uint32_t)i*2;
        wr_split(g_Wimg + W_W1HI + off, g_Wimg + W_W1LO + off, w1[gid]);
    } else {
        int idx = gid - 16384;
        int j = idx >> 6, o = idx & 63;
        uint32_t off = (uint32_t)o*528 + (uint32_t)j*2;
        wr_split(g_Wimg + W_W2HI + off, g_Wimg + W_W2LO + off, w2[idx]);
    }
}

// ---------------- K0c: transform tables ----------------
__global__ void k_tprep() {
    int gid = blockIdx.x * 256 + threadIdx.x;
    int sel = gid >> 14;
    int idx = gid & 16383;
    const float inv = 0.04428074428f;
    if (sel == 0) {
        int r = idx >> 8, k = idx & 255;
        int f = r >> 1;
        float ang = (float)((f*k) & 255) * (1.0f/128.0f);
        float v = (r & 1) ? -0.0625f*sinpif(ang) : 0.0625f*cospif(ang);
        uint32_t off = (uint32_t)r*T_ST + (uint32_t)k*2;
        wr_split(g_TY + off, g_TY + T_LOB + off, v);
    } else if (sel == 1) {
        int r = idx >> 8, k = idx & 255;
        int f = r >> 1;
        float v;
        if (r & 1) v = -2.0f*inv*sinpif((float)((f*k) % 510) * (1.0f/255.0f));
        else       v = (k == 0) ? inv : ((k == 255) ? ((f & 1) ? -inv : inv) : 0.0f);
        uint32_t off = (uint32_t)r*T_ST + (uint32_t)k*2;
        wr_split(g_TX + off, g_TX + T_LOB + off, v);
    } else if (sel == 2) {
        int r = idx >> 6, k = idx & 63;
        int f = k >> 1;
        float ang = (float)((f*r) & 255) * (1.0f/128.0f);
        float v = (k & 1) ? -0.125f*sinpif(ang)
                          : ((f == 0) ? 0.0625f : 0.125f)*cospif(ang);
        uint32_t off = (uint32_t)r*S_ST + (uint32_t)k*2;
        wr_split(g_SY + off, g_SY + S_LOB + off, v);
    } else {
        int r = idx >> 6, k = idx & 63;
        int f = k >> 1;
        float ang = (float)((f*r) % 510) * (1.0f/255.0f);
        float v = (k & 1) ? -2.0f*inv*sinpif(ang)
                          : ((f == 0) ? inv : 2.0f*inv)*cospif(ang);
        uint32_t off = (uint32_t)r*S_ST + (uint32_t)k*2;
        wr_split(g_SX + off, g_SX + S_LOB + off, v);
    }
}

// ---------------- K1: forward transforms via mma.sync (8 mn per block) ----------------
#define FW_B   66560
#define FW_TOT 133120
__global__ void __launch_bounds__(256) k_fwd_mma(const float* __restrict__ x) {
    extern __shared__ __align__(16) unsigned char sm[];
    int t = threadIdx.x, w = t >> 5, l = t & 31, l4 = l >> 2, lq = l & 3;
    int z = blockIdx.x;             // 512 = 2 branch * 8 b * 32 groups
    int branch = z >> 8;
    int grp = z & 255;
    int b = grp >> 5, g = grp & 31;

    // copy table once per block
    {
        const float4* src = (const float4*)(branch ? g_TX : g_TY);
        float4* dst = (float4*)sm;
        for (int i = t; i < T_TOT/16; i += 256) dst[i] = src[i];
    }

    int mt = w & 3, nh = w >> 2;
    const unsigned char* Th = sm;
    const unsigned char* Tl = sm + T_LOB;
    const unsigned char* Bh = sm + FW_B;
    const unsigned char* Bl = sm + FW_B + T_LOB;
    float* outb = (float*)(branch ? g_XfX : g_XfY);

    for (int it8 = 0; it8 < 8; it8++) {
        int mn = g*8 + it8;
        __syncthreads();            // protect B buffer (and cover table copy on iter 0)
        // stage B = X^T [ch][k]
        #pragma unroll
        for (int it = 0; it < 8; it++) {
            int flat = it*256 + t;
            int kp = flat >> 4, c4 = flat & 15;
            const float* p0;
            size_t stride1;
            if (branch == 0) {
                p0 = x + ((size_t)(b*256 + mn))*16384 + (size_t)(2*kp)*64 + c4*4;
                stride1 = 64;
            } else {
                p0 = x + (((size_t)(b*256 + 2*kp))*256 + mn)*64 + c4*4;
                stride1 = 16384;
            }
            float4 r0 = *(const float4*)p0;
            float4 r1 = *(const float4*)(p0 + stride1);
            float a0[4] = {r0.x, r0.y, r0.z, r0.w};
            float a1[4] = {r1.x, r1.y, r1.z, r1.w};
            #pragma unroll
            for (int j = 0; j < 4; j++) {
                uint32_t hi, lo;
                cvt_pair(a0[j], a1[j], hi, lo);
                uint32_t off = (uint32_t)(4*c4 + j)*T_ST + (uint32_t)kp*4;
                *(uint32_t*)(sm + FW_B + off)         = hi;
                *(uint32_t*)(sm + FW_B + T_LOB + off) = lo;
            }
        }
        __syncthreads();

        float c[4][4];
        #pragma unroll
        for (int j = 0; j < 4; j++)
            #pragma unroll
            for (int q = 0; q < 4; q++) c[j][q] = 0.f;

        #pragma unroll
        for (int kk = 0; kk < 16; kk++) {
            int kof = kk*32 + lq*4;
            int r0 = mt*16 + l4;
            uint32_t ah[4], al[4];
            ah[0] = *(const uint32_t*)(Th + r0*T_ST + kof);
            ah[1] = *(const uint32_t*)(Th + (r0+8)*T_ST + kof);
            ah[2] = *(const uint32_t*)(Th + r0*T_ST + kof + 16);
            ah[3] = *(const uint32_t*)(Th + (r0+8)*T_ST + kof + 16);
            al[0] = *(const uint32_t*)(Tl + r0*T_ST + kof);
            al[1] = *(const uint32_t*)(Tl + (r0+8)*T_ST + kof);
            al[2] = *(const uint32_t*)(Tl + r0*T_ST + kof + 16);
            al[3] = *(const uint32_t*)(Tl + (r0+8)*T_ST + kof + 16);
            #pragma unroll
            for (int j = 0; j < 4; j++) {
                int ncol = nh*32 + j*8 + l4;
                uint32_t bh0 = *(const uint32_t*)(Bh + ncol*T_ST + kof);
                uint32_t bh1 = *(const uint32_t*)(Bh + ncol*T_ST + kof + 16);
                uint32_t bl0 = *(const uint32_t*)(Bl + ncol*T_ST + kof);
                uint32_t bl1 = *(const uint32_t*)(Bl + ncol*T_ST + kof + 16);
                mma_bf16(c[j], ah, bh0, bh1);
                mma_bf16(c[j], ah, bl0, bl1);
                mma_bf16(c[j], al, bh0, bh1);
            }
        }

        #pragma unroll
        for (int j = 0; j < 4; j++) {
            int ch = nh*32 + j*8 + 2*lq;
            int r0 = mt*16 + l4, r1 = r0 + 8;
            size_t base0 = ((size_t)(b*32 + (r0 >> 1))*256 + mn)*128 + ch*2 + (r0 & 1);
            size_t base1 = ((size_t)(b*32 + (r1 >> 1))*256 + mn)*128 + ch*2 + (r1 & 1);
            outb[base0]     = c[j][0];
            outb[base0 + 2] = c[j][1];
            outb[base1]     = c[j][2];
            outb[base1 + 2] = c[j][3];
        }
    }
}

// ---------------- K2: complex GEMM via mma.sync (unchanged, proven) ----------------
#define MX_AHI 0
#define MX_ALO 69632
#define MX_WHI 139264
#define MX_WLO 174080
#define MX_TOT 208896

__global__ void __launch_bounds__(256) k_mix_mma() {
    extern __shared__ __align__(16) unsigned char sm[];
    int t = threadIdx.x, w = t >> 5, l = t & 31, l4 = l >> 2, lq = l & 3;
    int z = blockIdx.x, branch = z >> 8, bf = z & 255;
    const float2* A = (branch ? g_XfX : g_XfY) + (size_t)bf*MM*CI;
    const float2* W = (branch ? g_wx  : g_wy ) + (size_t)bf*CI*CO;
    float2*       C = (branch ? g_YfX : g_YfY) + (size_t)bf*MM*CO;

    {
        const float4* Af = (const float4*)A;
        #pragma unroll
        for (int it = 0; it < 32; it++) {
            int ft = it*256 + t;
            int row = ft >> 5, c4 = ft & 31;
            float4 v = Af[ft];
            uint32_t h01, l01, h23, l23;
            cvt_pair(v.x, v.y, h01, l01);
            cvt_pair(v.z, v.w, h23, l23);
            *(uint2*)(sm + MX_AHI + row*272 + c4*8) = make_uint2(h01, h23);
            *(uint2*)(sm + MX_ALO + row*272 + c4*8) = make_uint2(l01, l23);
        }
    }
    {
        #pragma unroll
        for (int it = 0; it < 16; it++) {
            int flat = it*256 + t;
            int i = flat >> 6, o = flat & 63;
            float2 wv = W[flat];
            uint32_t ha, la, hb, lb;
            cvt_pair(wv.x, -wv.y, ha, la);
            cvt_pair(wv.y,  wv.x, hb, lb);
            *(uint32_t*)(sm + MX_WHI + (2*o  )*272 + i*4) = ha;
            *(uint32_t*)(sm + MX_WHI + (2*o+1)*272 + i*4) = hb;
            *(uint32_t*)(sm + MX_WLO + (2*o  )*272 + i*4) = la;
            *(uint32_t*)(sm + MX_WLO + (2*o+1)*272 + i*4) = lb;
        }
    }
    __syncthreads();

    float acc[2][16][4];
    #pragma unroll
    for (int mt = 0; mt < 2; mt++)
        #pragma unroll
        for (int j2 = 0; j2 < 16; j2++)
            #pragma unroll
            for (int q = 0; q < 4; q++) acc[mt][j2][q] = 0.f;

    int m0 = w*32;
    #pragma unroll
    for (int kt = 0; kt < 8; kt++) {
        int kof = kt*32 + lq*4;
        uint32_t ah[2][4], al[2][4];
        #pragma unroll
        for (int mt = 0; mt < 2; mt++) {
            int row = m0 + mt*16 + l4;
            ah[mt][0] = *(const uint32_t*)(sm + MX_AHI + row*272 + kof);
            ah[mt][1] = *(const uint32_t*)(sm + MX_AHI + (row+8)*272 + kof);
            ah[mt][2] = *(const uint32_t*)(sm + MX_AHI + row*272 + kof + 16);
            ah[mt][3] = *(const uint32_t*)(sm + MX_AHI + (row+8)*272 + kof + 16);
            al[mt][0] = *(const uint32_t*)(sm + MX_ALO + row*272 + kof);
            al[mt][1] = *(const uint32_t*)(sm + MX_ALO + (row+8)*272 + kof);
            al[mt][2] = *(const uint32_t*)(sm + MX_ALO + row*272 + kof + 16);
            al[mt][3] = *(const uint32_t*)(sm + MX_ALO + (row+8)*272 + kof + 16);
        }
        #pragma unroll
        for (int j2 = 0; j2 < 16; j2++) {
            int nrow = j2*8 + l4;
            uint32_t bh0 = *(const uint32_t*)(sm + MX_WHI + nrow*272 + kof);
            uint32_t bh1 = *(const uint32_t*)(sm + MX_WHI + nrow*272 + kof + 16);
            uint32_t bl0 = *(const uint32_t*)(sm + MX_WLO + nrow*272 + kof);
            uint32_t bl1 = *(const uint32_t*)(sm + MX_WLO + nrow*272 + kof + 16);
            #pragma unroll
            for (int mt = 0; mt < 2; mt++) {
                mma_bf16(acc[mt][j2], ah[mt], bh0, bh1);
                mma_bf16(acc[mt][j2], ah[mt], bl0, bl1);
                mma_bf16(acc[mt][j2], al[mt], bh0, bh1);
            }
        }
    }

    float* Cf = (float*)C;
    #pragma unroll
    for (int mt = 0; mt < 2; mt++) {
        #pragma unroll
        for (int j2 = 0; j2 < 16; j2++) {
            int row = m0 + mt*16 + l4;
            int col = j2*8 + 2*lq;
            *(float2*)(Cf + (size_t)row*128 + col)     = make_float2(acc[mt][j2][0], acc[mt][j2][1]);
            *(float2*)(Cf + (size_t)(row+8)*128 + col) = make_float2(acc[mt][j2][2], acc[mt][j2][3]);
        }
    }
}

// ---------------- K3: inverse transforms via mma.sync (8 mn per block) ----------------
#define IV_B   69632
#define IV_TOT 87040
#define IV_BLO 8704
__global__ void __launch_bounds__(256) k_inv_mma() {
    extern __shared__ __align__(16) unsigned char sm[];
    int t = threadIdx.x, w = t >> 5, l = t & 31, l4 = l >> 2, lq = l & 3;
    int z = blockIdx.x;             // 512
    int branch = z >> 8;
    int grp = z & 255;
    int b = grp >> 5, g = grp & 31;

    {
        const float4* src = (const float4*)(branch ? g_SX : g_SY);
        float4* dst = (float4*)sm;
        for (int i = t; i < S_TOT/16; i += 256) dst[i] = src[i];
    }

    const unsigned char* Sh = sm;
    const unsigned char* Sl = sm + S_LOB;
    const unsigned char* Bh = sm + IV_B;
    const unsigned char* Bl = sm + IV_B + IV_BLO;
    const float2* Y = (branch ? g_YfX : g_YfY);
    float* outb = branch ? g_xsum2 : g_xsum;

    for (int it8 = 0; it8 < 8; it8++) {
        int mn = g*8 + it8;
        __syncthreads();
        #pragma unroll
        for (int it = 0; it < 8; it++) {
            int flat = it*256 + t;
            int f = flat >> 6, ch = flat & 63;
            float2 v = Y[((size_t)(b*32 + f)*256 + mn)*64 + ch];
            uint32_t hi, lo;
            cvt_pair(v.x, v.y, hi, lo);
            uint32_t off = (uint32_t)ch*S_ST + (uint32_t)f*4;
            *(uint32_t*)(sm + IV_B + off)          = hi;
            *(uint32_t*)(sm + IV_B + IV_BLO + off) = lo;
        }
        __syncthreads();

        float c[2][8][4];
        #pragma unroll
        for (int mt = 0; mt < 2; mt++)
            #pragma unroll
            for (int j = 0; j < 8; j++)
                #pragma unroll
                for (int q = 0; q < 4; q++) c[mt][j][q] = 0.f;

        #pragma unroll
        for (int kk = 0; kk < 4; kk++) {
            int kof = kk*32 + lq*4;
            uint32_t ah[2][4], al[2][4];
            #pragma unroll
            for (int mt = 0; mt < 2; mt++) {
                int r0 = (w + mt*8)*16 + l4;
                ah[mt][0] = *(const uint32_t*)(Sh + r0*S_ST + kof);
                ah[mt][1] = *(const uint32_t*)(Sh + (r0+8)*S_ST + kof);
                ah[mt][2] = *(const uint32_t*)(Sh + r0*S_ST + kof + 16);
                ah[mt][3] = *(const uint32_t*)(Sh + (r0+8)*S_ST + kof + 16);
                al[mt][0] = *(const uint32_t*)(Sl + r0*S_ST + kof);
                al[mt][1] = *(const uint32_t*)(Sl + (r0+8)*S_ST + kof);
                al[mt][2] = *(const uint32_t*)(Sl + r0*S_ST + kof + 16);
                al[mt][3] = *(const uint32_t*)(Sl + (r0+8)*S_ST + kof + 16);
            }
            #pragma unroll
            for (int j = 0; j < 8; j++) {
                int ncol = j*8 + l4;
                uint32_t bh0 = *(const uint32_t*)(Bh + ncol*S_ST + kof);
                uint32_t bh1 = *(const uint32_t*)(Bh + ncol*S_ST + kof + 16);
                uint32_t bl0 = *(const uint32_t*)(Bl + ncol*S_ST + kof);
                uint32_t bl1 = *(const uint32_t*)(Bl + ncol*S_ST + kof + 16);
                #pragma unroll
                for (int mt = 0; mt < 2; mt++) {
                    mma_bf16(c[mt][j], ah[mt], bh0, bh1);
                    mma_bf16(c[mt][j], ah[mt], bl0, bl1);
                    mma_bf16(c[mt][j], al[mt], bh0, bh1);
                }
            }
        }

        #pragma unroll
        for (int mt = 0; mt < 2; mt++) {
            #pragma unroll
            for (int j = 0; j < 8; j++) {
                int col = j*8 + 2*lq;
                int r0 = (w + mt*8)*16 + l4, r1 = r0 + 8;
                size_t a0, a1;
                if (branch == 0) {
                    a0 = (((size_t)(b*256 + mn))*256 + r0)*64 + col;
                    a1 = (((size_t)(b*256 + mn))*256 + r1)*64 + col;
                } else {
                    a0 = (((size_t)(b*256 + r0))*256 + mn)*64 + col;
                    a1 = (((size_t)(b*256 + r1))*256 + mn)*64 + col;
                }
                *(float2*)(outb + a0) = make_float2(c[mt][j][0], c[mt][j][1]);
                *(float2*)(outb + a1) = make_float2(c[mt][j][2], c[mt][j][3]);
            }
        }
    }
}

// ---------------- K4: MLP via mma.sync + LayerNorm (4 tiles per block) ----------------
#define SA_HI   0
#define SA_LO   36864
#define SW_BASE 73728
#define S_B1    215040
#define S_B2    216064
#define S_GAM   216320
#define S_BET   216576
#define SM_MLP  216832

__global__ void __launch_bounds__(256) k_mlp_mma(const float* __restrict__ b1,
                                                 const float* __restrict__ b2,
                                                 const float* __restrict__ gamma,
                                                 const float* __restrict__ beta,
                                                 float* __restrict__ out) {
    extern __shared__ __align__(16) unsigned char sm[];
    int t = threadIdx.x;
    int w = t >> 5, l = t & 31;
    int l4 = l >> 2, lq = l & 3;

    {
        const float4* src = (const float4*)g_Wimg;
        float4* dst = (float4*)(sm + SW_BASE);
        for (int i = t; i < W_TOT/16; i += 256) dst[i] = src[i];
    }
    float* b1s = (float*)(sm + S_B1);
    float* b2s = (float*)(sm + S_B2);
    float* gs  = (float*)(sm + S_GAM);
    float* bs  = (float*)(sm + S_BET);
    b1s[t] = b1[t];
    if (t < 64) { b2s[t] = b2[t]; gs[t] = gamma[t]; bs[t] = beta[t]; }

    const unsigned char* W1h = sm + SW_BASE + W_W1HI;
    const unsigned char* W1l = sm + SW_BASE + W_W1LO;
    const unsigned char* W2h = sm + SW_BASE + W_W2HI;
    const unsigned char* W2l = sm + SW_BASE + W_W2LO;

    for (int it4 = 0; it4 < 4; it4++) {
        size_t tile = (size_t)blockIdx.x*4 + it4;
        __syncthreads();            // protect A buffer (covers W copy on iter 0)
        {
            const float4* xs  = (const float4*)(g_xsum  + (tile*256 + t)*64);
            const float4* xs2 = (const float4*)(g_xsum2 + (tile*256 + t)*64);
            unsigned char* rh = sm + SA_HI + t*144;
            unsigned char* rl = sm + SA_LO + t*144;
            #pragma unroll
            for (int q = 0; q < 16; q++) {
                float4 v = xs[q], v2 = xs2[q];
                v.x += v2.x; v.y += v2.y; v.z += v2.z; v.w += v2.w;
                uint32_t h0, l0, h1, l1;
                cvt_pair(v.x, v.y, h0, l0);
                cvt_pair(v.z, v.w, h1, l1);
                *(uint32_t*)(rh + q*8    ) = h0;
                *(uint32_t*)(rh + q*8 + 4) = h1;
                *(uint32_t*)(rl + q*8    ) = l0;
                *(uint32_t*)(rl + q*8 + 4) = l1;
            }
        }
        __syncthreads();

        float d2[2][8][4];
        #pragma unroll
        for (int mt = 0; mt < 2; mt++)
            #pragma unroll
            for (int j = 0; j < 8; j++)
                #pragma unroll
                for (int q = 0; q < 4; q++) d2[mt][j][q] = 0.f;

        for (int c = 0; c < 4; c++) {
            float h[2][8][4];
            #pragma unroll
            for (int mt = 0; mt < 2; mt++)
                #pragma unroll
                for (int j = 0; j < 8; j++)
                    #pragma unroll
                    for (int q = 0; q < 4; q++) h[mt][j][q] = 0.f;

            #pragma unroll
            for (int kt = 0; kt < 4; kt++) {
                uint32_t ah[2][4], al[2][4];
                #pragma unroll
                for (int mt = 0; mt < 2; mt++) {
                    int row = w*32 + mt*16 + l4;
                    int kof = (kt*16 + 2*lq)*2;
                    ah[mt][0] = *(const uint32_t*)(sm + SA_HI + row*144 + kof);
                    ah[mt][1] = *(const uint32_t*)(sm + SA_HI + (row+8)*144 + kof);
                    ah[mt][2] = *(const uint32_t*)(sm + SA_HI + row*144 + kof + 16);
                    ah[mt][3] = *(const uint32_t*)(sm + SA_HI + (row+8)*144 + kof + 16);
                    al[mt][0] = *(const uint32_t*)(sm + SA_LO + row*144 + kof);
                    al[mt][1] = *(const uint32_t*)(sm + SA_LO + (row+8)*144 + kof);
                    al[mt][2] = *(const uint32_t*)(sm + SA_LO + row*144 + kof + 16);
                    al[mt][3] = *(const uint32_t*)(sm + SA_LO + (row+8)*144 + kof + 16);
                }
                #pragma unroll
                for (int j = 0; j < 8; j++) {
                    int n = c*64 + j*8 + l4;
                    int kof = (kt*16 + 2*lq)*2;
                    uint32_t bh0 = *(const uint32_t*)(W1h + n*144 + kof);
                    uint32_t bh1 = *(const uint32_t*)(W1h + n*144 + kof + 16);
                    uint32_t bl0 = *(const uint32_t*)(W1l + n*144 + kof);
                    uint32_t bl1 = *(const uint32_t*)(W1l + n*144 + kof + 16);
                    #pragma unroll
                    for (int mt = 0; mt < 2; mt++) {
                        mma_bf16(h[mt][j], ah[mt], bh0, bh1);
                        mma_bf16(h[mt][j], ah[mt], bl0, bl1);
                        mma_bf16(h[mt][j], al[mt], bh0, bh1);
                    }
                }
            }

            #pragma unroll
            for (int kt2 = 0; kt2 < 4; kt2++) {
                int j = 2*kt2;
                uint32_t ah2[2][4], al2[2][4];
                #pragma unroll
                for (int mt = 0; mt < 2; mt++) {
                    int g0 = c*64 + j*8 + 2*lq;
                    float bA = b1s[g0],   bB = b1s[g0+1];
                    float bC = b1s[g0+8], bD = b1s[g0+9];
                    float v0 = fmaxf(h[mt][j][0] + bA, 0.f);
                    float v1 = fmaxf(h[mt][j][1] + bB, 0.f);
                    cvt_pair(v0, v1, ah2[mt][0], al2[mt][0]);
                    v0 = fmaxf(h[mt][j][2] + bA, 0.f);
                    v1 = fmaxf(h[mt][j][3] + bB, 0.f);
                    cvt_pair(v0, v1, ah2[mt][1], al2[mt][1]);
                    v0 = fmaxf(h[mt][j+1][0] + bC, 0.f);
                    v1 = fmaxf(h[mt][j+1][1] + bD, 0.f);
                    cvt_pair(v0, v1, ah2[mt][2], al2[mt][2]);
                    v0 = fmaxf(h[mt][j+1][2] + bC, 0.f);
                    v1 = fmaxf(h[mt][j+1][3] + bD, 0.f);
                    cvt_pair(v0, v1, ah2[mt][3], al2[mt][3]);
                }
                int k0 = c*64 + kt2*16;
                #pragma unroll
                for (int j2 = 0; j2 < 8; j2++) {
                    int n = j2*8 + l4;
                    int kof = (k0 + 2*lq)*2;
                    uint32_t bh0 = *(const uint32_t*)(W2h + n*528 + kof);
                    uint32_t bh1 = *(const uint32_t*)(W2h + n*528 + kof + 16);
                    uint32_t bl0 = *(const uint32_t*)(W2l + n*528 + kof);
                    uint32_t bl1 = *(const uint32_t*)(W2l + n*528 + kof + 16);
                    #pragma unroll
                    for (int mt = 0; mt < 2; mt++) {
                        mma_bf16(d2[mt][j2], ah2[mt], bh0, bh1);
                        mma_bf16(d2[mt][j2], ah2[mt], bl0, bl1);
                        mma_bf16(d2[mt][j2], al2[mt], bh0, bh1);
                    }
                }
            }
        }

        #pragma unroll
        for (int mt = 0; mt < 2; mt++) {
            #pragma unroll
            for (int rh = 0; rh < 2; rh++) {
                float vals[16];
                #pragma unroll
                for (int j2 = 0; j2 < 8; j2++) {
                    int col = j2*8 + 2*lq;
                    vals[2*j2  ] = d2[mt][j2][2*rh  ] + b2s[col];
                    vals[2*j2+1] = d2[mt][j2][2*rh+1] + b2s[col+1];
                }
                float s = 0.f;
                #pragma unroll
                for (int q = 0; q < 16; q++) s += vals[q];
                s += __shfl_xor_sync(0xffffffffu, s, 1);
                s += __shfl_xor_sync(0xffffffffu, s, 2);
                float mu = s * (1.f/64.f);
                float v = 0.f;
                #pragma unroll
                for (int q = 0; q < 16; q++) { float d = vals[q] - mu; v = fmaf(d, d, v); }
                v += __shfl_xor_sync(0xffffffffu, v, 1);
                v += __shfl_xor_sync(0xffffffffu, v, 2);
                float rinv = rsqrtf(v * (1.f/64.f) + 1e-5f);
                size_t row = tile*256 + w*32 + mt*16 + rh*8 + l4;
                #pragma unroll
                for (int j2 = 0; j2 < 8; j2++) {
                    int col = j2*8 + 2*lq;
                    float2 r;
                    r.x = (vals[2*j2  ] - mu) * rinv * gs[col  ] + bs[col  ];
                    r.y = (vals[2*j2+1] - mu) * rinv * gs[col+1] + bs[col+1];
                    *(float2*)(out + row*64 + col) = r;
                }
            }
        }
    }
}

// ---------------- launcher ----------------
extern "C" void kernel_launch(void* const* d_in, const int* in_sizes, int n_in,
                              void* d_out, int out_size) {
    (void)in_sizes; (void)n_in; (void)out_size;
    const float* x     = (const float*)d_in[0];
    const float* att   = (const float*)d_in[1];
    const float* fwy   = (const float*)d_in[2];
    const float* fwx   = (const float*)d_in[3];
    const float* w1    = (const float*)d_in[4];
    const float* b1    = (const float*)d_in[5];
    const float* w2    = (const float*)d_in[6];
    const float* b2    = (const float*)d_in[7];
    const float* gamma = (const float*)d_in[8];
    const float* beta  = (const float*)d_in[9];
    float* out = (float*)d_out;

    cudaFuncSetAttribute(k_fwd_mma, cudaFuncAttributeMaxDynamicSharedMemorySize, FW_TOT);
    cudaFuncSetAttribute(k_mix_mma, cudaFuncAttributeMaxDynamicSharedMemorySize, MX_TOT);
    cudaFuncSetAttribute(k_inv_mma, cudaFuncAttributeMaxDynamicSharedMemorySize, IV_TOT);
    cudaFuncSetAttribute(k_mlp_mma, cudaFuncAttributeMaxDynamicSharedMemorySize, SM_MLP);

    k_weights<<<(BATCH*MODES*CI*CO)/256, 256>>>(att, fwy, fwx);
    k_wprep<<<128, 256>>>(w1, w2);
    k_tprep<<<256, 256>>>();
    k_fwd_mma<<<512, 256, FW_TOT>>>(x);
    k_mix_mma<<<2*BATCH*MODES, 256, MX_TOT>>>();
    k_inv_mma<<<512, 256, IV_TOT>>>();
    k_mlp_mma<<<512, 256, SM_MLP>>>(b1, b2, gamma, beta, out);
}

// round 8
// speedup vs baseline: 1.1050x; 1.1050x over previous
#include <cuda_runtime.h>
#include <cuda_bf16.h>
#include <cstdint>

#define BATCH 8
#define MM 256
#define NN 256
#define CI 64
#define CO 64
#define KK 4
#define MODES 32

typedef unsigned long long u64;

// ---------------- scratch ----------------
__device__ float2 g_wy [BATCH*MODES*CI*CO];
__device__ float2 g_wx [BATCH*MODES*CI*CO];
__device__ float2 g_XfY[BATCH*MODES*MM*CI];
__device__ float2 g_XfX[BATCH*MODES*NN*CI];
__device__ float2 g_YfY[BATCH*MODES*MM*CO];
__device__ float2 g_YfX[BATCH*MODES*NN*CO];
__device__ float  g_xsum [(size_t)BATCH*MM*NN*CO];
__device__ float  g_xsum2[(size_t)BATCH*MM*NN*CO];

// MLP weight image
#define W_W1HI 0
#define W_W1LO 36864
#define W_W2HI 73728
#define W_W2LO 107520
#define W_TOT  141312
__device__ __align__(16) unsigned char g_Wimg[W_TOT];

// transform tables (split bf16, smem-image layout)
#define T_ST   520
#define T_LOB  33280
#define T_TOT  66560
__device__ __align__(16) unsigned char g_TY[T_TOT];
__device__ __align__(16) unsigned char g_TX[T_TOT];
#define S_ST   136
#define S_LOB  34816
#define S_TOT  69632
__device__ __align__(16) unsigned char g_SY[S_TOT];
__device__ __align__(16) unsigned char g_SX[S_TOT];

// ---------------- bf16 helpers ----------------
__device__ __forceinline__ void cvt_pair(float v0, float v1, uint32_t& hi, uint32_t& lo) {
    __nv_bfloat16 h0 = __float2bfloat16(v0), h1 = __float2bfloat16(v1);
    float r0 = v0 - __bfloat162float(h0);
    float r1 = v1 - __bfloat162float(h1);
    hi = (uint32_t)__bfloat16_as_ushort(h0) | ((uint32_t)__bfloat16_as_ushort(h1) << 16);
    lo = (uint32_t)__bfloat16_as_ushort(__float2bfloat16(r0))
       | ((uint32_t)__bfloat16_as_ushort(__float2bfloat16(r1)) << 16);
}
__device__ __forceinline__ void mma_bf16(float* d, const uint32_t* a, uint32_t b0, uint32_t b1) {
    asm volatile(
        "mma.sync.aligned.m16n8k16.row.col.f32.bf16.bf16.f32 "
        "{%0,%1,%2,%3},{%4,%5,%6,%7},{%8,%9},{%0,%1,%2,%3};"
        : "+f"(d[0]), "+f"(d[1]), "+f"(d[2]), "+f"(d[3])
        : "r"(a[0]), "r"(a[1]), "r"(a[2]), "r"(a[3]), "r"(b0), "r"(b1));
}
__device__ __forceinline__ void wr_split(unsigned char* phi, unsigned char* plo, float v) {
    __nv_bfloat16 h = __float2bfloat16(v);
    float r = v - __bfloat162float(h);
    *(unsigned short*)phi = __bfloat16_as_ushort(h);
    *(unsigned short*)plo = __bfloat16_as_ushort(__float2bfloat16(r));
}

// ---------------- K0: spectral weights ----------------
__global__ void k_weights(const float* __restrict__ att,
                          const float* __restrict__ fwy,
                          const float* __restrict__ fwx) {
    int gid = blockIdx.x * 256 + threadIdx.x;
    int o = gid & 63, i = (gid >> 6) & 63, f = (gid >> 12) & 31, b = gid >> 17;
    float a0 = att[b*KK+0], a1 = att[b*KK+1], a2 = att[b*KK+2], a3 = att[b*KK+3];
    const int ks = CI*CO*MODES*2;
    int base = ((i*CO + o)*MODES + f)*2;
    float yr, yi, xr, xi;
    yr = a0*fwy[base   ] + a1*fwy[base+ks   ] + a2*fwy[base+2*ks  ] + a3*fwy[base+3*ks  ];
    yi = a0*fwy[base+1 ] + a1*fwy[base+ks+1 ] + a2*fwy[base+2*ks+1] + a3*fwy[base+3*ks+1];
    xr = a0*fwx[base   ] + a1*fwx[base+ks   ] + a2*fwx[base+2*ks  ] + a3*fwx[base+3*ks  ];
    xi = a0*fwx[base+1 ] + a1*fwx[base+ks+1 ] + a2*fwx[base+2*ks+1] + a3*fwx[base+3*ks+1];
    g_wy[gid] = make_float2(yr, yi);
    g_wx[gid] = make_float2(xr, xi);
}

// ---------------- K0b: MLP weight image ----------------
__global__ void k_wprep(const float* __restrict__ w1, const float* __restrict__ w2) {
    int gid = blockIdx.x * 256 + threadIdx.x;
    if (gid < 16384) {
        int i = gid >> 8, j = gid & 255;
        uint32_t off = (uint32_t)j*144 + (uint32_t)i*2;
        wr_split(g_Wimg + W_W1HI + off, g_Wimg + W_W1LO + off, w1[gid]);
    } else {
        int idx = gid - 16384;
        int j = idx >> 6, o = idx & 63;
        uint32_t off = (uint32_t)o*528 + (uint32_t)j*2;
        wr_split(g_Wimg + W_W2HI + off, g_Wimg + W_W2LO + off, w2[idx]);
    }
}

// ---------------- K0c: transform tables ----------------
__global__ void k_tprep() {
    int gid = blockIdx.x * 256 + threadIdx.x;
    int sel = gid >> 14;
    int idx = gid & 16383;
    const float inv = 0.04428074428f;
    if (sel == 0) {
        int r = idx >> 8, k = idx & 255;
        int f = r >> 1;
        float ang = (float)((f*k) & 255) * (1.0f/128.0f);
        float v = (r & 1) ? -0.0625f*sinpif(ang) : 0.0625f*cospif(ang);
        uint32_t off = (uint32_t)r*T_ST + (uint32_t)k*2;
        wr_split(g_TY + off, g_TY + T_LOB + off, v);
    } else if (sel == 1) {
        int r = idx >> 8, k = idx & 255;
        int f = r >> 1;
        float v;
        if (r & 1) v = -2.0f*inv*sinpif((float)((f*k) % 510) * (1.0f/255.0f));
        else       v = (k == 0) ? inv : ((k == 255) ? ((f & 1) ? -inv : inv) : 0.0f);
        uint32_t off = (uint32_t)r*T_ST + (uint32_t)k*2;
        wr_split(g_TX + off, g_TX + T_LOB + off, v);
    } else if (sel == 2) {
        int r = idx >> 6, k = idx & 63;
        int f = k >> 1;
        float ang = (float)((f*r) & 255) * (1.0f/128.0f);
        float v = (k & 1) ? -0.125f*sinpif(ang)
                          : ((f == 0) ? 0.0625f : 0.125f)*cospif(ang);
        uint32_t off = (uint32_t)r*S_ST + (uint32_t)k*2;
        wr_split(g_SY + off, g_SY + S_LOB + off, v);
    } else {
        int r = idx >> 6, k = idx & 63;
        int f = k >> 1;
        float ang = (float)((f*r) % 510) * (1.0f/255.0f);
        float v = (k & 1) ? -2.0f*inv*sinpif(ang)
                          : ((f == 0) ? inv : 2.0f*inv)*cospif(ang);
        uint32_t off = (uint32_t)r*S_ST + (uint32_t)k*2;
        wr_split(g_SX + off, g_SX + S_LOB + off, v);
    }
}

// ---------------- K1: forward transforms (512 thr, 8 mn per block) ----------------
#define FW_B   66560
#define FW_TOT 133120
__global__ void __launch_bounds__(512) k_fwd_mma(const float* __restrict__ x) {
    extern __shared__ __align__(16) unsigned char sm[];
    int t = threadIdx.x, w = t >> 5, l = t & 31, l4 = l >> 2, lq = l & 3;
    int z = blockIdx.x;             // 512
    int branch = z >> 8;
    int grp = z & 255;
    int b = grp >> 5, g = grp & 31;

    {
        const float4* src = (const float4*)(branch ? g_TX : g_TY);
        float4* dst = (float4*)sm;
        for (int i = t; i < T_TOT/16; i += 512) dst[i] = src[i];
    }

    int mt = w & 3, nh = w >> 2;    // mt: row tile 0..3, nh: 16-col group 0..3
    const unsigned char* Th = sm;
    const unsigned char* Tl = sm + T_LOB;
    const unsigned char* Bh = sm + FW_B;
    const unsigned char* Bl = sm + FW_B + T_LOB;
    float* outb = (float*)(branch ? g_XfX : g_XfY);

    for (int it8 = 0; it8 < 8; it8++) {
        int mn = g*8 + it8;
        __syncthreads();
        #pragma unroll
        for (int it = 0; it < 4; it++) {
            int flat = it*512 + t;          // 2048
            int kp = flat >> 4, c4 = flat & 15;
            const float* p0;
            size_t stride1;
            if (branch == 0) {
                p0 = x + ((size_t)(b*256 + mn))*16384 + (size_t)(2*kp)*64 + c4*4;
                stride1 = 64;
            } else {
                p0 = x + (((size_t)(b*256 + 2*kp))*256 + mn)*64 + c4*4;
                stride1 = 16384;
            }
            float4 r0 = *(const float4*)p0;
            float4 r1 = *(const float4*)(p0 + stride1);
            float a0[4] = {r0.x, r0.y, r0.z, r0.w};
            float a1[4] = {r1.x, r1.y, r1.z, r1.w};
            #pragma unroll
            for (int j = 0; j < 4; j++) {
                uint32_t hi, lo;
                cvt_pair(a0[j], a1[j], hi, lo);
                uint32_t off = (uint32_t)(4*c4 + j)*T_ST + (uint32_t)kp*4;
                *(uint32_t*)(sm + FW_B + off)         = hi;
                *(uint32_t*)(sm + FW_B + T_LOB + off) = lo;
            }
        }
        __syncthreads();

        float c[2][4];
        #pragma unroll
        for (int j = 0; j < 2; j++)
            #pragma unroll
            for (int q = 0; q < 4; q++) c[j][q] = 0.f;

        #pragma unroll
        for (int kk = 0; kk < 16; kk++) {
            int kof = kk*32 + lq*4;
            int r0 = mt*16 + l4;
            uint32_t ah[4], al[4];
            ah[0] = *(const uint32_t*)(Th + r0*T_ST + kof);
            ah[1] = *(const uint32_t*)(Th + (r0+8)*T_ST + kof);
            ah[2] = *(const uint32_t*)(Th + r0*T_ST + kof + 16);
            ah[3] = *(const uint32_t*)(Th + (r0+8)*T_ST + kof + 16);
            al[0] = *(const uint32_t*)(Tl + r0*T_ST + kof);
            al[1] = *(const uint32_t*)(Tl + (r0+8)*T_ST + kof);
            al[2] = *(const uint32_t*)(Tl + r0*T_ST + kof + 16);
            al[3] = *(const uint32_t*)(Tl + (r0+8)*T_ST + kof + 16);
            #pragma unroll
            for (int j = 0; j < 2; j++) {
                int ncol = nh*16 + j*8 + l4;
                uint32_t bh0 = *(const uint32_t*)(Bh + ncol*T_ST + kof);
                uint32_t bh1 = *(const uint32_t*)(Bh + ncol*T_ST + kof + 16);
                uint32_t bl0 = *(const uint32_t*)(Bl + ncol*T_ST + kof);
                uint32_t bl1 = *(const uint32_t*)(Bl + ncol*T_ST + kof + 16);
                mma_bf16(c[j], ah, bh0, bh1);
                mma_bf16(c[j], ah, bl0, bl1);
                mma_bf16(c[j], al, bh0, bh1);
            }
        }

        #pragma unroll
        for (int j = 0; j < 2; j++) {
            int ch = nh*16 + j*8 + 2*lq;
            int r0 = mt*16 + l4, r1 = r0 + 8;
            size_t base0 = ((size_t)(b*32 + (r0 >> 1))*256 + mn)*128 + ch*2 + (r0 & 1);
            size_t base1 = ((size_t)(b*32 + (r1 >> 1))*256 + mn)*128 + ch*2 + (r1 & 1);
            outb[base0]     = c[j][0];
            outb[base0 + 2] = c[j][1];
            outb[base1]     = c[j][2];
            outb[base1 + 2] = c[j][3];
        }
    }
}

// ---------------- K2: complex GEMM via mma.sync (512 thr) ----------------
#define MX_AHI 0
#define MX_ALO 69632
#define MX_WHI 139264
#define MX_WLO 174080
#define MX_TOT 208896

__global__ void __launch_bounds__(512) k_mix_mma() {
    extern __shared__ __align__(16) unsigned char sm[];
    int t = threadIdx.x, w = t >> 5, l = t & 31, l4 = l >> 2, lq = l & 3;
    int z = blockIdx.x, branch = z >> 8, bf = z & 255;
    const float2* A = (branch ? g_XfX : g_XfY) + (size_t)bf*MM*CI;
    const float2* W = (branch ? g_wx  : g_wy ) + (size_t)bf*CI*CO;
    float2*       C = (branch ? g_YfX : g_YfY) + (size_t)bf*MM*CO;

    {
        const float4* Af = (const float4*)A;
        #pragma unroll
        for (int it = 0; it < 16; it++) {
            int ft = it*512 + t;
            int row = ft >> 5, c4 = ft & 31;
            float4 v = Af[ft];
            uint32_t h01, l01, h23, l23;
            cvt_pair(v.x, v.y, h01, l01);
            cvt_pair(v.z, v.w, h23, l23);
            *(uint2*)(sm + MX_AHI + row*272 + c4*8) = make_uint2(h01, h23);
            *(uint2*)(sm + MX_ALO + row*272 + c4*8) = make_uint2(l01, l23);
        }
    }
    {
        #pragma unroll
        for (int it = 0; it < 8; it++) {
            int flat = it*512 + t;
            int i = flat >> 6, o = flat & 63;
            float2 wv = W[flat];
            uint32_t ha, la, hb, lb;
            cvt_pair(wv.x, -wv.y, ha, la);
            cvt_pair(wv.y,  wv.x, hb, lb);
            *(uint32_t*)(sm + MX_WHI + (2*o  )*272 + i*4) = ha;
            *(uint32_t*)(sm + MX_WHI + (2*o+1)*272 + i*4) = hb;
            *(uint32_t*)(sm + MX_WLO + (2*o  )*272 + i*4) = la;
            *(uint32_t*)(sm + MX_WLO + (2*o+1)*272 + i*4) = lb;
        }
    }
    __syncthreads();

    float acc[16][4];
    #pragma unroll
    for (int j2 = 0; j2 < 16; j2++)
        #pragma unroll
        for (int q = 0; q < 4; q++) acc[j2][q] = 0.f;

    int m0 = w*16;
    #pragma unroll
    for (int kt = 0; kt < 8; kt++) {
        int kof = kt*32 + lq*4;
        int row = m0 + l4;
        uint32_t ah[4], al[4];
        ah[0] = *(const uint32_t*)(sm + MX_AHI + row*272 + kof);
        ah[1] = *(const uint32_t*)(sm + MX_AHI + (row+8)*272 + kof);
        ah[2] = *(const uint32_t*)(sm + MX_AHI + row*272 + kof + 16);
        ah[3] = *(const uint32_t*)(sm + MX_AHI + (row+8)*272 + kof + 16);
        al[0] = *(const uint32_t*)(sm + MX_ALO + row*272 + kof);
        al[1] = *(const uint32_t*)(sm + MX_ALO + (row+8)*272 + kof);
        al[2] = *(const uint32_t*)(sm + MX_ALO + row*272 + kof + 16);
        al[3] = *(const uint32_t*)(sm + MX_ALO + (row+8)*272 + kof + 16);
        #pragma unroll
        for (int j2 = 0; j2 < 16; j2++) {
            int nrow = j2*8 + l4;
            uint32_t bh0 = *(const uint32_t*)(sm + MX_WHI + nrow*272 + kof);
            uint32_t bh1 = *(const uint32_t*)(sm + MX_WHI + nrow*272 + kof + 16);
            uint32_t bl0 = *(const uint32_t*)(sm + MX_WLO + nrow*272 + kof);
            uint32_t bl1 = *(const uint32_t*)(sm + MX_WLO + nrow*272 + kof + 16);
            mma_bf16(acc[j2], ah, bh0, bh1);
            mma_bf16(acc[j2], ah, bl0, bl1);
            mma_bf16(acc[j2], al, bh0, bh1);
        }
    }

    float* Cf = (float*)C;
    #pragma unroll
    for (int j2 = 0; j2 < 16; j2++) {
        int row = m0 + l4;
        int col = j2*8 + 2*lq;
        *(float2*)(Cf + (size_t)row*128 + col)     = make_float2(acc[j2][0], acc[j2][1]);
        *(float2*)(Cf + (size_t)(row+8)*128 + col) = make_float2(acc[j2][2], acc[j2][3]);
    }
}

// ---------------- K3: inverse transforms (512 thr, per-item grid) ----------------
#define IV_B   69632
#define IV_TOT 87040
#define IV_BLO 8704
__global__ void __launch_bounds__(512) k_inv_mma() {
    extern __shared__ __align__(16) unsigned char sm[];
    int t = threadIdx.x, w = t >> 5, l = t & 31, l4 = l >> 2, lq = l & 3;
    int z = blockIdx.x;             // 4096
    int branch = z >> 11;
    int bm = z & 2047;
    int b = bm >> 8, mn = bm & 255;

    {
        const float4* src = (const float4*)(branch ? g_SX : g_SY);
        float4* dst = (float4*)sm;
        for (int i = t; i < S_TOT/16; i += 512) dst[i] = src[i];
    }
    {
        const float2* Y = (branch ? g_YfX : g_YfY);
        #pragma unroll
        for (int it = 0; it < 4; it++) {
            int flat = it*512 + t;
            int f = flat >> 6, ch = flat & 63;
            float2 v = Y[((size_t)(b*32 + f)*256 + mn)*64 + ch];
            uint32_t hi, lo;
            cvt_pair(v.x, v.y, hi, lo);
            uint32_t off = (uint32_t)ch*S_ST + (uint32_t)f*4;
            *(uint32_t*)(sm + IV_B + off)          = hi;
            *(uint32_t*)(sm + IV_B + IV_BLO + off) = lo;
        }
    }
    __syncthreads();

    const unsigned char* Sh = sm;
    const unsigned char* Sl = sm + S_LOB;
    const unsigned char* Bh = sm + IV_B;
    const unsigned char* Bl = sm + IV_B + IV_BLO;
    float* outb = branch ? g_xsum2 : g_xsum;

    float c[8][4];
    #pragma unroll
    for (int j = 0; j < 8; j++)
        #pragma unroll
        for (int q = 0; q < 4; q++) c[j][q] = 0.f;

    #pragma unroll
    for (int kk = 0; kk < 4; kk++) {
        int kof = kk*32 + lq*4;
        int r0 = w*16 + l4;
        uint32_t ah[4], al[4];
        ah[0] = *(const uint32_t*)(Sh + r0*S_ST + kof);
        ah[1] = *(const uint32_t*)(Sh + (r0+8)*S_ST + kof);
        ah[2] = *(const uint32_t*)(Sh + r0*S_ST + kof + 16);
        ah[3] = *(const uint32_t*)(Sh + (r0+8)*S_ST + kof + 16);
        al[0] = *(const uint32_t*)(Sl + r0*S_ST + kof);
        al[1] = *(const uint32_t*)(Sl + (r0+8)*S_ST + kof);
        al[2] = *(const uint32_t*)(Sl + r0*S_ST + kof + 16);
        al[3] = *(const uint32_t*)(Sl + (r0+8)*S_ST + kof + 16);
        #pragma unroll
        for (int j = 0; j < 8; j++) {
            int ncol = j*8 + l4;
            uint32_t bh0 = *(const uint32_t*)(Bh + ncol*S_ST + kof);
            uint32_t bh1 = *(const uint32_t*)(Bh + ncol*S_ST + kof + 16);
            uint32_t bl0 = *(const uint32_t*)(Bl + ncol*S_ST + kof);
            uint32_t bl1 = *(const uint32_t*)(Bl + ncol*S_ST + kof + 16);
            mma_bf16(c[j], ah, bh0, bh1);
            mma_bf16(c[j], ah, bl0, bl1);
            mma_bf16(c[j], al, bh0, bh1);
        }
    }

    #pragma unroll
    for (int j = 0; j < 8; j++) {
        int col = j*8 + 2*lq;
        int r0 = w*16 + l4, r1 = r0 + 8;
        size_t a0, a1;
        if (branch == 0) {
            a0 = (((size_t)(b*256 + mn))*256 + r0)*64 + col;
            a1 = (((size_t)(b*256 + mn))*256 + r1)*64 + col;
        } else {
            a0 = (((size_t)(b*256 + r0))*256 + mn)*64 + col;
            a1 = (((size_t)(b*256 + r1))*256 + mn)*64 + col;
        }
        *(float2*)(outb + a0) = make_float2(c[j][0], c[j][1]);
        *(float2*)(outb + a1) = make_float2(c[j][2], c[j][3]);
    }
}

// ---------------- K4: MLP (512 thr, per-tile grid) ----------------
#define SA_HI   0
#define SA_LO   36864
#define SW_BASE 73728
#define S_B1    215040
#define S_B2    216064
#define S_GAM   216320
#define S_BET   216576
#define SM_MLP  216832

__global__ void __launch_bounds__(512) k_mlp_mma(const float* __restrict__ b1,
                                                 const float* __restrict__ b2,
                                                 const float* __restrict__ gamma,
                                                 const float* __restrict__ beta,
                                                 float* __restrict__ out) {
    extern __shared__ __align__(16) unsigned char sm[];
    int t = threadIdx.x;
    int w = t >> 5, l = t & 31;
    int l4 = l >> 2, lq = l & 3;
    size_t tile = blockIdx.x;

    {
        const float4* src = (const float4*)g_Wimg;
        float4* dst = (float4*)(sm + SW_BASE);
        for (int i = t; i < W_TOT/16; i += 512) dst[i] = src[i];
    }
    float* b1s = (float*)(sm + S_B1);
    float* b2s = (float*)(sm + S_B2);
    float* gs  = (float*)(sm + S_GAM);
    float* bs  = (float*)(sm + S_BET);
    if (t < 256) b1s[t] = b1[t];
    if (t >= 256 && t < 320) { int q = t - 256; b2s[q] = b2[q]; gs[q] = gamma[q]; bs[q] = beta[q]; }

    // stage A: thread handles half a row
    {
        int row = t >> 1, qh = (t & 1) * 8;
        const float4* xs  = (const float4*)(g_xsum  + (tile*256 + row)*64);
        const float4* xs2 = (const float4*)(g_xsum2 + (tile*256 + row)*64);
        unsigned char* rh = sm + SA_HI + row*144;
        unsigned char* rl = sm + SA_LO + row*144;
        #pragma unroll
        for (int q = 0; q < 8; q++) {
            float4 v = xs[qh + q], v2 = xs2[qh + q];
            v.x += v2.x; v.y += v2.y; v.z += v2.z; v.w += v2.w;
            uint32_t h0, l0, h1, l1;
            cvt_pair(v.x, v.y, h0, l0);
            cvt_pair(v.z, v.w, h1, l1);
            *(uint32_t*)(rh + (qh+q)*8    ) = h0;
            *(uint32_t*)(rh + (qh+q)*8 + 4) = h1;
            *(uint32_t*)(rl + (qh+q)*8    ) = l0;
            *(uint32_t*)(rl + (qh+q)*8 + 4) = l1;
        }
    }
    __syncthreads();

    const unsigned char* W1h = sm + SW_BASE + W_W1HI;
    const unsigned char* W1l = sm + SW_BASE + W_W1LO;
    const unsigned char* W2h = sm + SW_BASE + W_W2HI;
    const unsigned char* W2l = sm + SW_BASE + W_W2LO;

    float d2[8][4];
    #pragma unroll
    for (int j = 0; j < 8; j++)
        #pragma unroll
        for (int q = 0; q < 4; q++) d2[j][q] = 0.f;

    for (int c = 0; c < 4; c++) {
        float h[8][4];
        #pragma unroll
        for (int j = 0; j < 8; j++)
            #pragma unroll
            for (int q = 0; q < 4; q++) h[j][q] = 0.f;

        #pragma unroll
        for (int kt = 0; kt < 4; kt++) {
            int row = w*16 + l4;
            int kof = (kt*16 + 2*lq)*2;
            uint32_t ah[4], al[4];
            ah[0] = *(const uint32_t*)(sm + SA_HI + row*144 + kof);
            ah[1] = *(const uint32_t*)(sm + SA_HI + (row+8)*144 + kof);
            ah[2] = *(const uint32_t*)(sm + SA_HI + row*144 + kof + 16);
            ah[3] = *(const uint32_t*)(sm + SA_HI + (row+8)*144 + kof + 16);
            al[0] = *(const uint32_t*)(sm + SA_LO + row*144 + kof);
            al[1] = *(const uint32_t*)(sm + SA_LO + (row+8)*144 + kof);
            al[2] = *(const uint32_t*)(sm + SA_LO + row*144 + kof + 16);
            al[3] = *(const uint32_t*)(sm + SA_LO + (row+8)*144 + kof + 16);
            #pragma unroll
            for (int j = 0; j < 8; j++) {
                int n = c*64 + j*8 + l4;
                uint32_t bh0 = *(const uint32_t*)(W1h + n*144 + kof);
                uint32_t bh1 = *(const uint32_t*)(W1h + n*144 + kof + 16);
                uint32_t bl0 = *(const uint32_t*)(W1l + n*144 + kof);
                uint32_t bl1 = *(const uint32_t*)(W1l + n*144 + kof + 16);
                mma_bf16(h[j], ah, bh0, bh1);
                mma_bf16(h[j], ah, bl0, bl1);
                mma_bf16(h[j], al, bh0, bh1);
            }
        }

        #pragma unroll
        for (int kt2 = 0; kt2 < 4; kt2++) {
            int j = 2*kt2;
            uint32_t ah2[4], al2[4];
            {
                int g0 = c*64 + j*8 + 2*lq;
                float bA = b1s[g0],   bB = b1s[g0+1];
                float bC = b1s[g0+8], bD = b1s[g0+9];
                float v0 = fmaxf(h[j][0] + bA, 0.f);
                float v1 = fmaxf(h[j][1] + bB, 0.f);
                cvt_pair(v0, v1, ah2[0], al2[0]);
                v0 = fmaxf(h[j][2] + bA, 0.f);
                v1 = fmaxf(h[j][3] + bB, 0.f);
                cvt_pair(v0, v1, ah2[1], al2[1]);
                v0 = fmaxf(h[j+1][0] + bC, 0.f);
                v1 = fmaxf(h[j+1][1] + bD, 0.f);
                cvt_pair(v0, v1, ah2[2], al2[2]);
                v0 = fmaxf(h[j+1][2] + bC, 0.f);
                v1 = fmaxf(h[j+1][3] + bD, 0.f);
                cvt_pair(v0, v1, ah2[3], al2[3]);
            }
            int k0 = c*64 + kt2*16;
            #pragma unroll
            for (int j2 = 0; j2 < 8; j2++) {
                int n = j2*8 + l4;
                int kof = (k0 + 2*lq)*2;
                uint32_t bh0 = *(const uint32_t*)(W2h + n*528 + kof);
                uint32_t bh1 = *(const uint32_t*)(W2h + n*528 + kof + 16);
                uint32_t bl0 = *(const uint32_t*)(W2l + n*528 + kof);
                uint32_t bl1 = *(const uint32_t*)(W2l + n*528 + kof + 16);
                mma_bf16(d2[j2], ah2, bh0, bh1);
                mma_bf16(d2[j2], ah2, bl0, bl1);
                mma_bf16(d2[j2], al2, bh0, bh1);
            }
        }
    }

    #pragma unroll
    for (int rh = 0; rh < 2; rh++) {
        float vals[16];
        #pragma unroll
        for (int j2 = 0; j2 < 8; j2++) {
            int col = j2*8 + 2*lq;
            vals[2*j2  ] = d2[j2][2*rh  ] + b2s[col];
            vals[2*j2+1] = d2[j2][2*rh+1] + b2s[col+1];
        }
        float s = 0.f;
        #pragma unroll
        for (int q = 0; q < 16; q++) s += vals[q];
        s += __shfl_xor_sync(0xffffffffu, s, 1);
        s += __shfl_xor_sync(0xffffffffu, s, 2);
        float mu = s * (1.f/64.f);
        float v = 0.f;
        #pragma unroll
        for (int q = 0; q < 16; q++) { float d = vals[q] - mu; v = fmaf(d, d, v); }
        v += __shfl_xor_sync(0xffffffffu, v, 1);
        v += __shfl_xor_sync(0xffffffffu, v, 2);
        float rinv = rsqrtf(v * (1.f/64.f) + 1e-5f);
        size_t row = tile*256 + w*16 + rh*8 + l4;
        #pragma unroll
        for (int j2 = 0; j2 < 8; j2++) {
            int col = j2*8 + 2*lq;
            float2 r;
            r.x = (vals[2*j2  ] - mu) * rinv * gs[col  ] + bs[col  ];
            r.y = (vals[2*j2+1] - mu) * rinv * gs[col+1] + bs[col+1];
            *(float2*)(out + row*64 + col) = r;
        }
    }
}

// ---------------- launcher ----------------
extern "C" void kernel_launch(void* const* d_in, const int* in_sizes, int n_in,
                              void* d_out, int out_size) {
    (void)in_sizes; (void)n_in; (void)out_size;
    const float* x     = (const float*)d_in[0];
    const float* att   = (const float*)d_in[1];
    const float* fwy   = (const float*)d_in[2];
    const float* fwx   = (const float*)d_in[3];
    const float* w1    = (const float*)d_in[4];
    const float* b1    = (const float*)d_in[5];
    const float* w2    = (const float*)d_in[6];
    const float* b2    = (const float*)d_in[7];
    const float* gamma = (const float*)d_in[8];
    const float* beta  = (const float*)d_in[9];
    float* out = (float*)d_out;

    cudaFuncSetAttribute(k_fwd_mma, cudaFuncAttributeMaxDynamicSharedMemorySize, FW_TOT);
    cudaFuncSetAttribute(k_mix_mma, cudaFuncAttributeMaxDynamicSharedMemorySize, MX_TOT);
    cudaFuncSetAttribute(k_inv_mma, cudaFuncAttributeMaxDynamicSharedMemorySize, IV_TOT);
    cudaFuncSetAttribute(k_mlp_mma, cudaFuncAttributeMaxDynamicSharedMemorySize, SM_MLP);

    k_weights<<<(BATCH*MODES*CI*CO)/256, 256>>>(att, fwy, fwx);
    k_wprep<<<128, 256>>>(w1, w2);
    k_tprep<<<256, 256>>>();
    k_fwd_mma<<<512, 512, FW_TOT>>>(x);
    k_mix_mma<<<2*BATCH*MODES, 512, MX_TOT>>>();
    k_inv_mma<<<2*BATCH*MM, 512, IV_TOT>>>();
    k_mlp_mma<<<(BATCH*MM*NN)/256, 512, SM_MLP>>>(b1, b2, gamma, beta, out);
}

// round 9
// speedup vs baseline: 1.2259x; 1.1094x over previous
#include <cuda_runtime.h>
#include <cuda_bf16.h>
#include <cstdint>

#define BATCH 8
#define MM 256
#define NN 256
#define CI 64
#define CO 64
#define KK 4
#define MODES 32

typedef unsigned long long u64;

// ---------------- scratch ----------------
__device__ float2 g_wy [BATCH*MODES*CI*CO];
__device__ float2 g_wx [BATCH*MODES*CI*CO];
__device__ float2 g_XfY[BATCH*MODES*MM*CI];
__device__ float2 g_XfX[BATCH*MODES*NN*CI];
__device__ float2 g_YfY[BATCH*MODES*MM*CO];
__device__ float2 g_YfX[BATCH*MODES*NN*CO];
__device__ float  g_xsum [(size_t)BATCH*MM*NN*CO];
__device__ float  g_xsum2[(size_t)BATCH*MM*NN*CO];

// MLP weight image (strides already 16B-aligned: W1 144, W2 528)
#define W_W1HI 0
#define W_W1LO 36864
#define W_W2HI 73728
#define W_W2LO 107520
#define W_TOT  141312
__device__ __align__(16) unsigned char g_Wimg[W_TOT];

// transform tables (split bf16) — ldmatrix-compatible strides
#define T_ST   528
#define T_LOB  33792
#define T_TOT  67584
__device__ __align__(16) unsigned char g_TY[T_TOT];
__device__ __align__(16) unsigned char g_TX[T_TOT];
#define S_ST   144
#define S_LOB  36864
#define S_TOT  73728
__device__ __align__(16) unsigned char g_SY[S_TOT];
__device__ __align__(16) unsigned char g_SX[S_TOT];

// ---------------- helpers ----------------
__device__ __forceinline__ uint32_t smem_u32(const void* p) {
    uint32_t a;
    asm("{ .reg .u64 t; cvta.to.shared.u64 t, %1; cvt.u32.u64 %0, t; }" : "=r"(a) : "l"(p));
    return a;
}
__device__ __forceinline__ void ldsm4(uint32_t* r, uint32_t a) {
    asm volatile("ldmatrix.sync.aligned.m8n8.x4.shared.b16 {%0,%1,%2,%3}, [%4];"
        : "=r"(r[0]), "=r"(r[1]), "=r"(r[2]), "=r"(r[3]) : "r"(a));
}
__device__ __forceinline__ void cvt_pair(float v0, float v1, uint32_t& hi, uint32_t& lo) {
    __nv_bfloat16 h0 = __float2bfloat16(v0), h1 = __float2bfloat16(v1);
    float r0 = v0 - __bfloat162float(h0);
    float r1 = v1 - __bfloat162float(h1);
    hi = (uint32_t)__bfloat16_as_ushort(h0) | ((uint32_t)__bfloat16_as_ushort(h1) << 16);
    lo = (uint32_t)__bfloat16_as_ushort(__float2bfloat16(r0))
       | ((uint32_t)__bfloat16_as_ushort(__float2bfloat16(r1)) << 16);
}
__device__ __forceinline__ void mma_bf16(float* d, const uint32_t* a, uint32_t b0, uint32_t b1) {
    asm volatile(
        "mma.sync.aligned.m16n8k16.row.col.f32.bf16.bf16.f32 "
        "{%0,%1,%2,%3},{%4,%5,%6,%7},{%8,%9},{%0,%1,%2,%3};"
        : "+f"(d[0]), "+f"(d[1]), "+f"(d[2]), "+f"(d[3])
        : "r"(a[0]), "r"(a[1]), "r"(a[2]), "r"(a[3]), "r"(b0), "r"(b1));
}
__device__ __forceinline__ void wr_split(unsigned char* phi, unsigned char* plo, float v) {
    __nv_bfloat16 h = __float2bfloat16(v);
    float r = v - __bfloat162float(h);
    *(unsigned short*)phi = __bfloat16_as_ushort(h);
    *(unsigned short*)plo = __bfloat16_as_ushort(__float2bfloat16(r));
}

// ---------------- K0: spectral weights ----------------
__global__ void k_weights(const float* __restrict__ att,
                          const float* __restrict__ fwy,
                          const float* __restrict__ fwx) {
    int gid = blockIdx.x * 256 + threadIdx.x;
    int o = gid & 63, i = (gid >> 6) & 63, f = (gid >> 12) & 31, b = gid >> 17;
    float a0 = att[b*KK+0], a1 = att[b*KK+1], a2 = att[b*KK+2], a3 = att[b*KK+3];
    const int ks = CI*CO*MODES*2;
    int base = ((i*CO + o)*MODES + f)*2;
    float yr, yi, xr, xi;
    yr = a0*fwy[base   ] + a1*fwy[base+ks   ] + a2*fwy[base+2*ks  ] + a3*fwy[base+3*ks  ];
    yi = a0*fwy[base+1 ] + a1*fwy[base+ks+1 ] + a2*fwy[base+2*ks+1] + a3*fwy[base+3*ks+1];
    xr = a0*fwx[base   ] + a1*fwx[base+ks   ] + a2*fwx[base+2*ks  ] + a3*fwx[base+3*ks  ];
    xi = a0*fwx[base+1 ] + a1*fwx[base+ks+1 ] + a2*fwx[base+2*ks+1] + a3*fwx[base+3*ks+1];
    g_wy[gid] = make_float2(yr, yi);
    g_wx[gid] = make_float2(xr, xi);
}

// ---------------- K0b: MLP weight image ----------------
__global__ void k_wprep(const float* __restrict__ w1, const float* __restrict__ w2) {
    int gid = blockIdx.x * 256 + threadIdx.x;
    if (gid < 16384) {
        int i = gid >> 8, j = gid & 255;
        uint32_t off = (uint32_t)j*144 + (uint32_t)i*2;
        wr_split(g_Wimg + W_W1HI + off, g_Wimg + W_W1LO + off, w1[gid]);
    } else {
        int idx = gid - 16384;
        int j = idx >> 6, o = idx & 63;
        uint32_t off = (uint32_t)o*528 + (uint32_t)j*2;
        wr_split(g_Wimg + W_W2HI + off, g_Wimg + W_W2LO + off, w2[idx]);
    }
}

// ---------------- K0c: transform tables ----------------
__global__ void k_tprep() {
    int gid = blockIdx.x * 256 + threadIdx.x;
    int sel = gid >> 14;
    int idx = gid & 16383;
    const float inv = 0.04428074428f;
    if (sel == 0) {
        int r = idx >> 8, k = idx & 255;
        int f = r >> 1;
        float ang = (float)((f*k) & 255) * (1.0f/128.0f);
        float v = (r & 1) ? -0.0625f*sinpif(ang) : 0.0625f*cospif(ang);
        uint32_t off = (uint32_t)r*T_ST + (uint32_t)k*2;
        wr_split(g_TY + off, g_TY + T_LOB + off, v);
    } else if (sel == 1) {
        int r = idx >> 8, k = idx & 255;
        int f = r >> 1;
        float v;
        if (r & 1) v = -2.0f*inv*sinpif((float)((f*k) % 510) * (1.0f/255.0f));
        else       v = (k == 0) ? inv : ((k == 255) ? ((f & 1) ? -inv : inv) : 0.0f);
        uint32_t off = (uint32_t)r*T_ST + (uint32_t)k*2;
        wr_split(g_TX + off, g_TX + T_LOB + off, v);
    } else if (sel == 2) {
        int r = idx >> 6, k = idx & 63;
        int f = k >> 1;
        float ang = (float)((f*r) & 255) * (1.0f/128.0f);
        float v = (k & 1) ? -0.125f*sinpif(ang)
                          : ((f == 0) ? 0.0625f : 0.125f)*cospif(ang);
        uint32_t off = (uint32_t)r*S_ST + (uint32_t)k*2;
        wr_split(g_SY + off, g_SY + S_LOB + off, v);
    } else {
        int r = idx >> 6, k = idx & 63;
        int f = k >> 1;
        float ang = (float)((f*r) % 510) * (1.0f/255.0f);
        float v = (k & 1) ? -2.0f*inv*sinpif(ang)
                          : ((f == 0) ? inv : 2.0f*inv)*cospif(ang);
        uint32_t off = (uint32_t)r*S_ST + (uint32_t)k*2;
        wr_split(g_SX + off, g_SX + S_LOB + off, v);
    }
}

// ---------------- K1: forward transforms (512 thr, 8 mn/block, ldmatrix) ----------------
#define FW_B   67584
#define FW_TOT 135168
__global__ void __launch_bounds__(512) k_fwd_mma(const float* __restrict__ x) {
    extern __shared__ __align__(16) unsigned char sm[];
    int t = threadIdx.x, w = t >> 5, l = t & 31, lq = l & 3;
    int z = blockIdx.x;             // 512
    int branch = z >> 8;
    int grp = z & 255;
    int b = grp >> 5, g = grp & 31;

    {
        const float4* src = (const float4*)(branch ? g_TX : g_TY);
        float4* dst = (float4*)sm;
        for (int i = t; i < T_TOT/16; i += 512) dst[i] = src[i];
    }

    int mt = w & 3, nh = w >> 2;
    uint32_t smb = smem_u32(sm);
    uint32_t aAddr = smb + (uint32_t)(mt*16 + (l & 15))*T_ST + (uint32_t)((l >> 4)*16);
    uint32_t bAddr = smb + FW_B
                   + (uint32_t)(nh*16 + ((l >> 4)*8) + (l & 7))*T_ST
                   + (uint32_t)(((l >> 3) & 1)*16);
    float* outb = (float*)(branch ? g_XfX : g_XfY);

    for (int it8 = 0; it8 < 8; it8++) {
        int mn = g*8 + it8;
        __syncthreads();
        #pragma unroll
        for (int it = 0; it < 4; it++) {
            int flat = it*512 + t;          // 2048
            int kp = flat >> 4, c4 = flat & 15;
            const float* p0;
            size_t stride1;
            if (branch == 0) {
                p0 = x + ((size_t)(b*256 + mn))*16384 + (size_t)(2*kp)*64 + c4*4;
                stride1 = 64;
            } else {
                p0 = x + (((size_t)(b*256 + 2*kp))*256 + mn)*64 + c4*4;
                stride1 = 16384;
            }
            float4 r0 = *(const float4*)p0;
            float4 r1 = *(const float4*)(p0 + stride1);
            float a0[4] = {r0.x, r0.y, r0.z, r0.w};
            float a1[4] = {r1.x, r1.y, r1.z, r1.w};
            #pragma unroll
            for (int j = 0; j < 4; j++) {
                uint32_t hi, lo;
                cvt_pair(a0[j], a1[j], hi, lo);
                uint32_t off = (uint32_t)(4*c4 + j)*T_ST + (uint32_t)kp*4;
                *(uint32_t*)(sm + FW_B + off)         = hi;
                *(uint32_t*)(sm + FW_B + T_LOB + off) = lo;
            }
        }
        __syncthreads();

        float c[2][4];
        #pragma unroll
        for (int j = 0; j < 2; j++)
            #pragma unroll
            for (int q = 0; q < 4; q++) c[j][q] = 0.f;

        #pragma unroll
        for (int kk = 0; kk < 16; kk++) {
            uint32_t ah[4], al[4], bh[4], bl[4];
            ldsm4(ah, aAddr + kk*32);
            ldsm4(al, aAddr + T_LOB + kk*32);
            ldsm4(bh, bAddr + kk*32);
            ldsm4(bl, bAddr + T_LOB + kk*32);
            mma_bf16(c[0], ah, bh[0], bh[1]);
            mma_bf16(c[0], ah, bl[0], bl[1]);
            mma_bf16(c[0], al, bh[0], bh[1]);
            mma_bf16(c[1], ah, bh[2], bh[3]);
            mma_bf16(c[1], ah, bl[2], bl[3]);
            mma_bf16(c[1], al, bh[2], bh[3]);
        }

        #pragma unroll
        for (int j = 0; j < 2; j++) {
            int ch = nh*16 + j*8 + 2*lq;
            int r0 = mt*16 + (l >> 2), r1 = r0 + 8;
            size_t base0 = ((size_t)(b*32 + (r0 >> 1))*256 + mn)*128 + ch*2 + (r0 & 1);
            size_t base1 = ((size_t)(b*32 + (r1 >> 1))*256 + mn)*128 + ch*2 + (r1 & 1);
            outb[base0]     = c[j][0];
            outb[base0 + 2] = c[j][1];
            outb[base1]     = c[j][2];
            outb[base1 + 2] = c[j][3];
        }
    }
}

// ---------------- K2: complex GEMM via mma.sync (unchanged from R8) ----------------
#define MX_AHI 0
#define MX_ALO 69632
#define MX_WHI 139264
#define MX_WLO 174080
#define MX_TOT 208896

__global__ void __launch_bounds__(512) k_mix_mma() {
    extern __shared__ __align__(16) unsigned char sm[];
    int t = threadIdx.x, w = t >> 5, l = t & 31, l4 = l >> 2, lq = l & 3;
    int z = blockIdx.x, branch = z >> 8, bf = z & 255;
    const float2* A = (branch ? g_XfX : g_XfY) + (size_t)bf*MM*CI;
    const float2* W = (branch ? g_wx  : g_wy ) + (size_t)bf*CI*CO;
    float2*       C = (branch ? g_YfX : g_YfY) + (size_t)bf*MM*CO;

    {
        const float4* Af = (const float4*)A;
        #pragma unroll
        for (int it = 0; it < 16; it++) {
            int ft = it*512 + t;
            int row = ft >> 5, c4 = ft & 31;
            float4 v = Af[ft];
            uint32_t h01, l01, h23, l23;
            cvt_pair(v.x, v.y, h01, l01);
            cvt_pair(v.z, v.w, h23, l23);
            *(uint2*)(sm + MX_AHI + row*272 + c4*8) = make_uint2(h01, h23);
            *(uint2*)(sm + MX_ALO + row*272 + c4*8) = make_uint2(l01, l23);
        }
    }
    {
        #pragma unroll
        for (int it = 0; it < 8; it++) {
            int flat = it*512 + t;
            int i = flat >> 6, o = flat & 63;
            float2 wv = W[flat];
            uint32_t ha, la, hb, lb;
            cvt_pair(wv.x, -wv.y, ha, la);
            cvt_pair(wv.y,  wv.x, hb, lb);
            *(uint32_t*)(sm + MX_WHI + (2*o  )*272 + i*4) = ha;
            *(uint32_t*)(sm + MX_WHI + (2*o+1)*272 + i*4) = hb;
            *(uint32_t*)(sm + MX_WLO + (2*o  )*272 + i*4) = la;
            *(uint32_t*)(sm + MX_WLO + (2*o+1)*272 + i*4) = lb;
        }
    }
    __syncthreads();

    float acc[16][4];
    #pragma unroll
    for (int j2 = 0; j2 < 16; j2++)
        #pragma unroll
        for (int q = 0; q < 4; q++) acc[j2][q] = 0.f;

    int m0 = w*16;
    #pragma unroll
    for (int kt = 0; kt < 8; kt++) {
        int kof = kt*32 + lq*4;
        int row = m0 + l4;
        uint32_t ah[4], al[4];
        ah[0] = *(const uint32_t*)(sm + MX_AHI + row*272 + kof);
        ah[1] = *(const uint32_t*)(sm + MX_AHI + (row+8)*272 + kof);
        ah[2] = *(const uint32_t*)(sm + MX_AHI + row*272 + kof + 16);
        ah[3] = *(const uint32_t*)(sm + MX_AHI + (row+8)*272 + kof + 16);
        al[0] = *(const uint32_t*)(sm + MX_ALO + row*272 + kof);
        al[1] = *(const uint32_t*)(sm + MX_ALO + (row+8)*272 + kof);
        al[2] = *(const uint32_t*)(sm + MX_ALO + row*272 + kof + 16);
        al[3] = *(const uint32_t*)(sm + MX_ALO + (row+8)*272 + kof + 16);
        #pragma unroll
        for (int j2 = 0; j2 < 16; j2++) {
            int nrow = j2*8 + l4;
            uint32_t bh0 = *(const uint32_t*)(sm + MX_WHI + nrow*272 + kof);
            uint32_t bh1 = *(const uint32_t*)(sm + MX_WHI + nrow*272 + kof + 16);
            uint32_t bl0 = *(const uint32_t*)(sm + MX_WLO + nrow*272 + kof);
            uint32_t bl1 = *(const uint32_t*)(sm + MX_WLO + nrow*272 + kof + 16);
            mma_bf16(acc[j2], ah, bh0, bh1);
            mma_bf16(acc[j2], ah, bl0, bl1);
            mma_bf16(acc[j2], al, bh0, bh1);
        }
    }

    float* Cf = (float*)C;
    #pragma unroll
    for (int j2 = 0; j2 < 16; j2++) {
        int row = m0 + l4;
        int col = j2*8 + 2*lq;
        *(float2*)(Cf + (size_t)row*128 + col)     = make_float2(acc[j2][0], acc[j2][1]);
        *(float2*)(Cf + (size_t)(row+8)*128 + col) = make_float2(acc[j2][2], acc[j2][3]);
    }
}

// ---------------- K3: inverse transforms (512 thr, per-item grid, ldmatrix) ----------------
#define IV_B   73728
#define IV_BLO 9216
#define IV_TOT 92160
__global__ void __launch_bounds__(512) k_inv_mma() {
    extern __shared__ __align__(16) unsigned char sm[];
    int t = threadIdx.x, w = t >> 5, l = t & 31, lq = l & 3;
    int z = blockIdx.x;             // 4096
    int branch = z >> 11;
    int bm = z & 2047;
    int b = bm >> 8, mn = bm & 255;

    {
        const float4* src = (const float4*)(branch ? g_SX : g_SY);
        float4* dst = (float4*)sm;
        for (int i = t; i < S_TOT/16; i += 512) dst[i] = src[i];
    }
    {
        const float2* Y = (branch ? g_YfX : g_YfY);
        #pragma unroll
        for (int it = 0; it < 4; it++) {
            int flat = it*512 + t;
            int f = flat >> 6, ch = flat & 63;
            float2 v = Y[((size_t)(b*32 + f)*256 + mn)*64 + ch];
            uint32_t hi, lo;
            cvt_pair(v.x, v.y, hi, lo);
            uint32_t off = (uint32_t)ch*S_ST + (uint32_t)f*4;
            *(uint32_t*)(sm + IV_B + off)          = hi;
            *(uint32_t*)(sm + IV_B + IV_BLO + off) = lo;
        }
    }
    __syncthreads();

    uint32_t smb = smem_u32(sm);
    uint32_t aAddr = smb + (uint32_t)(w*16 + (l & 15))*S_ST + (uint32_t)((l >> 4)*16);
    uint32_t bBase = smb + IV_B
                   + (uint32_t)(((l >> 4)*8) + (l & 7))*S_ST
                   + (uint32_t)(((l >> 3) & 1)*16);
    float* outb = branch ? g_xsum2 : g_xsum;

    float c[8][4];
    #pragma unroll
    for (int j = 0; j < 8; j++)
        #pragma unroll
        for (int q = 0; q < 4; q++) c[j][q] = 0.f;

    #pragma unroll
    for (int kk = 0; kk < 4; kk++) {
        uint32_t ah[4], al[4];
        ldsm4(ah, aAddr + kk*32);
        ldsm4(al, aAddr + S_LOB + kk*32);
        #pragma unroll
        for (int u = 0; u < 4; u++) {
            uint32_t bh[4], bl[4];
            uint32_t ba = bBase + (uint32_t)(u*16)*S_ST + kk*32;
            ldsm4(bh, ba);
            ldsm4(bl, ba + IV_BLO);
            mma_bf16(c[2*u  ], ah, bh[0], bh[1]);
            mma_bf16(c[2*u  ], ah, bl[0], bl[1]);
            mma_bf16(c[2*u  ], al, bh[0], bh[1]);
            mma_bf16(c[2*u+1], ah, bh[2], bh[3]);
            mma_bf16(c[2*u+1], ah, bl[2], bl[3]);
            mma_bf16(c[2*u+1], al, bh[2], bh[3]);
        }
    }

    #pragma unroll
    for (int j = 0; j < 8; j++) {
        int col = j*8 + 2*lq;
        int r0 = w*16 + (l >> 2), r1 = r0 + 8;
        size_t a0, a1;
        if (branch == 0) {
            a0 = (((size_t)(b*256 + mn))*256 + r0)*64 + col;
            a1 = (((size_t)(b*256 + mn))*256 + r1)*64 + col;
        } else {
            a0 = (((size_t)(b*256 + r0))*256 + mn)*64 + col;
            a1 = (((size_t)(b*256 + r1))*256 + mn)*64 + col;
        }
        *(float2*)(outb + a0) = make_float2(c[j][0], c[j][1]);
        *(float2*)(outb + a1) = make_float2(c[j][2], c[j][3]);
    }
}

// ---------------- K4: MLP (512 thr, per-tile grid, ldmatrix) ----------------
#define SA_HI   0
#define SA_LO   36864
#define SW_BASE 73728
#define S_B1    215040
#define S_B2    216064
#define S_GAM   216320
#define S_BET   216576
#define SM_MLP  216832

__global__ void __launch_bounds__(512) k_mlp_mma(const float* __restrict__ b1,
                                                 const float* __restrict__ b2,
                                                 const float* __restrict__ gamma,
                                                 const float* __restrict__ beta,
                                                 float* __restrict__ out) {
    extern __shared__ __align__(16) unsigned char sm[];
    int t = threadIdx.x;
    int w = t >> 5, l = t & 31;
    int lq = l & 3;
    size_t tile = blockIdx.x;

    {
        const float4* src = (const float4*)g_Wimg;
        float4* dst = (float4*)(sm + SW_BASE);
        for (int i = t; i < W_TOT/16; i += 512) dst[i] = src[i];
    }
    float* b1s = (float*)(sm + S_B1);
    float* b2s = (float*)(sm + S_B2);
    float* gs  = (float*)(sm + S_GAM);
    float* bs  = (float*)(sm + S_BET);
    if (t < 256) b1s[t] = b1[t];
    if (t >= 256 && t < 320) { int q = t - 256; b2s[q] = b2[q]; gs[q] = gamma[q]; bs[q] = beta[q]; }

    {
        int row = t >> 1, qh = (t & 1) * 8;
        const float4* xs  = (const float4*)(g_xsum  + (tile*256 + row)*64);
        const float4* xs2 = (const float4*)(g_xsum2 + (tile*256 + row)*64);
        unsigned char* rh = sm + SA_HI + row*144;
        unsigned char* rl = sm + SA_LO + row*144;
        #pragma unroll
        for (int q = 0; q < 8; q++) {
            float4 v = xs[qh + q], v2 = xs2[qh + q];
            v.x += v2.x; v.y += v2.y; v.z += v2.z; v.w += v2.w;
            uint32_t h0, l0, h1, l1;
            cvt_pair(v.x, v.y, h0, l0);
            cvt_pair(v.z, v.w, h1, l1);
            *(uint32_t*)(rh + (qh+q)*8    ) = h0;
            *(uint32_t*)(rh + (qh+q)*8 + 4) = h1;
            *(uint32_t*)(rl + (qh+q)*8    ) = l0;
            *(uint32_t*)(rl + (qh+q)*8 + 4) = l1;
        }
    }
    __syncthreads();

    uint32_t smb = smem_u32(sm);
    uint32_t aAddr  = smb + SA_HI + (uint32_t)(w*16 + (l & 15))*144 + (uint32_t)((l >> 4)*16);
    uint32_t w1Base = smb + SW_BASE + W_W1HI
                    + (uint32_t)(((l >> 4)*8) + (l & 7))*144 + (uint32_t)(((l >> 3) & 1)*16);
    uint32_t w2Base = smb + SW_BASE + W_W2HI
                    + (uint32_t)(((l >> 4)*8) + (l & 7))*528 + (uint32_t)(((l >> 3) & 1)*16);

    float d2[8][4];
    #pragma unroll
    for (int j = 0; j < 8; j++)
        #pragma unroll
        for (int q = 0; q < 4; q++) d2[j][q] = 0.f;

    for (int c = 0; c < 4; c++) {
        float h[8][4];
        #pragma unroll
        for (int j = 0; j < 8; j++)
            #pragma unroll
            for (int q = 0; q < 4; q++) h[j][q] = 0.f;

        #pragma unroll
        for (int kt = 0; kt < 4; kt++) {
            uint32_t ah[4], al[4];
            ldsm4(ah, aAddr + kt*32);
            ldsm4(al, aAddr + (SA_LO - SA_HI) + kt*32);
            #pragma unroll
            for (int u = 0; u < 4; u++) {
                uint32_t bh[4], bl[4];
                uint32_t ba = w1Base + (uint32_t)(c*64 + u*16)*144 + kt*32;
                ldsm4(bh, ba);
                ldsm4(bl, ba + (W_W1LO - W_W1HI));
                mma_bf16(h[2*u  ], ah, bh[0], bh[1]);
                mma_bf16(h[2*u  ], ah, bl[0], bl[1]);
                mma_bf16(h[2*u  ], al, bh[0], bh[1]);
                mma_bf16(h[2*u+1], ah, bh[2], bh[3]);
                mma_bf16(h[2*u+1], ah, bl[2], bl[3]);
                mma_bf16(h[2*u+1], al, bh[2], bh[3]);
            }
        }

        #pragma unroll
        for (int kt2 = 0; kt2 < 4; kt2++) {
            int j = 2*kt2;
            uint32_t ah2[4], al2[4];
            {
                int g0 = c*64 + j*8 + 2*lq;
                float bA = b1s[g0],   bB = b1s[g0+1];
                float bC = b1s[g0+8], bD = b1s[g0+9];
                float v0 = fmaxf(h[j][0] + bA, 0.f);
                float v1 = fmaxf(h[j][1] + bB, 0.f);
                cvt_pair(v0, v1, ah2[0], al2[0]);
                v0 = fmaxf(h[j][2] + bA, 0.f);
                v1 = fmaxf(h[j][3] + bB, 0.f);
                cvt_pair(v0, v1, ah2[1], al2[1]);
                v0 = fmaxf(h[j+1][0] + bC, 0.f);
                v1 = fmaxf(h[j+1][1] + bD, 0.f);
                cvt_pair(v0, v1, ah2[2], al2[2]);
                v0 = fmaxf(h[j+1][2] + bC, 0.f);
                v1 = fmaxf(h[j+1][3] + bD, 0.f);
                cvt_pair(v0, v1, ah2[3], al2[3]);
            }
            uint32_t kByte = (uint32_t)(c*128 + kt2*32);
            #pragma unroll
            for (int u = 0; u < 4; u++) {
                uint32_t bh[4], bl[4];
                uint32_t ba = w2Base + (uint32_t)(u*16)*528 + kByte;
                ldsm4(bh, ba);
                ldsm4(bl, ba + (W_W2LO - W_W2HI));
                mma_bf16(d2[2*u  ], ah2, bh[0], bh[1]);
                mma_bf16(d2[2*u  ], ah2, bl[0], bl[1]);
                mma_bf16(d2[2*u  ], al2, bh[0], bh[1]);
                mma_bf16(d2[2*u+1], ah2, bh[2], bh[3]);
                mma_bf16(d2[2*u+1], ah2, bl[2], bl[3]);
                mma_bf16(d2[2*u+1], al2, bh[2], bh[3]);
            }
        }
    }

    #pragma unroll
    for (int rh = 0; rh < 2; rh++) {
        float vals[16];
        #pragma unroll
        for (int j2 = 0; j2 < 8; j2++) {
            int col = j2*8 + 2*lq;
            vals[2*j2  ] = d2[j2][2*rh  ] + b2s[col];
            vals[2*j2+1] = d2[j2][2*rh+1] + b2s[col+1];
        }
        float s = 0.f;
        #pragma unroll
        for (int q = 0; q < 16; q++) s += vals[q];
        s += __shfl_xor_sync(0xffffffffu, s, 1);
        s += __shfl_xor_sync(0xffffffffu, s, 2);
        float mu = s * (1.f/64.f);
        float v = 0.f;
        #pragma unroll
        for (int q = 0; q < 16; q++) { float d = vals[q] - mu; v = fmaf(d, d, v); }
        v += __shfl_xor_sync(0xffffffffu, v, 1);
        v += __shfl_xor_sync(0xffffffffu, v, 2);
        float rinv = rsqrtf(v * (1.f/64.f) + 1e-5f);
        size_t row = tile*256 + w*16 + rh*8 + (l >> 2);
        #pragma unroll
        for (int j2 = 0; j2 < 8; j2++) {
            int col = j2*8 + 2*lq;
            float2 r;
            r.x = (vals[2*j2  ] - mu) * rinv * gs[col  ] + bs[col  ];
            r.y = (vals[2*j2+1] - mu) * rinv * gs[col+1] + bs[col+1];
            *(float2*)(out + row*64 + col) = r;
        }
    }
}

// ---------------- launcher ----------------
extern "C" void kernel_launch(void* const* d_in, const int* in_sizes, int n_in,
                              void* d_out, int out_size) {
    (void)in_sizes; (void)n_in; (void)out_size;
    const float* x     = (const float*)d_in[0];
    const float* att   = (const float*)d_in[1];
    const float* fwy   = (const float*)d_in[2];
    const float* fwx   = (const float*)d_in[3];
    const float* w1    = (const float*)d_in[4];
    const float* b1    = (const float*)d_in[5];
    const float* w2    = (const float*)d_in[6];
    const float* b2    = (const float*)d_in[7];
    const float* gamma = (const float*)d_in[8];
    const float* beta  = (const float*)d_in[9];
    float* out = (float*)d_out;

    cudaFuncSetAttribute(k_fwd_mma, cudaFuncAttributeMaxDynamicSharedMemorySize, FW_TOT);
    cudaFuncSetAttribute(k_mix_mma, cudaFuncAttributeMaxDynamicSharedMemorySize, MX_TOT);
    cudaFuncSetAttribute(k_inv_mma, cudaFuncAttributeMaxDynamicSharedMemorySize, IV_TOT);
    cudaFuncSetAttribute(k_mlp_mma, cudaFuncAttributeMaxDynamicSharedMemorySize, SM_MLP);

    k_weights<<<(BATCH*MODES*CI*CO)/256, 256>>>(att, fwy, fwx);
    k_wprep<<<128, 256>>>(w1, w2);
    k_tprep<<<256, 256>>>();
    k_fwd_mma<<<512, 512, FW_TOT>>>(x);
    k_mix_mma<<<2*BATCH*MODES, 512, MX_TOT>>>();
    k_inv_mma<<<2*BATCH*MM, 512, IV_TOT>>>();
    k_mlp_mma<<<(BATCH*MM*NN)/256, 512, SM_MLP>>>(b1, b2, gamma, beta, out);
}

// round 10
// speedup vs baseline: 1.2361x; 1.0083x over previous
#include <cuda_runtime.h>
#include <cuda_bf16.h>
#include <cstdint>

#define BATCH 8
#define MM 256
#define NN 256
#define CI 64
#define CO 64
#define KK 4
#define MODES 32

typedef unsigned long long u64;

// ---------------- scratch ----------------
__device__ float2 g_wy [BATCH*MODES*CI*CO];
__device__ float2 g_wx [BATCH*MODES*CI*CO];
__device__ float2 g_XfY[BATCH*MODES*MM*CI];
__device__ float2 g_XfX[BATCH*MODES*NN*CI];
__device__ float2 g_YfY[BATCH*MODES*MM*CO];
__device__ float2 g_YfX[BATCH*MODES*NN*CO];
__device__ float  g_xsum [(size_t)BATCH*MM*NN*CO];
__device__ float  g_xsum2[(size_t)BATCH*MM*NN*CO];

// MLP weight image
#define W_W1HI 0
#define W_W1LO 36864
#define W_W2HI 73728
#define W_W2LO 107520
#define W_TOT  141312
__device__ __align__(16) unsigned char g_Wimg[W_TOT];

// transform tables (split bf16) — ldmatrix strides
#define T_ST   528
#define T_LOB  33792
#define T_TOT  67584
__device__ __align__(16) unsigned char g_TY[T_TOT];
__device__ __align__(16) unsigned char g_TX[T_TOT];
#define S_ST   144
#define S_LOB  36864
#define S_TOT  73728
__device__ __align__(16) unsigned char g_SY[S_TOT];
__device__ __align__(16) unsigned char g_SX[S_TOT];

// ---------------- helpers ----------------
__device__ __forceinline__ uint32_t smem_u32(const void* p) {
    uint32_t a;
    asm("{ .reg .u64 t; cvta.to.shared.u64 t, %1; cvt.u32.u64 %0, t; }" : "=r"(a) : "l"(p));
    return a;
}
__device__ __forceinline__ void ldsm4(uint32_t* r, uint32_t a) {
    asm volatile("ldmatrix.sync.aligned.m8n8.x4.shared.b16 {%0,%1,%2,%3}, [%4];"
        : "=r"(r[0]), "=r"(r[1]), "=r"(r[2]), "=r"(r[3]) : "r"(a));
}
__device__ __forceinline__ void ldsm4t(uint32_t* r, uint32_t a) {
    asm volatile("ldmatrix.sync.aligned.m8n8.x4.trans.shared.b16 {%0,%1,%2,%3}, [%4];"
        : "=r"(r[0]), "=r"(r[1]), "=r"(r[2]), "=r"(r[3]) : "r"(a));
}
__device__ __forceinline__ void cvt_pair(float v0, float v1, uint32_t& hi, uint32_t& lo) {
    __nv_bfloat16 h0 = __float2bfloat16(v0), h1 = __float2bfloat16(v1);
    float r0 = v0 - __bfloat162float(h0);
    float r1 = v1 - __bfloat162float(h1);
    hi = (uint32_t)__bfloat16_as_ushort(h0) | ((uint32_t)__bfloat16_as_ushort(h1) << 16);
    lo = (uint32_t)__bfloat16_as_ushort(__float2bfloat16(r0))
       | ((uint32_t)__bfloat16_as_ushort(__float2bfloat16(r1)) << 16);
}
__device__ __forceinline__ void mma_bf16(float* d, const uint32_t* a, uint32_t b0, uint32_t b1) {
    asm volatile(
        "mma.sync.aligned.m16n8k16.row.col.f32.bf16.bf16.f32 "
        "{%0,%1,%2,%3},{%4,%5,%6,%7},{%8,%9},{%0,%1,%2,%3};"
        : "+f"(d[0]), "+f"(d[1]), "+f"(d[2]), "+f"(d[3])
        : "r"(a[0]), "r"(a[1]), "r"(a[2]), "r"(a[3]), "r"(b0), "r"(b1));
}
__device__ __forceinline__ void wr_split(unsigned char* phi, unsigned char* plo, float v) {
    __nv_bfloat16 h = __float2bfloat16(v);
    float r = v - __bfloat162float(h);
    *(unsigned short*)phi = __bfloat16_as_ushort(h);
    *(unsigned short*)plo = __bfloat16_as_ushort(__float2bfloat16(r));
}

// ---------------- K0: spectral weights ----------------
__global__ void k_weights(const float* __restrict__ att,
                          const float* __restrict__ fwy,
                          const float* __restrict__ fwx) {
    int gid = blockIdx.x * 256 + threadIdx.x;
    int o = gid & 63, i = (gid >> 6) & 63, f = (gid >> 12) & 31, b = gid >> 17;
    float a0 = att[b*KK+0], a1 = att[b*KK+1], a2 = att[b*KK+2], a3 = att[b*KK+3];
    const int ks = CI*CO*MODES*2;
    int base = ((i*CO + o)*MODES + f)*2;
    float yr, yi, xr, xi;
    yr = a0*fwy[base   ] + a1*fwy[base+ks   ] + a2*fwy[base+2*ks  ] + a3*fwy[base+3*ks  ];
    yi = a0*fwy[base+1 ] + a1*fwy[base+ks+1 ] + a2*fwy[base+2*ks+1] + a3*fwy[base+3*ks+1];
    xr = a0*fwx[base   ] + a1*fwx[base+ks   ] + a2*fwx[base+2*ks  ] + a3*fwx[base+3*ks  ];
    xi = a0*fwx[base+1 ] + a1*fwx[base+ks+1 ] + a2*fwx[base+2*ks+1] + a3*fwx[base+3*ks+1];
    g_wy[gid] = make_float2(yr, yi);
    g_wx[gid] = make_float2(xr, xi);
}

// ---------------- K0b: MLP weight image ----------------
__global__ void k_wprep(const float* __restrict__ w1, const float* __restrict__ w2) {
    int gid = blockIdx.x * 256 + threadIdx.x;
    if (gid < 16384) {
        int i = gid >> 8, j = gid & 255;
        uint32_t off = (uint32_t)j*144 + (uint32_t)i*2;
        wr_split(g_Wimg + W_W1HI + off, g_Wimg + W_W1LO + off, w1[gid]);
    } else {
        int idx = gid - 16384;
        int j = idx >> 6, o = idx & 63;
        uint32_t off = (uint32_t)o*528 + (uint32_t)j*2;
        wr_split(g_Wimg + W_W2HI + off, g_Wimg + W_W2LO + off, w2[idx]);
    }
}

// ---------------- K0c: transform tables ----------------
__global__ void k_tprep() {
    int gid = blockIdx.x * 256 + threadIdx.x;
    int sel = gid >> 14;
    int idx = gid & 16383;
    const float inv = 0.04428074428f;
    if (sel == 0) {
        int r = idx >> 8, k = idx & 255;
        int f = r >> 1;
        float ang = (float)((f*k) & 255) * (1.0f/128.0f);
        float v = (r & 1) ? -0.0625f*sinpif(ang) : 0.0625f*cospif(ang);
        uint32_t off = (uint32_t)r*T_ST + (uint32_t)k*2;
        wr_split(g_TY + off, g_TY + T_LOB + off, v);
    } else if (sel == 1) {
        int r = idx >> 8, k = idx & 255;
        int f = r >> 1;
        float v;
        if (r & 1) v = -2.0f*inv*sinpif((float)((f*k) % 510) * (1.0f/255.0f));
        else       v = (k == 0) ? inv : ((k == 255) ? ((f & 1) ? -inv : inv) : 0.0f);
        uint32_t off = (uint32_t)r*T_ST + (uint32_t)k*2;
        wr_split(g_TX + off, g_TX + T_LOB + off, v);
    } else if (sel == 2) {
        int r = idx >> 6, k = idx & 63;
        int f = k >> 1;
        float ang = (float)((f*r) & 255) * (1.0f/128.0f);
        float v = (k & 1) ? -0.125f*sinpif(ang)
                          : ((f == 0) ? 0.0625f : 0.125f)*cospif(ang);
        uint32_t off = (uint32_t)r*S_ST + (uint32_t)k*2;
        wr_split(g_SY + off, g_SY + S_LOB + off, v);
    } else {
        int r = idx >> 6, k = idx & 63;
        int f = k >> 1;
        float ang = (float)((f*r) % 510) * (1.0f/255.0f);
        float v = (k & 1) ? -2.0f*inv*sinpif(ang)
                          : ((f == 0) ? inv : 2.0f*inv)*cospif(ang);
        uint32_t off = (uint32_t)r*S_ST + (uint32_t)k*2;
        wr_split(g_SX + off, g_SX + S_LOB + off, v);
    }
}

// ---------------- K1: forward transforms (512 thr, trans-B staging) ----------------
// B stored natural [k=256][ch=64] bf16, stride 144B, hi/lo planes 36864 each
#define FW_B    67584
#define FB_LOB  36864
#define FW_TOT  141312
__global__ void __launch_bounds__(512) k_fwd_mma(const float* __restrict__ x) {
    extern __shared__ __align__(16) unsigned char sm[];
    int t = threadIdx.x, w = t >> 5, l = t & 31, lq = l & 3;
    int z = blockIdx.x;             // 512
    int branch = z >> 8;
    int grp = z & 255;
    int b = grp >> 5, g = grp & 31;

    {
        const float4* src = (const float4*)(branch ? g_TX : g_TY);
        float4* dst = (float4*)sm;
        for (int i = t; i < T_TOT/16; i += 512) dst[i] = src[i];
    }

    int mt = w & 3, nh = w >> 2;
    uint32_t smb = smem_u32(sm);
    uint32_t aAddr = smb + (uint32_t)(mt*16 + (l & 15))*T_ST + (uint32_t)((l >> 4)*16);
    // trans-B: lane -> k-row (l&7) + ((l>>3)&1)*8, ch col = nh*16 (+8 via (l>>4)*16B)
    uint32_t bAddr = smb + FW_B
                   + (uint32_t)((l & 7) + ((l >> 3) & 1)*8)*144
                   + (uint32_t)(nh*32) + (uint32_t)((l >> 4)*16);
    float* outb = (float*)(branch ? g_XfX : g_XfY);

    for (int it8 = 0; it8 < 8; it8++) {
        int mn = g*8 + it8;
        __syncthreads();
        // stage B natural [k][ch]: contiguous conflict-free STS.64
        #pragma unroll
        for (int it = 0; it < 8; it++) {
            int flat = it*512 + t;          // 4096 = 256 k x 16 c4
            int c4 = flat & 15, k = flat >> 4;
            const float* p0;
            if (branch == 0) p0 = x + ((size_t)(b*256 + mn))*16384 + (size_t)k*64 + c4*4;
            else             p0 = x + (((size_t)(b*256 + k))*256 + mn)*64 + c4*4;
            float4 v = *(const float4*)p0;
            uint32_t h0, l0, h1, l1;
            cvt_pair(v.x, v.y, h0, l0);
            cvt_pair(v.z, v.w, h1, l1);
            *(uint2*)(sm + FW_B + k*144 + c4*8)          = make_uint2(h0, h1);
            *(uint2*)(sm + FW_B + FB_LOB + k*144 + c4*8) = make_uint2(l0, l1);
        }
        __syncthreads();

        float c[2][4];
        #pragma unroll
        for (int j = 0; j < 2; j++)
            #pragma unroll
            for (int q = 0; q < 4; q++) c[j][q] = 0.f;

        #pragma unroll
        for (int kk = 0; kk < 16; kk++) {
            uint32_t ah[4], al[4], bh[4], bl[4];
            ldsm4(ah, aAddr + kk*32);
            ldsm4(al, aAddr + T_LOB + kk*32);
            ldsm4t(bh, bAddr + kk*2304);            // 16 k-rows * 144B
            ldsm4t(bl, bAddr + FB_LOB + kk*2304);
            mma_bf16(c[0], ah, bh[0], bh[1]);
            mma_bf16(c[0], ah, bl[0], bl[1]);
            mma_bf16(c[0], al, bh[0], bh[1]);
            mma_bf16(c[1], ah, bh[2], bh[3]);
            mma_bf16(c[1], ah, bl[2], bl[3]);
            mma_bf16(c[1], al, bh[2], bh[3]);
        }

        #pragma unroll
        for (int j = 0; j < 2; j++) {
            int ch = nh*16 + j*8 + 2*lq;
            int r0 = mt*16 + (l >> 2), r1 = r0 + 8;
            size_t base0 = ((size_t)(b*32 + (r0 >> 1))*256 + mn)*128 + ch*2 + (r0 & 1);
            size_t base1 = ((size_t)(b*32 + (r1 >> 1))*256 + mn)*128 + ch*2 + (r1 & 1);
            outb[base0]     = c[j][0];
            outb[base0 + 2] = c[j][1];
            outb[base1]     = c[j][2];
            outb[base1 + 2] = c[j][3];
        }
    }
}

// ---------------- K2: complex GEMM via mma.sync (unchanged) ----------------
#define MX_AHI 0
#define MX_ALO 69632
#define MX_WHI 139264
#define MX_WLO 174080
#define MX_TOT 208896

__global__ void __launch_bounds__(512) k_mix_mma() {
    extern __shared__ __align__(16) unsigned char sm[];
    int t = threadIdx.x, w = t >> 5, l = t & 31, l4 = l >> 2, lq = l & 3;
    int z = blockIdx.x, branch = z >> 8, bf = z & 255;
    const float2* A = (branch ? g_XfX : g_XfY) + (size_t)bf*MM*CI;
    const float2* W = (branch ? g_wx  : g_wy ) + (size_t)bf*CI*CO;
    float2*       C = (branch ? g_YfX : g_YfY) + (size_t)bf*MM*CO;

    {
        const float4* Af = (const float4*)A;
        #pragma unroll
        for (int it = 0; it < 16; it++) {
            int ft = it*512 + t;
            int row = ft >> 5, c4 = ft & 31;
            float4 v = Af[ft];
            uint32_t h01, l01, h23, l23;
            cvt_pair(v.x, v.y, h01, l01);
            cvt_pair(v.z, v.w, h23, l23);
            *(uint2*)(sm + MX_AHI + row*272 + c4*8) = make_uint2(h01, h23);
            *(uint2*)(sm + MX_ALO + row*272 + c4*8) = make_uint2(l01, l23);
        }
    }
    {
        #pragma unroll
        for (int it = 0; it < 8; it++) {
            int flat = it*512 + t;
            int i = flat >> 6, o = flat & 63;
            float2 wv = W[flat];
            uint32_t ha, la, hb, lb;
            cvt_pair(wv.x, -wv.y, ha, la);
            cvt_pair(wv.y,  wv.x, hb, lb);
            *(uint32_t*)(sm + MX_WHI + (2*o  )*272 + i*4) = ha;
            *(uint32_t*)(sm + MX_WHI + (2*o+1)*272 + i*4) = hb;
            *(uint32_t*)(sm + MX_WLO + (2*o  )*272 + i*4) = la;
            *(uint32_t*)(sm + MX_WLO + (2*o+1)*272 + i*4) = lb;
        }
    }
    __syncthreads();

    float acc[16][4];
    #pragma unroll
    for (int j2 = 0; j2 < 16; j2++)
        #pragma unroll
        for (int q = 0; q < 4; q++) acc[j2][q] = 0.f;

    int m0 = w*16;
    #pragma unroll
    for (int kt = 0; kt < 8; kt++) {
        int kof = kt*32 + lq*4;
        int row = m0 + l4;
        uint32_t ah[4], al[4];
        ah[0] = *(const uint32_t*)(sm + MX_AHI + row*272 + kof);
        ah[1] = *(const uint32_t*)(sm + MX_AHI + (row+8)*272 + kof);
        ah[2] = *(const uint32_t*)(sm + MX_AHI + row*272 + kof + 16);
        ah[3] = *(const uint32_t*)(sm + MX_AHI + (row+8)*272 + kof + 16);
        al[0] = *(const uint32_t*)(sm + MX_ALO + row*272 + kof);
        al[1] = *(const uint32_t*)(sm + MX_ALO + (row+8)*272 + kof);
        al[2] = *(const uint32_t*)(sm + MX_ALO + row*272 + kof + 16);
        al[3] = *(const uint32_t*)(sm + MX_ALO + (row+8)*272 + kof + 16);
        #pragma unroll
        for (int j2 = 0; j2 < 16; j2++) {
            int nrow = j2*8 + l4;
            uint32_t bh0 = *(const uint32_t*)(sm + MX_WHI + nrow*272 + kof);
            uint32_t bh1 = *(const uint32_t*)(sm + MX_WHI + nrow*272 + kof + 16);
            uint32_t bl0 = *(const uint32_t*)(sm + MX_WLO + nrow*272 + kof);
            uint32_t bl1 = *(const uint32_t*)(sm + MX_WLO + nrow*272 + kof + 16);
            mma_bf16(acc[j2], ah, bh0, bh1);
            mma_bf16(acc[j2], ah, bl0, bl1);
            mma_bf16(acc[j2], al, bh0, bh1);
        }
    }

    float* Cf = (float*)C;
    #pragma unroll
    for (int j2 = 0; j2 < 16; j2++) {
        int row = m0 + l4;
        int col = j2*8 + 2*lq;
        *(float2*)(Cf + (size_t)row*128 + col)     = make_float2(acc[j2][0], acc[j2][1]);
        *(float2*)(Cf + (size_t)(row+8)*128 + col) = make_float2(acc[j2][2], acc[j2][3]);
    }
}

// ---------------- K3: inverse transforms (512 thr, trans-B staging) ----------------
// B stored natural [k=2f+p][ch=64], stride 144B, planes 9216
#define IV_B   73728
#define IV_BLO 9216
#define IV_TOT 92160
__global__ void __launch_bounds__(512) k_inv_mma() {
    extern __shared__ __align__(16) unsigned char sm[];
    int t = threadIdx.x, w = t >> 5, l = t & 31, lq = l & 3;
    int z = blockIdx.x;             // 4096
    int branch = z >> 11;
    int bm = z & 2047;
    int b = bm >> 8, mn = bm & 255;

    {
        const float4* src = (const float4*)(branch ? g_SX : g_SY);
        float4* dst = (float4*)sm;
        for (int i = t; i < S_TOT/16; i += 512) dst[i] = src[i];
    }
    // stage B natural [k=2f|2f+1][ch]: contiguous conflict-free STS.32
    {
        const float2* Y = (branch ? g_YfX : g_YfY);
        #pragma unroll
        for (int it = 0; it < 2; it++) {
            int flat = it*512 + t;          // 1024 = 32 f x 32 ch-pairs
            int f = flat >> 5, cp = flat & 31;
            const float4* yp = (const float4*)(Y + ((size_t)(b*32 + f)*256 + mn)*64 + 2*cp);
            float4 v = *yp;                 // (re0,im0,re1,im1)
            uint32_t rh_, rl_, ih_, il_;
            cvt_pair(v.x, v.z, rh_, rl_);   // re pair
            cvt_pair(v.y, v.w, ih_, il_);   // im pair
            *(uint32_t*)(sm + IV_B + (2*f  )*144 + cp*4)          = rh_;
            *(uint32_t*)(sm + IV_B + (2*f+1)*144 + cp*4)          = ih_;
            *(uint32_t*)(sm + IV_B + IV_BLO + (2*f  )*144 + cp*4) = rl_;
            *(uint32_t*)(sm + IV_B + IV_BLO + (2*f+1)*144 + cp*4) = il_;
        }
    }
    __syncthreads();

    uint32_t smb = smem_u32(sm);
    uint32_t aAddr = smb + (uint32_t)(w*16 + (l & 15))*S_ST + (uint32_t)((l >> 4)*16);
    uint32_t bBase = smb + IV_B
                   + (uint32_t)((l & 7) + ((l >> 3) & 1)*8)*144
                   + (uint32_t)((l >> 4)*16);
    float* outb = branch ? g_xsum2 : g_xsum;

    float c[8][4];
    #pragma unroll
    for (int j = 0; j < 8; j++)
        #pragma unroll
        for (int q = 0; q < 4; q++) c[j][q] = 0.f;

    #pragma unroll
    for (int kk = 0; kk < 4; kk++) {
        uint32_t ah[4], al[4];
        ldsm4(ah, aAddr + kk*32);
        ldsm4(al, aAddr + S_LOB + kk*32);
        #pragma unroll
        for (int u = 0; u < 4; u++) {
            uint32_t bh[4], bl[4];
            uint32_t ba = bBase + (uint32_t)(u*32) + (uint32_t)(kk*16)*144;
            ldsm4t(bh, ba);
            ldsm4t(bl, ba + IV_BLO);
            mma_bf16(c[2*u  ], ah, bh[0], bh[1]);
            mma_bf16(c[2*u  ], ah, bl[0], bl[1]);
            mma_bf16(c[2*u  ], al, bh[0], bh[1]);
            mma_bf16(c[2*u+1], ah, bh[2], bh[3]);
            mma_bf16(c[2*u+1], ah, bl[2], bl[3]);
            mma_bf16(c[2*u+1], al, bh[2], bh[3]);
        }
    }

    #pragma unroll
    for (int j = 0; j < 8; j++) {
        int col = j*8 + 2*lq;
        int r0 = w*16 + (l >> 2), r1 = r0 + 8;
        size_t a0, a1;
        if (branch == 0) {
            a0 = (((size_t)(b*256 + mn))*256 + r0)*64 + col;
            a1 = (((size_t)(b*256 + mn))*256 + r1)*64 + col;
        } else {
            a0 = (((size_t)(b*256 + r0))*256 + mn)*64 + col;
            a1 = (((size_t)(b*256 + r1))*256 + mn)*64 + col;
        }
        *(float2*)(outb + a0) = make_float2(c[j][0], c[j][1]);
        *(float2*)(outb + a1) = make_float2(c[j][2], c[j][3]);
    }
}

// ---------------- K4: MLP (512 thr, per-tile grid, ldmatrix) — unchanged R9 ----------------
#define SA_HI   0
#define SA_LO   36864
#define SW_BASE 73728
#define S_B1    215040
#define S_B2    216064
#define S_GAM   216320
#define S_BET   216576
#define SM_MLP  216832

__global__ void __launch_bounds__(512) k_mlp_mma(const float* __restrict__ b1,
                                                 const float* __restrict__ b2,
                                                 const float* __restrict__ gamma,
                                                 const float* __restrict__ beta,
                                                 float* __restrict__ out) {
    extern __shared__ __align__(16) unsigned char sm[];
    int t = threadIdx.x;
    int w = t >> 5, l = t & 31;
    int lq = l & 3;
    size_t tile = blockIdx.x;

    {
        const float4* src = (const float4*)g_Wimg;
        float4* dst = (float4*)(sm + SW_BASE);
        for (int i = t; i < W_TOT/16; i += 512) dst[i] = src[i];
    }
    float* b1s = (float*)(sm + S_B1);
    float* b2s = (float*)(sm + S_B2);
    float* gs  = (float*)(sm + S_GAM);
    float* bs  = (float*)(sm + S_BET);
    if (t < 256) b1s[t] = b1[t];
    if (t >= 256 && t < 320) { int q = t - 256; b2s[q] = b2[q]; gs[q] = gamma[q]; bs[q] = beta[q]; }

    {
        int row = t >> 1, qh = (t & 1) * 8;
        const float4* xs  = (const float4*)(g_xsum  + (tile*256 + row)*64);
        const float4* xs2 = (const float4*)(g_xsum2 + (tile*256 + row)*64);
        unsigned char* rh = sm + SA_HI + row*144;
        unsigned char* rl = sm + SA_LO + row*144;
        #pragma unroll
        for (int q = 0; q < 8; q++) {
            float4 v = xs[qh + q], v2 = xs2[qh + q];
            v.x += v2.x; v.y += v2.y; v.z += v2.z; v.w += v2.w;
            uint32_t h0, l0, h1, l1;
            cvt_pair(v.x, v.y, h0, l0);
            cvt_pair(v.z, v.w, h1, l1);
            *(uint32_t*)(rh + (qh+q)*8    ) = h0;
            *(uint32_t*)(rh + (qh+q)*8 + 4) = h1;
            *(uint32_t*)(rl + (qh+q)*8    ) = l0;
            *(uint32_t*)(rl + (qh+q)*8 + 4) = l1;
        }
    }
    __syncthreads();

    uint32_t smb = smem_u32(sm);
    uint32_t aAddr  = smb + SA_HI + (uint32_t)(w*16 + (l & 15))*144 + (uint32_t)((l >> 4)*16);
    uint32_t w1Base = smb + SW_BASE + W_W1HI
                    + (uint32_t)(((l >> 4)*8) + (l & 7))*144 + (uint32_t)(((l >> 3) & 1)*16);
    uint32_t w2Base = smb + SW_BASE + W_W2HI
                    + (uint32_t)(((l >> 4)*8) + (l & 7))*528 + (uint32_t)(((l >> 3) & 1)*16);

    float d2[8][4];
    #pragma unroll
    for (int j = 0; j < 8; j++)
        #pragma unroll
        for (int q = 0; q < 4; q++) d2[j][q] = 0.f;

    for (int c = 0; c < 4; c++) {
        float h[8][4];
        #pragma unroll
        for (int j = 0; j < 8; j++)
            #pragma unroll
            for (int q = 0; q < 4; q++) h[j][q] = 0.f;

        #pragma unroll
        for (int kt = 0; kt < 4; kt++) {
            uint32_t ah[4], al[4];
            ldsm4(ah, aAddr + kt*32);
            ldsm4(al, aAddr + (SA_LO - SA_HI) + kt*32);
            #pragma unroll
            for (int u = 0; u < 4; u++) {
                uint32_t bh[4], bl[4];
                uint32_t ba = w1Base + (uint32_t)(c*64 + u*16)*144 + kt*32;
                ldsm4(bh, ba);
                ldsm4(bl, ba + (W_W1LO - W_W1HI));
                mma_bf16(h[2*u  ], ah, bh[0], bh[1]);
                mma_bf16(h[2*u  ], ah, bl[0], bl[1]);
                mma_bf16(h[2*u  ], al, bh[0], bh[1]);
                mma_bf16(h[2*u+1], ah, bh[2], bh[3]);
                mma_bf16(h[2*u+1], ah, bl[2], bl[3]);
                mma_bf16(h[2*u+1], al, bh[2], bh[3]);
            }
        }

        #pragma unroll
        for (int kt2 = 0; kt2 < 4; kt2++) {
            int j = 2*kt2;
            uint32_t ah2[4], al2[4];
            {
                int g0 = c*64 + j*8 + 2*lq;
                float bA = b1s[g0],   bB = b1s[g0+1];
                float bC = b1s[g0+8], bD = b1s[g0+9];
                float v0 = fmaxf(h[j][0] + bA, 0.f);
                float v1 = fmaxf(h[j][1] + bB, 0.f);
                cvt_pair(v0, v1, ah2[0], al2[0]);
                v0 = fmaxf(h[j][2] + bA, 0.f);
                v1 = fmaxf(h[j][3] + bB, 0.f);
                cvt_pair(v0, v1, ah2[1], al2[1]);
                v0 = fmaxf(h[j+1][0] + bC, 0.f);
                v1 = fmaxf(h[j+1][1] + bD, 0.f);
                cvt_pair(v0, v1, ah2[2], al2[2]);
                v0 = fmaxf(h[j+1][2] + bC, 0.f);
                v1 = fmaxf(h[j+1][3] + bD, 0.f);
                cvt_pair(v0, v1, ah2[3], al2[3]);
            }
            uint32_t kByte = (uint32_t)(c*128 + kt2*32);
            #pragma unroll
            for (int u = 0; u < 4; u++) {
                uint32_t bh[4], bl[4];
                uint32_t ba = w2Base + (uint32_t)(u*16)*528 + kByte;
                ldsm4(bh, ba);
                ldsm4(bl, ba + (W_W2LO - W_W2HI));
                mma_bf16(d2[2*u  ], ah2, bh[0], bh[1]);
                mma_bf16(d2[2*u  ], ah2, bl[0], bl[1]);
                mma_bf16(d2[2*u  ], al2, bh[0], bh[1]);
                mma_bf16(d2[2*u+1], ah2, bh[2], bh[3]);
                mma_bf16(d2[2*u+1], ah2, bl[2], bl[3]);
                mma_bf16(d2[2*u+1], al2, bh[2], bh[3]);
            }
        }
    }

    #pragma unroll
    for (int rh = 0; rh < 2; rh++) {
        float vals[16];
        #pragma unroll
        for (int j2 = 0; j2 < 8; j2++) {
            int col = j2*8 + 2*lq;
            vals[2*j2  ] = d2[j2][2*rh  ] + b2s[col];
            vals[2*j2+1] = d2[j2][2*rh+1] + b2s[col+1];
        }
        float s = 0.f;
        #pragma unroll
        for (int q = 0; q < 16; q++) s += vals[q];
        s += __shfl_xor_sync(0xffffffffu, s, 1);
        s += __shfl_xor_sync(0xffffffffu, s, 2);
        float mu = s * (1.f/64.f);
        float v = 0.f;
        #pragma unroll
        for (int q = 0; q < 16; q++) { float d = vals[q] - mu; v = fmaf(d, d, v); }
        v += __shfl_xor_sync(0xffffffffu, v, 1);
        v += __shfl_xor_sync(0xffffffffu, v, 2);
        float rinv = rsqrtf(v * (1.f/64.f) + 1e-5f);
        size_t row = tile*256 + w*16 + rh*8 + (l >> 2);
        #pragma unroll
        for (int j2 = 0; j2 < 8; j2++) {
            int col = j2*8 + 2*lq;
            float2 r;
            r.x = (vals[2*j2  ] - mu) * rinv * gs[col  ] + bs[col  ];
            r.y = (vals[2*j2+1] - mu) * rinv * gs[col+1] + bs[col+1];
            *(float2*)(out + row*64 + col) = r;
        }
    }
}

// ---------------- launcher ----------------
extern "C" void kernel_launch(void* const* d_in, const int* in_sizes, int n_in,
                              void* d_out, int out_size) {
    (void)in_sizes; (void)n_in; (void)out_size;
    const float* x     = (const float*)d_in[0];
    const float* att   = (const float*)d_in[1];
    const float* fwy   = (const float*)d_in[2];
    const float* fwx   = (const float*)d_in[3];
    const float* w1    = (const float*)d_in[4];
    const float* b1    = (const float*)d_in[5];
    const float* w2    = (const float*)d_in[6];
    const float* b2    = (const float*)d_in[7];
    const float* gamma = (const float*)d_in[8];
    const float* beta  = (const float*)d_in[9];
    float* out = (float*)d_out;

    cudaFuncSetAttribute(k_fwd_mma, cudaFuncAttributeMaxDynamicSharedMemorySize, FW_TOT);
    cudaFuncSetAttribute(k_mix_mma, cudaFuncAttributeMaxDynamicSharedMemorySize, MX_TOT);
    cudaFuncSetAttribute(k_inv_mma, cudaFuncAttributeMaxDynamicSharedMemorySize, IV_TOT);
    cudaFuncSetAttribute(k_mlp_mma, cudaFuncAttributeMaxDynamicSharedMemorySize, SM_MLP);

    k_weights<<<(BATCH*MODES*CI*CO)/256, 256>>>(att, fwy, fwx);
    k_wprep<<<128, 256>>>(w1, w2);
    k_tprep<<<256, 256>>>();
    k_fwd_mma<<<512, 512, FW_TOT>>>(x);
    k_mix_mma<<<2*BATCH*MODES, 512, MX_TOT>>>();
    k_inv_mma<<<2*BATCH*MM, 512, IV_TOT>>>();
    k_mlp_mma<<<(BATCH*MM*NN)/256, 512, SM_MLP>>>(b1, b2, gamma, beta, out);
}

// round 11
// speedup vs baseline: 1.3070x; 1.0574x over previous
#include <cuda_runtime.h>
#include <cuda_bf16.h>
#include <cstdint>

#define BATCH 8
#define MM 256
#define NN 256
#define CI 64
#define CO 64
#define KK 4
#define MODES 32

typedef unsigned long long u64;

// ---------------- scratch ----------------
__device__ float2 g_wy [BATCH*MODES*CI*CO];
__device__ float2 g_wx [BATCH*MODES*CI*CO];
__device__ float2 g_XfY[BATCH*MODES*MM*CI];
__device__ float2 g_XfX[BATCH*MODES*NN*CI];
__device__ float2 g_YfY[BATCH*MODES*MM*CO];
__device__ float2 g_YfX[BATCH*MODES*NN*CO];
__device__ float  g_xsum [(size_t)BATCH*MM*NN*CO];
__device__ float  g_xsum2[(size_t)BATCH*MM*NN*CO];

// MLP weight image
#define W_W1HI 0
#define W_W1LO 36864
#define W_W2HI 73728
#define W_W2LO 107520
#define W_TOT  141312
__device__ __align__(16) unsigned char g_Wimg[W_TOT];

// transform tables (split bf16) — ldmatrix strides
#define T_ST   528
#define T_LOB  33792
#define T_TOT  67584
__device__ __align__(16) unsigned char g_TY[T_TOT];
__device__ __align__(16) unsigned char g_TX[T_TOT];
#define S_ST   144
#define S_LOB  36864
#define S_TOT  73728
__device__ __align__(16) unsigned char g_SY[S_TOT];
__device__ __align__(16) unsigned char g_SX[S_TOT];

// ---------------- helpers ----------------
__device__ __forceinline__ uint32_t smem_u32(const void* p) {
    uint32_t a;
    asm("{ .reg .u64 t; cvta.to.shared.u64 t, %1; cvt.u32.u64 %0, t; }" : "=r"(a) : "l"(p));
    return a;
}
__device__ __forceinline__ void ldsm4(uint32_t* r, uint32_t a) {
    asm volatile("ldmatrix.sync.aligned.m8n8.x4.shared.b16 {%0,%1,%2,%3}, [%4];"
        : "=r"(r[0]), "=r"(r[1]), "=r"(r[2]), "=r"(r[3]) : "r"(a));
}
__device__ __forceinline__ void ldsm4t(uint32_t* r, uint32_t a) {
    asm volatile("ldmatrix.sync.aligned.m8n8.x4.trans.shared.b16 {%0,%1,%2,%3}, [%4];"
        : "=r"(r[0]), "=r"(r[1]), "=r"(r[2]), "=r"(r[3]) : "r"(a));
}
__device__ __forceinline__ void cvt_pair(float v0, float v1, uint32_t& hi, uint32_t& lo) {
    __nv_bfloat16 h0 = __float2bfloat16(v0), h1 = __float2bfloat16(v1);
    float r0 = v0 - __bfloat162float(h0);
    float r1 = v1 - __bfloat162float(h1);
    hi = (uint32_t)__bfloat16_as_ushort(h0) | ((uint32_t)__bfloat16_as_ushort(h1) << 16);
    lo = (uint32_t)__bfloat16_as_ushort(__float2bfloat16(r0))
       | ((uint32_t)__bfloat16_as_ushort(__float2bfloat16(r1)) << 16);
}
__device__ __forceinline__ void mma_bf16(float* d, const uint32_t* a, uint32_t b0, uint32_t b1) {
    asm volatile(
        "mma.sync.aligned.m16n8k16.row.col.f32.bf16.bf16.f32 "
        "{%0,%1,%2,%3},{%4,%5,%6,%7},{%8,%9},{%0,%1,%2,%3};"
        : "+f"(d[0]), "+f"(d[1]), "+f"(d[2]), "+f"(d[3])
        : "r"(a[0]), "r"(a[1]), "r"(a[2]), "r"(a[3]), "r"(b0), "r"(b1));
}
__device__ __forceinline__ void wr_split(unsigned char* phi, unsigned char* plo, float v) {
    __nv_bfloat16 h = __float2bfloat16(v);
    float r = v - __bfloat162float(h);
    *(unsigned short*)phi = __bfloat16_as_ushort(h);
    *(unsigned short*)plo = __bfloat16_as_ushort(__float2bfloat16(r));
}

// ---------------- K0: spectral weights ----------------
__global__ void k_weights(const float* __restrict__ att,
                          const float* __restrict__ fwy,
                          const float* __restrict__ fwx) {
    int gid = blockIdx.x * 256 + threadIdx.x;
    int o = gid & 63, i = (gid >> 6) & 63, f = (gid >> 12) & 31, b = gid >> 17;
    float a0 = att[b*KK+0], a1 = att[b*KK+1], a2 = att[b*KK+2], a3 = att[b*KK+3];
    const int ks = CI*CO*MODES*2;
    int base = ((i*CO + o)*MODES + f)*2;
    float yr, yi, xr, xi;
    yr = a0*fwy[base   ] + a1*fwy[base+ks   ] + a2*fwy[base+2*ks  ] + a3*fwy[base+3*ks  ];
    yi = a0*fwy[base+1 ] + a1*fwy[base+ks+1 ] + a2*fwy[base+2*ks+1] + a3*fwy[base+3*ks+1];
    xr = a0*fwx[base   ] + a1*fwx[base+ks   ] + a2*fwx[base+2*ks  ] + a3*fwx[base+3*ks  ];
    xi = a0*fwx[base+1 ] + a1*fwx[base+ks+1 ] + a2*fwx[base+2*ks+1] + a3*fwx[base+3*ks+1];
    g_wy[gid] = make_float2(yr, yi);
    g_wx[gid] = make_float2(xr, xi);
}

// ---------------- K0b: MLP weight image ----------------
__global__ void k_wprep(const float* __restrict__ w1, const float* __restrict__ w2) {
    int gid = blockIdx.x * 256 + threadIdx.x;
    if (gid < 16384) {
        int i = gid >> 8, j = gid & 255;
        uint32_t off = (uint32_t)j*144 + (uint32_t)i*2;
        wr_split(g_Wimg + W_W1HI + off, g_Wimg + W_W1LO + off, w1[gid]);
    } else {
        int idx = gid - 16384;
        int j = idx >> 6, o = idx & 63;
        uint32_t off = (uint32_t)o*528 + (uint32_t)j*2;
        wr_split(g_Wimg + W_W2HI + off, g_Wimg + W_W2LO + off, w2[idx]);
    }
}

// ---------------- K0c: transform tables ----------------
__global__ void k_tprep() {
    int gid = blockIdx.x * 256 + threadIdx.x;
    int sel = gid >> 14;
    int idx = gid & 16383;
    const float inv = 0.04428074428f;
    if (sel == 0) {
        int r = idx >> 8, k = idx & 255;
        int f = r >> 1;
        float ang = (float)((f*k) & 255) * (1.0f/128.0f);
        float v = (r & 1) ? -0.0625f*sinpif(ang) : 0.0625f*cospif(ang);
        uint32_t off = (uint32_t)r*T_ST + (uint32_t)k*2;
        wr_split(g_TY + off, g_TY + T_LOB + off, v);
    } else if (sel == 1) {
        int r = idx >> 8, k = idx & 255;
        int f = r >> 1;
        float v;
        if (r & 1) v = -2.0f*inv*sinpif((float)((f*k) % 510) * (1.0f/255.0f));
        else       v = (k == 0) ? inv : ((k == 255) ? ((f & 1) ? -inv : inv) : 0.0f);
        uint32_t off = (uint32_t)r*T_ST + (uint32_t)k*2;
        wr_split(g_TX + off, g_TX + T_LOB + off, v);
    } else if (sel == 2) {
        int r = idx >> 6, k = idx & 63;
        int f = k >> 1;
        float ang = (float)((f*r) & 255) * (1.0f/128.0f);
        float v = (k & 1) ? -0.125f*sinpif(ang)
                          : ((f == 0) ? 0.0625f : 0.125f)*cospif(ang);
        uint32_t off = (uint32_t)r*S_ST + (uint32_t)k*2;
        wr_split(g_SY + off, g_SY + S_LOB + off, v);
    } else {
        int r = idx >> 6, k = idx & 63;
        int f = k >> 1;
        float ang = (float)((f*r) % 510) * (1.0f/255.0f);
        float v = (k & 1) ? -2.0f*inv*sinpif(ang)
                          : ((f == 0) ? inv : 2.0f*inv)*cospif(ang);
        uint32_t off = (uint32_t)r*S_ST + (uint32_t)k*2;
        wr_split(g_SX + off, g_SX + S_LOB + off, v);
    }
}

// ---------------- K1: forward transforms (512 thr, pipelined staging) ----------------
#define FW_B    67584
#define FB_LOB  36864
#define FW_TOT  141312
__global__ void __launch_bounds__(512) k_fwd_mma(const float* __restrict__ x) {
    extern __shared__ __align__(16) unsigned char sm[];
    int t = threadIdx.x, w = t >> 5, l = t & 31, lq = l & 3;
    int z = blockIdx.x;             // 512
    int branch = z >> 8;
    int grp = z & 255;
    int b = grp >> 5, g = grp & 31;

    {
        const float4* src = (const float4*)(branch ? g_TX : g_TY);
        float4* dst = (float4*)sm;
        for (int i = t; i < T_TOT/16; i += 512) dst[i] = src[i];
    }

    int mt = w & 3, nh = w >> 2;
    uint32_t smb = smem_u32(sm);
    uint32_t aAddr = smb + (uint32_t)(mt*16 + (l & 15))*T_ST + (uint32_t)((l >> 4)*16);
    uint32_t bAddr = smb + FW_B
                   + (uint32_t)((l & 7) + ((l >> 3) & 1)*8)*144
                   + (uint32_t)(nh*32) + (uint32_t)((l >> 4)*16);
    float* outb = (float*)(branch ? g_XfX : g_XfY);

    // register pipeline: v holds next iteration's x-tile slice
    float4 v[8];
    {
        int mn0 = g*8;
        #pragma unroll
        for (int it = 0; it < 8; it++) {
            int flat = it*512 + t;
            int c4 = flat & 15, k = flat >> 4;
            const float* p0;
            if (branch == 0) p0 = x + ((size_t)(b*256 + mn0))*16384 + (size_t)k*64 + c4*4;
            else             p0 = x + (((size_t)(b*256 + k))*256 + mn0)*64 + c4*4;
            v[it] = *(const float4*)p0;
        }
    }

    for (int it8 = 0; it8 < 8; it8++) {
        int mn = g*8 + it8;
        __syncthreads();            // prev MMA readers done (covers table copy on it8=0)
        // stage from registers: cvt + conflict-free STS.64
        #pragma unroll
        for (int it = 0; it < 8; it++) {
            int flat = it*512 + t;
            int c4 = flat & 15, k = flat >> 4;
            uint32_t h0, l0, h1, l1;
            cvt_pair(v[it].x, v[it].y, h0, l0);
            cvt_pair(v[it].z, v[it].w, h1, l1);
            *(uint2*)(sm + FW_B + k*144 + c4*8)          = make_uint2(h0, h1);
            *(uint2*)(sm + FW_B + FB_LOB + k*144 + c4*8) = make_uint2(l0, l1);
        }
        __syncthreads();

        // issue next iteration's global loads (latency hidden by MMA below)
        if (it8 < 7) {
            int mn1 = mn + 1;
            #pragma unroll
            for (int it = 0; it < 8; it++) {
                int flat = it*512 + t;
                int c4 = flat & 15, k = flat >> 4;
                const float* p0;
                if (branch == 0) p0 = x + ((size_t)(b*256 + mn1))*16384 + (size_t)k*64 + c4*4;
                else             p0 = x + (((size_t)(b*256 + k))*256 + mn1)*64 + c4*4;
                v[it] = *(const float4*)p0;
            }
        }

        float c[2][4];
        #pragma unroll
        for (int j = 0; j < 2; j++)
            #pragma unroll
            for (int q = 0; q < 4; q++) c[j][q] = 0.f;

        #pragma unroll
        for (int kk = 0; kk < 16; kk++) {
            uint32_t ah[4], al[4], bh[4], bl[4];
            ldsm4(ah, aAddr + kk*32);
            ldsm4(al, aAddr + T_LOB + kk*32);
            ldsm4t(bh, bAddr + kk*2304);
            ldsm4t(bl, bAddr + FB_LOB + kk*2304);
            mma_bf16(c[0], ah, bh[0], bh[1]);
            mma_bf16(c[0], ah, bl[0], bl[1]);
            mma_bf16(c[0], al, bh[0], bh[1]);
            mma_bf16(c[1], ah, bh[2], bh[3]);
            mma_bf16(c[1], ah, bl[2], bl[3]);
            mma_bf16(c[1], al, bh[2], bh[3]);
        }

        #pragma unroll
        for (int j = 0; j < 2; j++) {
            int ch = nh*16 + j*8 + 2*lq;
            int r0 = mt*16 + (l >> 2), r1 = r0 + 8;
            size_t base0 = ((size_t)(b*32 + (r0 >> 1))*256 + mn)*128 + ch*2 + (r0 & 1);
            size_t base1 = ((size_t)(b*32 + (r1 >> 1))*256 + mn)*128 + ch*2 + (r1 & 1);
            outb[base0]     = c[j][0];
            outb[base0 + 2] = c[j][1];
            outb[base1]     = c[j][2];
            outb[base1 + 2] = c[j][3];
        }
    }
}

// ---------------- K2: complex GEMM via mma.sync (unchanged) ----------------
#define MX_AHI 0
#define MX_ALO 69632
#define MX_WHI 139264
#define MX_WLO 174080
#define MX_TOT 208896

__global__ void __launch_bounds__(512) k_mix_mma() {
    extern __shared__ __align__(16) unsigned char sm[];
    int t = threadIdx.x, w = t >> 5, l = t & 31, l4 = l >> 2, lq = l & 3;
    int z = blockIdx.x, branch = z >> 8, bf = z & 255;
    const float2* A = (branch ? g_XfX : g_XfY) + (size_t)bf*MM*CI;
    const float2* W = (branch ? g_wx  : g_wy ) + (size_t)bf*CI*CO;
    float2*       C = (branch ? g_YfX : g_YfY) + (size_t)bf*MM*CO;

    {
        const float4* Af = (const float4*)A;
        #pragma unroll
        for (int it = 0; it < 16; it++) {
            int ft = it*512 + t;
            int row = ft >> 5, c4 = ft & 31;
            float4 v = Af[ft];
            uint32_t h01, l01, h23, l23;
            cvt_pair(v.x, v.y, h01, l01);
            cvt_pair(v.z, v.w, h23, l23);
            *(uint2*)(sm + MX_AHI + row*272 + c4*8) = make_uint2(h01, h23);
            *(uint2*)(sm + MX_ALO + row*272 + c4*8) = make_uint2(l01, l23);
        }
    }
    {
        #pragma unroll
        for (int it = 0; it < 8; it++) {
            int flat = it*512 + t;
            int i = flat >> 6, o = flat & 63;
            float2 wv = W[flat];
            uint32_t ha, la, hb, lb;
            cvt_pair(wv.x, -wv.y, ha, la);
            cvt_pair(wv.y,  wv.x, hb, lb);
            *(uint32_t*)(sm + MX_WHI + (2*o  )*272 + i*4) = ha;
            *(uint32_t*)(sm + MX_WHI + (2*o+1)*272 + i*4) = hb;
            *(uint32_t*)(sm + MX_WLO + (2*o  )*272 + i*4) = la;
            *(uint32_t*)(sm + MX_WLO + (2*o+1)*272 + i*4) = lb;
        }
    }
    __syncthreads();

    float acc[16][4];
    #pragma unroll
    for (int j2 = 0; j2 < 16; j2++)
        #pragma unroll
        for (int q = 0; q < 4; q++) acc[j2][q] = 0.f;

    int m0 = w*16;
    #pragma unroll
    for (int kt = 0; kt < 8; kt++) {
        int kof = kt*32 + lq*4;
        int row = m0 + l4;
        uint32_t ah[4], al[4];
        ah[0] = *(const uint32_t*)(sm + MX_AHI + row*272 + kof);
        ah[1] = *(const uint32_t*)(sm + MX_AHI + (row+8)*272 + kof);
        ah[2] = *(const uint32_t*)(sm + MX_AHI + row*272 + kof + 16);
        ah[3] = *(const uint32_t*)(sm + MX_AHI + (row+8)*272 + kof + 16);
        al[0] = *(const uint32_t*)(sm + MX_ALO + row*272 + kof);
        al[1] = *(const uint32_t*)(sm + MX_ALO + (row+8)*272 + kof);
        al[2] = *(const uint32_t*)(sm + MX_ALO + row*272 + kof + 16);
        al[3] = *(const uint32_t*)(sm + MX_ALO + (row+8)*272 + kof + 16);
        #pragma unroll
        for (int j2 = 0; j2 < 16; j2++) {
            int nrow = j2*8 + l4;
            uint32_t bh0 = *(const uint32_t*)(sm + MX_WHI + nrow*272 + kof);
            uint32_t bh1 = *(const uint32_t*)(sm + MX_WHI + nrow*272 + kof + 16);
            uint32_t bl0 = *(const uint32_t*)(sm + MX_WLO + nrow*272 + kof);
            uint32_t bl1 = *(const uint32_t*)(sm + MX_WLO + nrow*272 + kof + 16);
            mma_bf16(acc[j2], ah, bh0, bh1);
            mma_bf16(acc[j2], ah, bl0, bl1);
            mma_bf16(acc[j2], al, bh0, bh1);
        }
    }

    float* Cf = (float*)C;
    #pragma unroll
    for (int j2 = 0; j2 < 16; j2++) {
        int row = m0 + l4;
        int col = j2*8 + 2*lq;
        *(float2*)(Cf + (size_t)row*128 + col)     = make_float2(acc[j2][0], acc[j2][1]);
        *(float2*)(Cf + (size_t)(row+8)*128 + col) = make_float2(acc[j2][2], acc[j2][3]);
    }
}

// ---------------- K3: inverse transforms (512 thr, trans-B staging) ----------------
#define IV_B   73728
#define IV_BLO 9216
#define IV_TOT 92160
__global__ void __launch_bounds__(512) k_inv_mma() {
    extern __shared__ __align__(16) unsigned char sm[];
    int t = threadIdx.x, w = t >> 5, l = t & 31, lq = l & 3;
    int z = blockIdx.x;             // 4096
    int branch = z >> 11;
    int bm = z & 2047;
    int b = bm >> 8, mn = bm & 255;

    {
        const float4* src = (const float4*)(branch ? g_SX : g_SY);
        float4* dst = (float4*)sm;
        for (int i = t; i < S_TOT/16; i += 512) dst[i] = src[i];
    }
    {
        const float2* Y = (branch ? g_YfX : g_YfY);
        #pragma unroll
        for (int it = 0; it < 2; it++) {
            int flat = it*512 + t;
            int f = flat >> 5, cp = flat & 31;
            const float4* yp = (const float4*)(Y + ((size_t)(b*32 + f)*256 + mn)*64 + 2*cp);
            float4 v = *yp;
            uint32_t rh_, rl_, ih_, il_;
            cvt_pair(v.x, v.z, rh_, rl_);
            cvt_pair(v.y, v.w, ih_, il_);
            *(uint32_t*)(sm + IV_B + (2*f  )*144 + cp*4)          = rh_;
            *(uint32_t*)(sm + IV_B + (2*f+1)*144 + cp*4)          = ih_;
            *(uint32_t*)(sm + IV_B + IV_BLO + (2*f  )*144 + cp*4) = rl_;
            *(uint32_t*)(sm + IV_B + IV_BLO + (2*f+1)*144 + cp*4) = il_;
        }
    }
    __syncthreads();

    uint32_t smb = smem_u32(sm);
    uint32_t aAddr = smb + (uint32_t)(w*16 + (l & 15))*S_ST + (uint32_t)((l >> 4)*16);
    uint32_t bBase = smb + IV_B
                   + (uint32_t)((l & 7) + ((l >> 3) & 1)*8)*144
                   + (uint32_t)((l >> 4)*16);
    float* outb = branch ? g_xsum2 : g_xsum;

    float c[8][4];
    #pragma unroll
    for (int j = 0; j < 8; j++)
        #pragma unroll
        for (int q = 0; q < 4; q++) c[j][q] = 0.f;

    #pragma unroll
    for (int kk = 0; kk < 4; kk++) {
        uint32_t ah[4], al[4];
        ldsm4(ah, aAddr + kk*32);
        ldsm4(al, aAddr + S_LOB + kk*32);
        #pragma unroll
        for (int u = 0; u < 4; u++) {
            uint32_t bh[4], bl[4];
            uint32_t ba = bBase + (uint32_t)(u*32) + (uint32_t)(kk*16)*144;
            ldsm4t(bh, ba);
            ldsm4t(bl, ba + IV_BLO);
            mma_bf16(c[2*u  ], ah, bh[0], bh[1]);
            mma_bf16(c[2*u  ], ah, bl[0], bl[1]);
            mma_bf16(c[2*u  ], al, bh[0], bh[1]);
            mma_bf16(c[2*u+1], ah, bh[2], bh[3]);
            mma_bf16(c[2*u+1], ah, bl[2], bl[3]);
            mma_bf16(c[2*u+1], al, bh[2], bh[3]);
        }
    }

    #pragma unroll
    for (int j = 0; j < 8; j++) {
        int col = j*8 + 2*lq;
        int r0 = w*16 + (l >> 2), r1 = r0 + 8;
        size_t a0, a1;
        if (branch == 0) {
            a0 = (((size_t)(b*256 + mn))*256 + r0)*64 + col;
            a1 = (((size_t)(b*256 + mn))*256 + r1)*64 + col;
        } else {
            a0 = (((size_t)(b*256 + r0))*256 + mn)*64 + col;
            a1 = (((size_t)(b*256 + r1))*256 + mn)*64 + col;
        }
        *(float2*)(outb + a0) = make_float2(c[j][0], c[j][1]);
        *(float2*)(outb + a1) = make_float2(c[j][2], c[j][3]);
    }
}

// ---------------- K4: MLP (512 thr, per-tile grid, ldmatrix) ----------------
#define SA_HI   0
#define SA_LO   36864
#define SW_BASE 73728
#define S_B1    215040
#define S_B2    216064
#define S_GAM   216320
#define S_BET   216576
#define SM_MLP  216832

__global__ void __launch_bounds__(512) k_mlp_mma(const float* __restrict__ b1,
                                                 const float* __restrict__ b2,
                                                 const float* __restrict__ gamma,
                                                 const float* __restrict__ beta,
                                                 float* __restrict__ out) {
    extern __shared__ __align__(16) unsigned char sm[];
    int t = threadIdx.x;
    int w = t >> 5, l = t & 31;
    int lq = l & 3;
    size_t tile = blockIdx.x;

    {
        const float4* src = (const float4*)g_Wimg;
        float4* dst = (float4*)(sm + SW_BASE);
        for (int i = t; i < W_TOT/16; i += 512) dst[i] = src[i];
    }
    float* b1s = (float*)(sm + S_B1);
    float* b2s = (float*)(sm + S_B2);
    float* gs  = (float*)(sm + S_GAM);
    float* bs  = (float*)(sm + S_BET);
    if (t < 256) b1s[t] = b1[t];
    if (t >= 256 && t < 320) { int q = t - 256; b2s[q] = b2[q]; gs[q] = gamma[q]; bs[q] = beta[q]; }

    {
        int row = t >> 1, qh = (t & 1) * 8;
        const float4* xs  = (const float4*)(g_xsum  + (tile*256 + row)*64);
        const float4* xs2 = (const float4*)(g_xsum2 + (tile*256 + row)*64);
        unsigned char* rh = sm + SA_HI + row*144;
        unsigned char* rl = sm + SA_LO + row*144;
        #pragma unroll
        for (int q = 0; q < 8; q++) {
            float4 v = xs[qh + q], v2 = xs2[qh + q];
            v.x += v2.x; v.y += v2.y; v.z += v2.z; v.w += v2.w;
            uint32_t h0, l0, h1, l1;
            cvt_pair(v.x, v.y, h0, l0);
            cvt_pair(v.z, v.w, h1, l1);
            *(uint32_t*)(rh + (qh+q)*8    ) = h0;
            *(uint32_t*)(rh + (qh+q)*8 + 4) = h1;
            *(uint32_t*)(rl + (qh+q)*8    ) = l0;
            *(uint32_t*)(rl + (qh+q)*8 + 4) = l1;
        }
    }
    __syncthreads();

    uint32_t smb = smem_u32(sm);
    uint32_t aAddr  = smb + SA_HI + (uint32_t)(w*16 + (l & 15))*144 + (uint32_t)((l >> 4)*16);
    uint32_t w1Base = smb + SW_BASE + W_W1HI
                    + (uint32_t)(((l >> 4)*8) + (l & 7))*144 + (uint32_t)(((l >> 3) & 1)*16);
    uint32_t w2Base = smb + SW_BASE + W_W2HI
                    + (uint32_t)(((l >> 4)*8) + (l & 7))*528 + (uint32_t)(((l >> 3) & 1)*16);

    float d2[8][4];
    #pragma unroll
    for (int j = 0; j < 8; j++)
        #pragma unroll
        for (int q = 0; q < 4; q++) d2[j][q] = 0.f;

    for (int c = 0; c < 4; c++) {
        float h[8][4];
        #pragma unroll
        for (int j = 0; j < 8; j++)
            #pragma unroll
            for (int q = 0; q < 4; q++) h[j][q] = 0.f;

        #pragma unroll
        for (int kt = 0; kt < 4; kt++) {
            uint32_t ah[4], al[4];
            ldsm4(ah, aAddr + kt*32);
            ldsm4(al, aAddr + (SA_LO - SA_HI) + kt*32);
            #pragma unroll
            for (int u = 0; u < 4; u++) {
                uint32_t bh[4], bl[4];
                uint32_t ba = w1Base + (uint32_t)(c*64 + u*16)*144 + kt*32;
                ldsm4(bh, ba);
                ldsm4(bl, ba + (W_W1LO - W_W1HI));
                mma_bf16(h[2*u  ], ah, bh[0], bh[1]);
                mma_bf16(h[2*u  ], ah, bl[0], bl[1]);
                mma_bf16(h[2*u  ], al, bh[0], bh[1]);
                mma_bf16(h[2*u+1], ah, bh[2], bh[3]);
                mma_bf16(h[2*u+1], ah, bl[2], bl[3]);
                mma_bf16(h[2*u+1], al, bh[2], bh[3]);
            }
        }

        #pragma unroll
        for (int kt2 = 0; kt2 < 4; kt2++) {
            int j = 2*kt2;
            uint32_t ah2[4], al2[4];
            {
                int g0 = c*64 + j*8 + 2*lq;
                float bA = b1s[g0],   bB = b1s[g0+1];
                float bC = b1s[g0+8], bD = b1s[g0+9];
                float v0 = fmaxf(h[j][0] + bA, 0.f);
                float v1 = fmaxf(h[j][1] + bB, 0.f);
                cvt_pair(v0, v1, ah2[0], al2[0]);
                v0 = fmaxf(h[j][2] + bA, 0.f);
                v1 = fmaxf(h[j][3] + bB, 0.f);
                cvt_pair(v0, v1, ah2[1], al2[1]);
                v0 = fmaxf(h[j+1][0] + bC, 0.f);
                v1 = fmaxf(h[j+1][1] + bD, 0.f);
                cvt_pair(v0, v1, ah2[2], al2[2]);
                v0 = fmaxf(h[j+1][2] + bC, 0.f);
                v1 = fmaxf(h[j+1][3] + bD, 0.f);
                cvt_pair(v0, v1, ah2[3], al2[3]);
            }
            uint32_t kByte = (uint32_t)(c*128 + kt2*32);
            #pragma unroll
            for (int u = 0; u < 4; u++) {
                uint32_t bh[4], bl[4];
                uint32_t ba = w2Base + (uint32_t)(u*16)*528 + kByte;
                ldsm4(bh, ba);
                ldsm4(bl, ba + (W_W2LO - W_W2HI));
                mma_bf16(d2[2*u  ], ah2, bh[0], bh[1]);
                mma_bf16(d2[2*u  ], ah2, bl[0], bl[1]);
                mma_bf16(d2[2*u  ], al2, bh[0], bh[1]);
                mma_bf16(d2[2*u+1], ah2, bh[2], bh[3]);
                mma_bf16(d2[2*u+1], ah2, bl[2], bl[3]);
                mma_bf16(d2[2*u+1], al2, bh[2], bh[3]);
            }
        }
    }

    #pragma unroll
    for (int rh = 0; rh < 2; rh++) {
        float vals[16];
        #pragma unroll
        for (int j2 = 0; j2 < 8; j2++) {
            int col = j2*8 + 2*lq;
            vals[2*j2  ] = d2[j2][2*rh  ] + b2s[col];
            vals[2*j2+1] = d2[j2][2*rh+1] + b2s[col+1];
        }
        float s = 0.f;
        #pragma unroll
        for (int q = 0; q < 16; q++) s += vals[q];
        s += __shfl_xor_sync(0xffffffffu, s, 1);
        s += __shfl_xor_sync(0xffffffffu, s, 2);
        float mu = s * (1.f/64.f);
        float v = 0.f;
        #pragma unroll
        for (int q = 0; q < 16; q++) { float d = vals[q] - mu; v = fmaf(d, d, v); }
        v += __shfl_xor_sync(0xffffffffu, v, 1);
        v += __shfl_xor_sync(0xffffffffu, v, 2);
        float rinv = rsqrtf(v * (1.f/64.f) + 1e-5f);
        size_t row = tile*256 + w*16 + rh*8 + (l >> 2);
        #pragma unroll
        for (int j2 = 0; j2 < 8; j2++) {
            int col = j2*8 + 2*lq;
            float2 r;
            r.x = (vals[2*j2  ] - mu) * rinv * gs[col  ] + bs[col  ];
            r.y = (vals[2*j2+1] - mu) * rinv * gs[col+1] + bs[col+1];
            *(float2*)(out + row*64 + col) = r;
        }
    }
}

// ---------------- launcher ----------------
extern "C" void kernel_launch(void* const* d_in, const int* in_sizes, int n_in,
                              void* d_out, int out_size) {
    (void)in_sizes; (void)n_in; (void)out_size;
    const float* x     = (const float*)d_in[0];
    const float* att   = (const float*)d_in[1];
    const float* fwy   = (const float*)d_in[2];
    const float* fwx   = (const float*)d_in[3];
    const float* w1    = (const float*)d_in[4];
    const float* b1    = (const float*)d_in[5];
    const float* w2    = (const float*)d_in[6];
    const float* b2    = (const float*)d_in[7];
    const float* gamma = (const float*)d_in[8];
    const float* beta  = (const float*)d_in[9];
    float* out = (float*)d_out;

    cudaFuncSetAttribute(k_fwd_mma, cudaFuncAttributeMaxDynamicSharedMemorySize, FW_TOT);
    cudaFuncSetAttribute(k_mix_mma, cudaFuncAttributeMaxDynamicSharedMemorySize, MX_TOT);
    cudaFuncSetAttribute(k_inv_mma, cudaFuncAttributeMaxDynamicSharedMemorySize, IV_TOT);
    cudaFuncSetAttribute(k_mlp_mma, cudaFuncAttributeMaxDynamicSharedMemorySize, SM_MLP);

    k_weights<<<(BATCH*MODES*CI*CO)/256, 256>>>(att, fwy, fwx);
    k_wprep<<<128, 256>>>(w1, w2);
    k_tprep<<<256, 256>>>();
    k_fwd_mma<<<512, 512, FW_TOT>>>(x);
    k_mix_mma<<<2*BATCH*MODES, 512, MX_TOT>>>();
    k_inv_mma<<<2*BATCH*MM, 512, IV_TOT>>>();
    k_mlp_mma<<<(BATCH*MM*NN)/256, 512, SM_MLP>>>(b1, b2, gamma, beta, out);
}

// round 12
// speedup vs baseline: 1.3092x; 1.0016x over previous
#include <cuda_runtime.h>
#include <cuda_bf16.h>
#include <cstdint>

#define BATCH 8
#define MM 256
#define NN 256
#define CI 64
#define CO 64
#define KK 4
#define MODES 32

typedef unsigned long long u64;

// ---------------- scratch ----------------
__device__ float2 g_wy [BATCH*MODES*CI*CO];
__device__ float2 g_wx [BATCH*MODES*CI*CO];
__device__ float2 g_XfY[BATCH*MODES*MM*CI];
__device__ float2 g_XfX[BATCH*MODES*NN*CI];
__device__ float2 g_YfY[BATCH*MODES*MM*CO];
__device__ float2 g_YfX[BATCH*MODES*NN*CO];
__device__ float  g_xsum [(size_t)BATCH*MM*NN*CO];
__device__ float  g_xsum2[(size_t)BATCH*MM*NN*CO];

// MLP weight image
#define W_W1HI 0
#define W_W1LO 36864
#define W_W2HI 73728
#define W_W2LO 107520
#define W_TOT  141312
__device__ __align__(16) unsigned char g_Wimg[W_TOT];

// transform tables (split bf16) — ldmatrix strides
#define T_ST   528
#define T_LOB  33792
#define T_TOT  67584
__device__ __align__(16) unsigned char g_TY[T_TOT];
__device__ __align__(16) unsigned char g_TX[T_TOT];
#define S_ST   144
#define S_LOB  36864
#define S_TOT  73728
__device__ __align__(16) unsigned char g_SY[S_TOT];
__device__ __align__(16) unsigned char g_SX[S_TOT];

// ---------------- helpers ----------------
__device__ __forceinline__ uint32_t smem_u32(const void* p) {
    uint32_t a;
    asm("{ .reg .u64 t; cvta.to.shared.u64 t, %1; cvt.u32.u64 %0, t; }" : "=r"(a) : "l"(p));
    return a;
}
__device__ __forceinline__ void ldsm4(uint32_t* r, uint32_t a) {
    asm volatile("ldmatrix.sync.aligned.m8n8.x4.shared.b16 {%0,%1,%2,%3}, [%4];"
        : "=r"(r[0]), "=r"(r[1]), "=r"(r[2]), "=r"(r[3]) : "r"(a));
}
__device__ __forceinline__ void ldsm4t(uint32_t* r, uint32_t a) {
    asm volatile("ldmatrix.sync.aligned.m8n8.x4.trans.shared.b16 {%0,%1,%2,%3}, [%4];"
        : "=r"(r[0]), "=r"(r[1]), "=r"(r[2]), "=r"(r[3]) : "r"(a));
}
__device__ __forceinline__ void cvt_pair(float v0, float v1, uint32_t& hi, uint32_t& lo) {
    __nv_bfloat16 h0 = __float2bfloat16(v0), h1 = __float2bfloat16(v1);
    float r0 = v0 - __bfloat162float(h0);
    float r1 = v1 - __bfloat162float(h1);
    hi = (uint32_t)__bfloat16_as_ushort(h0) | ((uint32_t)__bfloat16_as_ushort(h1) << 16);
    lo = (uint32_t)__bfloat16_as_ushort(__float2bfloat16(r0))
       | ((uint32_t)__bfloat16_as_ushort(__float2bfloat16(r1)) << 16);
}
__device__ __forceinline__ void mma_bf16(float* d, const uint32_t* a, uint32_t b0, uint32_t b1) {
    asm volatile(
        "mma.sync.aligned.m16n8k16.row.col.f32.bf16.bf16.f32 "
        "{%0,%1,%2,%3},{%4,%5,%6,%7},{%8,%9},{%0,%1,%2,%3};"
        : "+f"(d[0]), "+f"(d[1]), "+f"(d[2]), "+f"(d[3])
        : "r"(a[0]), "r"(a[1]), "r"(a[2]), "r"(a[3]), "r"(b0), "r"(b1));
}
__device__ __forceinline__ void wr_split(unsigned char* phi, unsigned char* plo, float v) {
    __nv_bfloat16 h = __float2bfloat16(v);
    float r = v - __bfloat162float(h);
    *(unsigned short*)phi = __bfloat16_as_ushort(h);
    *(unsigned short*)plo = __bfloat16_as_ushort(__float2bfloat16(r));
}

// ---------------- K0: spectral weights ----------------
__global__ void k_weights(const float* __restrict__ att,
                          const float* __restrict__ fwy,
                          const float* __restrict__ fwx) {
    int gid = blockIdx.x * 256 + threadIdx.x;
    int o = gid & 63, i = (gid >> 6) & 63, f = (gid >> 12) & 31, b = gid >> 17;
    float a0 = att[b*KK+0], a1 = att[b*KK+1], a2 = att[b*KK+2], a3 = att[b*KK+3];
    const int ks = CI*CO*MODES*2;
    int base = ((i*CO + o)*MODES + f)*2;
    float yr, yi, xr, xi;
    yr = a0*fwy[base   ] + a1*fwy[base+ks   ] + a2*fwy[base+2*ks  ] + a3*fwy[base+3*ks  ];
    yi = a0*fwy[base+1 ] + a1*fwy[base+ks+1 ] + a2*fwy[base+2*ks+1] + a3*fwy[base+3*ks+1];
    xr = a0*fwx[base   ] + a1*fwx[base+ks   ] + a2*fwx[base+2*ks  ] + a3*fwx[base+3*ks  ];
    xi = a0*fwx[base+1 ] + a1*fwx[base+ks+1 ] + a2*fwx[base+2*ks+1] + a3*fwx[base+3*ks+1];
    g_wy[gid] = make_float2(yr, yi);
    g_wx[gid] = make_float2(xr, xi);
}

// ---------------- K0b: MLP weight image ----------------
__global__ void k_wprep(const float* __restrict__ w1, const float* __restrict__ w2) {
    int gid = blockIdx.x * 256 + threadIdx.x;
    if (gid < 16384) {
        int i = gid >> 8, j = gid & 255;
        uint32_t off = (uint32_t)j*144 + (uint32_t)i*2;
        wr_split(g_Wimg + W_W1HI + off, g_Wimg + W_W1LO + off, w1[gid]);
    } else {
        int idx = gid - 16384;
        int j = idx >> 6, o = idx & 63;
        uint32_t off = (uint32_t)o*528 + (uint32_t)j*2;
        wr_split(g_Wimg + W_W2HI + off, g_Wimg + W_W2LO + off, w2[idx]);
    }
}

// ---------------- K0c: transform tables ----------------
__global__ void k_tprep() {
    int gid = blockIdx.x * 256 + threadIdx.x;
    int sel = gid >> 14;
    int idx = gid & 16383;
    const float inv = 0.04428074428f;
    if (sel == 0) {
        int r = idx >> 8, k = idx & 255;
        int f = r >> 1;
        float ang = (float)((f*k) & 255) * (1.0f/128.0f);
        float v = (r & 1) ? -0.0625f*sinpif(ang) : 0.0625f*cospif(ang);
        uint32_t off = (uint32_t)r*T_ST + (uint32_t)k*2;
        wr_split(g_TY + off, g_TY + T_LOB + off, v);
    } else if (sel == 1) {
        int r = idx >> 8, k = idx & 255;
        int f = r >> 1;
        float v;
        if (r & 1) v = -2.0f*inv*sinpif((float)((f*k) % 510) * (1.0f/255.0f));
        else       v = (k == 0) ? inv : ((k == 255) ? ((f & 1) ? -inv : inv) : 0.0f);
        uint32_t off = (uint32_t)r*T_ST + (uint32_t)k*2;
        wr_split(g_TX + off, g_TX + T_LOB + off, v);
    } else if (sel == 2) {
        int r = idx >> 6, k = idx & 63;
        int f = k >> 1;
        float ang = (float)((f*r) & 255) * (1.0f/128.0f);
        float v = (k & 1) ? -0.125f*sinpif(ang)
                          : ((f == 0) ? 0.0625f : 0.125f)*cospif(ang);
        uint32_t off = (uint32_t)r*S_ST + (uint32_t)k*2;
        wr_split(g_SY + off, g_SY + S_LOB + off, v);
    } else {
        int r = idx >> 6, k = idx & 63;
        int f = k >> 1;
        float ang = (float)((f*r) % 510) * (1.0f/255.0f);
        float v = (k & 1) ? -2.0f*inv*sinpif(ang)
                          : ((f == 0) ? inv : 2.0f*inv)*cospif(ang);
        uint32_t off = (uint32_t)r*S_ST + (uint32_t)k*2;
        wr_split(g_SX + off, g_SX + S_LOB + off, v);
    }
}

// ---------------- K1: forward transforms (512 thr, pipelined) — unchanged R11 ----------------
#define FW_B    67584
#define FB_LOB  36864
#define FW_TOT  141312
__global__ void __launch_bounds__(512) k_fwd_mma(const float* __restrict__ x) {
    extern __shared__ __align__(16) unsigned char sm[];
    int t = threadIdx.x, w = t >> 5, l = t & 31, lq = l & 3;
    int z = blockIdx.x;
    int branch = z >> 8;
    int grp = z & 255;
    int b = grp >> 5, g = grp & 31;

    {
        const float4* src = (const float4*)(branch ? g_TX : g_TY);
        float4* dst = (float4*)sm;
        for (int i = t; i < T_TOT/16; i += 512) dst[i] = src[i];
    }

    int mt = w & 3, nh = w >> 2;
    uint32_t smb = smem_u32(sm);
    uint32_t aAddr = smb + (uint32_t)(mt*16 + (l & 15))*T_ST + (uint32_t)((l >> 4)*16);
    uint32_t bAddr = smb + FW_B
                   + (uint32_t)((l & 7) + ((l >> 3) & 1)*8)*144
                   + (uint32_t)(nh*32) + (uint32_t)((l >> 4)*16);
    float* outb = (float*)(branch ? g_XfX : g_XfY);

    float4 v[8];
    {
        int mn0 = g*8;
        #pragma unroll
        for (int it = 0; it < 8; it++) {
            int flat = it*512 + t;
            int c4 = flat & 15, k = flat >> 4;
            const float* p0;
            if (branch == 0) p0 = x + ((size_t)(b*256 + mn0))*16384 + (size_t)k*64 + c4*4;
            else             p0 = x + (((size_t)(b*256 + k))*256 + mn0)*64 + c4*4;
            v[it] = *(const float4*)p0;
        }
    }

    for (int it8 = 0; it8 < 8; it8++) {
        int mn = g*8 + it8;
        __syncthreads();
        #pragma unroll
        for (int it = 0; it < 8; it++) {
            int flat = it*512 + t;
            int c4 = flat & 15, k = flat >> 4;
            uint32_t h0, l0, h1, l1;
            cvt_pair(v[it].x, v[it].y, h0, l0);
            cvt_pair(v[it].z, v[it].w, h1, l1);
            *(uint2*)(sm + FW_B + k*144 + c4*8)          = make_uint2(h0, h1);
            *(uint2*)(sm + FW_B + FB_LOB + k*144 + c4*8) = make_uint2(l0, l1);
        }
        __syncthreads();

        if (it8 < 7) {
            int mn1 = mn + 1;
            #pragma unroll
            for (int it = 0; it < 8; it++) {
                int flat = it*512 + t;
                int c4 = flat & 15, k = flat >> 4;
                const float* p0;
                if (branch == 0) p0 = x + ((size_t)(b*256 + mn1))*16384 + (size_t)k*64 + c4*4;
                else             p0 = x + (((size_t)(b*256 + k))*256 + mn1)*64 + c4*4;
                v[it] = *(const float4*)p0;
            }
        }

        float c[2][4];
        #pragma unroll
        for (int j = 0; j < 2; j++)
            #pragma unroll
            for (int q = 0; q < 4; q++) c[j][q] = 0.f;

        #pragma unroll
        for (int kk = 0; kk < 16; kk++) {
            uint32_t ah[4], al[4], bh[4], bl[4];
            ldsm4(ah, aAddr + kk*32);
            ldsm4(al, aAddr + T_LOB + kk*32);
            ldsm4t(bh, bAddr + kk*2304);
            ldsm4t(bl, bAddr + FB_LOB + kk*2304);
            mma_bf16(c[0], ah, bh[0], bh[1]);
            mma_bf16(c[0], ah, bl[0], bl[1]);
            mma_bf16(c[0], al, bh[0], bh[1]);
            mma_bf16(c[1], ah, bh[2], bh[3]);
            mma_bf16(c[1], ah, bl[2], bl[3]);
            mma_bf16(c[1], al, bh[2], bh[3]);
        }

        #pragma unroll
        for (int j = 0; j < 2; j++) {
            int ch = nh*16 + j*8 + 2*lq;
            int r0 = mt*16 + (l >> 2), r1 = r0 + 8;
            size_t base0 = ((size_t)(b*32 + (r0 >> 1))*256 + mn)*128 + ch*2 + (r0 & 1);
            size_t base1 = ((size_t)(b*32 + (r1 >> 1))*256 + mn)*128 + ch*2 + (r1 & 1);
            outb[base0]     = c[j][0];
            outb[base0 + 2] = c[j][1];
            outb[base1]     = c[j][2];
            outb[base1 + 2] = c[j][3];
        }
    }
}

// ---------------- K2: complex GEMM via mma.sync (ldmatrix fragments) ----------------
#define MX_AHI 0
#define MX_ALO 69632
#define MX_WHI 139264
#define MX_WLO 174080
#define MX_TOT 208896

__global__ void __launch_bounds__(512) k_mix_mma() {
    extern __shared__ __align__(16) unsigned char sm[];
    int t = threadIdx.x, w = t >> 5, l = t & 31, lq = l & 3;
    int z = blockIdx.x, branch = z >> 8, bf = z & 255;
    const float2* A = (branch ? g_XfX : g_XfY) + (size_t)bf*MM*CI;
    const float2* W = (branch ? g_wx  : g_wy ) + (size_t)bf*CI*CO;
    float2*       C = (branch ? g_YfX : g_YfY) + (size_t)bf*MM*CO;

    {
        const float4* Af = (const float4*)A;
        #pragma unroll
        for (int it = 0; it < 16; it++) {
            int ft = it*512 + t;
            int row = ft >> 5, c4 = ft & 31;
            float4 v = Af[ft];
            uint32_t h01, l01, h23, l23;
            cvt_pair(v.x, v.y, h01, l01);
            cvt_pair(v.z, v.w, h23, l23);
            *(uint2*)(sm + MX_AHI + row*272 + c4*8) = make_uint2(h01, h23);
            *(uint2*)(sm + MX_ALO + row*272 + c4*8) = make_uint2(l01, l23);
        }
    }
    {
        #pragma unroll
        for (int it = 0; it < 8; it++) {
            int flat = it*512 + t;
            int i = flat >> 6, o = flat & 63;
            float2 wv = W[flat];
            uint32_t ha, la, hb, lb;
            cvt_pair(wv.x, -wv.y, ha, la);
            cvt_pair(wv.y,  wv.x, hb, lb);
            *(uint32_t*)(sm + MX_WHI + (2*o  )*272 + i*4) = ha;
            *(uint32_t*)(sm + MX_WHI + (2*o+1)*272 + i*4) = hb;
            *(uint32_t*)(sm + MX_WLO + (2*o  )*272 + i*4) = la;
            *(uint32_t*)(sm + MX_WLO + (2*o+1)*272 + i*4) = lb;
        }
    }
    __syncthreads();

    uint32_t smb = smem_u32(sm);
    int m0 = w*16;
    // A fragments: rows m0..m0+15, 272B stride (68 words ≡ 4 mod 32: conflict-free)
    uint32_t aAddr = smb + MX_AHI + (uint32_t)(m0 + (l & 15))*272 + (uint32_t)((l >> 4)*16);
    // B fragments (mlp W pattern): 16 n-rows per ldsm4
    uint32_t bBase = smb + MX_WHI + (uint32_t)(((l >> 4)*8) + (l & 7))*272
                   + (uint32_t)(((l >> 3) & 1)*16);

    float acc[16][4];
    #pragma unroll
    for (int j2 = 0; j2 < 16; j2++)
        #pragma unroll
        for (int q = 0; q < 4; q++) acc[j2][q] = 0.f;

    #pragma unroll
    for (int kt = 0; kt < 8; kt++) {
        uint32_t ah[4], al[4];
        ldsm4(ah, aAddr + kt*32);
        ldsm4(al, aAddr + (MX_ALO - MX_AHI) + kt*32);
        #pragma unroll
        for (int u = 0; u < 8; u++) {
            uint32_t bh[4], bl[4];
            uint32_t ba = bBase + (uint32_t)(u*16)*272 + kt*32;
            ldsm4(bh, ba);
            ldsm4(bl, ba + (MX_WLO - MX_WHI));
            mma_bf16(acc[2*u  ], ah, bh[0], bh[1]);
            mma_bf16(acc[2*u  ], ah, bl[0], bl[1]);
            mma_bf16(acc[2*u  ], al, bh[0], bh[1]);
            mma_bf16(acc[2*u+1], ah, bh[2], bh[3]);
            mma_bf16(acc[2*u+1], ah, bl[2], bl[3]);
            mma_bf16(acc[2*u+1], al, bh[2], bh[3]);
        }
    }

    float* Cf = (float*)C;
    #pragma unroll
    for (int j2 = 0; j2 < 16; j2++) {
        int row = m0 + (l >> 2);
        int col = j2*8 + 2*lq;
        *(float2*)(Cf + (size_t)row*128 + col)     = make_float2(acc[j2][0], acc[j2][1]);
        *(float2*)(Cf + (size_t)(row+8)*128 + col) = make_float2(acc[j2][2], acc[j2][3]);
    }
}

// ---------------- K3: inverse transforms (512 thr, amortized + pipelined) ----------------
#define IV_B   73728
#define IV_BLO 9216
#define IV_TOT 92160
__global__ void __launch_bounds__(512) k_inv_mma() {
    extern __shared__ __align__(16) unsigned char sm[];
    int t = threadIdx.x, w = t >> 5, l = t & 31, lq = l & 3;
    int z = blockIdx.x;             // 512 = 2 branch * 8 b * 32 groups
    int branch = z >> 8;
    int grp = z & 255;
    int b = grp >> 5, g = grp & 31;

    {
        const float4* src = (const float4*)(branch ? g_SX : g_SY);
        float4* dst = (float4*)sm;
        for (int i = t; i < S_TOT/16; i += 512) dst[i] = src[i];
    }

    uint32_t smb = smem_u32(sm);
    uint32_t aAddr = smb + (uint32_t)(w*16 + (l & 15))*S_ST + (uint32_t)((l >> 4)*16);
    uint32_t bBase = smb + IV_B
                   + (uint32_t)((l & 7) + ((l >> 3) & 1)*8)*144
                   + (uint32_t)((l >> 4)*16);
    const float2* Y = (branch ? g_YfX : g_YfY);
    float* outb = branch ? g_xsum2 : g_xsum;

    // prefetch first item's Y
    float4 y[2];
    {
        int mn0 = g*8;
        #pragma unroll
        for (int it = 0; it < 2; it++) {
            int flat = it*512 + t;
            int f = flat >> 5, cp = flat & 31;
            y[it] = *(const float4*)(Y + ((size_t)(b*32 + f)*256 + mn0)*64 + 2*cp);
        }
    }
    __syncthreads();               // table visible

    // hoist loop-invariant A fragments (S table)
    uint32_t ah[4][4], al[4][4];
    #pragma unroll
    for (int kk = 0; kk < 4; kk++) {
        ldsm4(ah[kk], aAddr + kk*32);
        ldsm4(al[kk], aAddr + S_LOB + kk*32);
    }

    for (int it8 = 0; it8 < 8; it8++) {
        int mn = g*8 + it8;
        if (it8 > 0) __syncthreads();   // previous MMA done reading B
        #pragma unroll
        for (int it = 0; it < 2; it++) {
            int flat = it*512 + t;
            int f = flat >> 5, cp = flat & 31;
            float4 v = y[it];
            uint32_t rh_, rl_, ih_, il_;
            cvt_pair(v.x, v.z, rh_, rl_);
            cvt_pair(v.y, v.w, ih_, il_);
            *(uint32_t*)(sm + IV_B + (2*f  )*144 + cp*4)          = rh_;
            *(uint32_t*)(sm + IV_B + (2*f+1)*144 + cp*4)          = ih_;
            *(uint32_t*)(sm + IV_B + IV_BLO + (2*f  )*144 + cp*4) = rl_;
            *(uint32_t*)(sm + IV_B + IV_BLO + (2*f+1)*144 + cp*4) = il_;
        }
        __syncthreads();

        // prefetch next item's Y (hidden under MMA)
        if (it8 < 7) {
            int mn1 = mn + 1;
            #pragma unroll
            for (int it = 0; it < 2; it++) {
                int flat = it*512 + t;
                int f = flat >> 5, cp = flat & 31;
                y[it] = *(const float4*)(Y + ((size_t)(b*32 + f)*256 + mn1)*64 + 2*cp);
            }
        }

        float c[8][4];
        #pragma unroll
        for (int j = 0; j < 8; j++)
            #pragma unroll
            for (int q = 0; q < 4; q++) c[j][q] = 0.f;

        #pragma unroll
        for (int kk = 0; kk < 4; kk++) {
            #pragma unroll
            for (int u = 0; u < 4; u++) {
                uint32_t bh[4], bl[4];
                uint32_t ba = bBase + (uint32_t)(u*32) + (uint32_t)(kk*16)*144;
                ldsm4t(bh, ba);
                ldsm4t(bl, ba + IV_BLO);
                mma_bf16(c[2*u  ], ah[kk], bh[0], bh[1]);
                mma_bf16(c[2*u  ], ah[kk], bl[0], bl[1]);
                mma_bf16(c[2*u  ], al[kk], bh[0], bh[1]);
                mma_bf16(c[2*u+1], ah[kk], bh[2], bh[3]);
                mma_bf16(c[2*u+1], ah[kk], bl[2], bl[3]);
                mma_bf16(c[2*u+1], al[kk], bh[2], bh[3]);
            }
        }

        #pragma unroll
        for (int j = 0; j < 8; j++) {
            int col = j*8 + 2*lq;
            int r0 = w*16 + (l >> 2), r1 = r0 + 8;
            size_t a0, a1;
            if (branch == 0) {
                a0 = (((size_t)(b*256 + mn))*256 + r0)*64 + col;
                a1 = (((size_t)(b*256 + mn))*256 + r1)*64 + col;
            } else {
                a0 = (((size_t)(b*256 + r0))*256 + mn)*64 + col;
                a1 = (((size_t)(b*256 + r1))*256 + mn)*64 + col;
            }
            *(float2*)(outb + a0) = make_float2(c[j][0], c[j][1]);
            *(float2*)(outb + a1) = make_float2(c[j][2], c[j][3]);
        }
    }
}

// ---------------- K4: MLP (512 thr, per-tile grid, ldmatrix) — unchanged ----------------
#define SA_HI   0
#define SA_LO   36864
#define SW_BASE 73728
#define S_B1    215040
#define S_B2    216064
#define S_GAM   216320
#define S_BET   216576
#define SM_MLP  216832

__global__ void __launch_bounds__(512) k_mlp_mma(const float* __restrict__ b1,
                                                 const float* __restrict__ b2,
                                                 const float* __restrict__ gamma,
                                                 const float* __restrict__ beta,
                                                 float* __restrict__ out) {
    extern __shared__ __align__(16) unsigned char sm[];
    int t = threadIdx.x;
    int w = t >> 5, l = t & 31;
    int lq = l & 3;
    size_t tile = blockIdx.x;

    {
        const float4* src = (const float4*)g_Wimg;
        float4* dst = (float4*)(sm + SW_BASE);
        for (int i = t; i < W_TOT/16; i += 512) dst[i] = src[i];
    }
    float* b1s = (float*)(sm + S_B1);
    float* b2s = (float*)(sm + S_B2);
    float* gs  = (float*)(sm + S_GAM);
    float* bs  = (float*)(sm + S_BET);
    if (t < 256) b1s[t] = b1[t];
    if (t >= 256 && t < 320) { int q = t - 256; b2s[q] = b2[q]; gs[q] = gamma[q]; bs[q] = beta[q]; }

    {
        int row = t >> 1, qh = (t & 1) * 8;
        const float4* xs  = (const float4*)(g_xsum  + (tile*256 + row)*64);
        const float4* xs2 = (const float4*)(g_xsum2 + (tile*256 + row)*64);
        unsigned char* rh = sm + SA_HI + row*144;
        unsigned char* rl = sm + SA_LO + row*144;
        #pragma unroll
        for (int q = 0; q < 8; q++) {
            float4 v = xs[qh + q], v2 = xs2[qh + q];
            v.x += v2.x; v.y += v2.y; v.z += v2.z; v.w += v2.w;
            uint32_t h0, l0, h1, l1;
            cvt_pair(v.x, v.y, h0, l0);
            cvt_pair(v.z, v.w, h1, l1);
            *(uint32_t*)(rh + (qh+q)*8    ) = h0;
            *(uint32_t*)(rh + (qh+q)*8 + 4) = h1;
            *(uint32_t*)(rl + (qh+q)*8    ) = l0;
            *(uint32_t*)(rl + (qh+q)*8 + 4) = l1;
        }
    }
    __syncthreads();

    uint32_t smb = smem_u32(sm);
    uint32_t aAddr  = smb + SA_HI + (uint32_t)(w*16 + (l & 15))*144 + (uint32_t)((l >> 4)*16);
    uint32_t w1Base = smb + SW_BASE + W_W1HI
                    + (uint32_t)(((l >> 4)*8) + (l & 7))*144 + (uint32_t)(((l >> 3) & 1)*16);
    uint32_t w2Base = smb + SW_BASE + W_W2HI
                    + (uint32_t)(((l >> 4)*8) + (l & 7))*528 + (uint32_t)(((l >> 3) & 1)*16);

    float d2[8][4];
    #pragma unroll
    for (int j = 0; j < 8; j++)
        #pragma unroll
        for (int q = 0; q < 4; q++) d2[j][q] = 0.f;

    for (int c = 0; c < 4; c++) {
        float h[8][4];
        #pragma unroll
        for (int j = 0; j < 8; j++)
            #pragma unroll
            for (int q = 0; q < 4; q++) h[j][q] = 0.f;

        #pragma unroll
        for (int kt = 0; kt < 4; kt++) {
            uint32_t ah[4], al[4];
            ldsm4(ah, aAddr + kt*32);
            ldsm4(al, aAddr + (SA_LO - SA_HI) + kt*32);
            #pragma unroll
            for (int u = 0; u < 4; u++) {
                uint32_t bh[4], bl[4];
                uint32_t ba = w1Base + (uint32_t)(c*64 + u*16)*144 + kt*32;
                ldsm4(bh, ba);
                ldsm4(bl, ba + (W_W1LO - W_W1HI));
                mma_bf16(h[2*u  ], ah, bh[0], bh[1]);
                mma_bf16(h[2*u  ], ah, bl[0], bl[1]);
                mma_bf16(h[2*u  ], al, bh[0], bh[1]);
                mma_bf16(h[2*u+1], ah, bh[2], bh[3]);
                mma_bf16(h[2*u+1], ah, bl[2], bl[3]);
                mma_bf16(h[2*u+1], al, bh[2], bh[3]);
            }
        }

        #pragma unroll
        for (int kt2 = 0; kt2 < 4; kt2++) {
            int j = 2*kt2;
            uint32_t ah2[4], al2[4];
            {
                int g0 = c*64 + j*8 + 2*lq;
                float bA = b1s[g0],   bB = b1s[g0+1];
                float bC = b1s[g0+8], bD = b1s[g0+9];
                float v0 = fmaxf(h[j][0] + bA, 0.f);
                float v1 = fmaxf(h[j][1] + bB, 0.f);
                cvt_pair(v0, v1, ah2[0], al2[0]);
                v0 = fmaxf(h[j][2] + bA, 0.f);
                v1 = fmaxf(h[j][3] + bB, 0.f);
                cvt_pair(v0, v1, ah2[1], al2[1]);
                v0 = fmaxf(h[j+1][0] + bC, 0.f);
                v1 = fmaxf(h[j+1][1] + bD, 0.f);
                cvt_pair(v0, v1, ah2[2], al2[2]);
                v0 = fmaxf(h[j+1][2] + bC, 0.f);
                v1 = fmaxf(h[j+1][3] + bD, 0.f);
                cvt_pair(v0, v1, ah2[3], al2[3]);
            }
            uint32_t kByte = (uint32_t)(c*128 + kt2*32);
            #pragma unroll
            for (int u = 0; u < 4; u++) {
                uint32_t bh[4], bl[4];
                uint32_t ba = w2Base + (uint32_t)(u*16)*528 + kByte;
                ldsm4(bh, ba);
                ldsm4(bl, ba + (W_W2LO - W_W2HI));
                mma_bf16(d2[2*u  ], ah2, bh[0], bh[1]);
                mma_bf16(d2[2*u  ], ah2, bl[0], bl[1]);
                mma_bf16(d2[2*u  ], al2, bh[0], bh[1]);
                mma_bf16(d2[2*u+1], ah2, bh[2], bh[3]);
                mma_bf16(d2[2*u+1], ah2, bl[2], bl[3]);
                mma_bf16(d2[2*u+1], al2, bh[2], bh[3]);
            }
        }
    }

    #pragma unroll
    for (int rh = 0; rh < 2; rh++) {
        float vals[16];
        #pragma unroll
        for (int j2 = 0; j2 < 8; j2++) {
            int col = j2*8 + 2*lq;
            vals[2*j2  ] = d2[j2][2*rh  ] + b2s[col];
            vals[2*j2+1] = d2[j2][2*rh+1] + b2s[col+1];
        }
        float s = 0.f;
        #pragma unroll
        for (int q = 0; q < 16; q++) s += vals[q];
        s += __shfl_xor_sync(0xffffffffu, s, 1);
        s += __shfl_xor_sync(0xffffffffu, s, 2);
        float mu = s * (1.f/64.f);
        float v = 0.f;
        #pragma unroll
        for (int q = 0; q < 16; q++) { float d = vals[q] - mu; v = fmaf(d, d, v); }
        v += __shfl_xor_sync(0xffffffffu, v, 1);
        v += __shfl_xor_sync(0xffffffffu, v, 2);
        float rinv = rsqrtf(v * (1.f/64.f) + 1e-5f);
        size_t row = tile*256 + w*16 + rh*8 + (l >> 2);
        #pragma unroll
        for (int j2 = 0; j2 < 8; j2++) {
            int col = j2*8 + 2*lq;
            float2 r;
            r.x = (vals[2*j2  ] - mu) * rinv * gs[col  ] + bs[col  ];
            r.y = (vals[2*j2+1] - mu) * rinv * gs[col+1] + bs[col+1];
            *(float2*)(out + row*64 + col) = r;
        }
    }
}

// ---------------- launcher ----------------
extern "C" void kernel_launch(void* const* d_in, const int* in_sizes, int n_in,
                              void* d_out, int out_size) {
    (void)in_sizes; (void)n_in; (void)out_size;
    const float* x     = (const float*)d_in[0];
    const float* att   = (const float*)d_in[1];
    const float* fwy   = (const float*)d_in[2];
    const float* fwx   = (const float*)d_in[3];
    const float* w1    = (const float*)d_in[4];
    const float* b1    = (const float*)d_in[5];
    const float* w2    = (const float*)d_in[6];
    const float* b2    = (const float*)d_in[7];
    const float* gamma = (const float*)d_in[8];
    const float* beta  = (const float*)d_in[9];
    float* out = (float*)d_out;

    cudaFuncSetAttribute(k_fwd_mma, cudaFuncAttributeMaxDynamicSharedMemorySize, FW_TOT);
    cudaFuncSetAttribute(k_mix_mma, cudaFuncAttributeMaxDynamicSharedMemorySize, MX_TOT);
    cudaFuncSetAttribute(k_inv_mma, cudaFuncAttributeMaxDynamicSharedMemorySize, IV_TOT);
    cudaFuncSetAttribute(k_mlp_mma, cudaFuncAttributeMaxDynamicSharedMemorySize, SM_MLP);

    k_weights<<<(BATCH*MODES*CI*CO)/256, 256>>>(att, fwy, fwx);
    k_wprep<<<128, 256>>>(w1, w2);
    k_tprep<<<256, 256>>>();
    k_fwd_mma<<<512, 512, FW_TOT>>>(x);
    k_mix_mma<<<2*BATCH*MODES, 512, MX_TOT>>>();
    k_inv_mma<<<512, 512, IV_TOT>>>();
    k_mlp_mma<<<(BATCH*MM*NN)/256, 512, SM_MLP>>>(b1, b2, gamma, beta, out);
}

// round 13
// speedup vs baseline: 1.9068x; 1.4565x over previous
#include <cuda_runtime.h>
#include <cuda_fp16.h>
#include <cstdint>

#define BATCH 8
#define MM 256
#define NN 256
#define CI 64
#define CO 64
#define KK 4
#define MODES 32

// ---------------- scratch ----------------
__device__ float2 g_wy [BATCH*MODES*CI*CO];
__device__ float2 g_wx [BATCH*MODES*CI*CO];
__device__ float2 g_XfY[BATCH*MODES*MM*CI];
__device__ float2 g_XfX[BATCH*MODES*NN*CI];
__device__ float2 g_YfY[BATCH*MODES*MM*CO];
__device__ float2 g_YfX[BATCH*MODES*NN*CO];
__device__ float  g_xsum [(size_t)BATCH*MM*NN*CO];
__device__ float  g_xsum2[(size_t)BATCH*MM*NN*CO];

// MLP weight image (single fp16): W1 [256n][64k] stride 144; W2 [64n][256k] stride 528
#define W_W1   0
#define W_W2   36864
#define W_TOT  70656
__device__ __align__(16) unsigned char g_Wimg[W_TOT];

// transform tables (single fp16)
#define T_ST   528
#define T_TOT  33792
__device__ __align__(16) unsigned char g_TY[T_TOT];
__device__ __align__(16) unsigned char g_TX[T_TOT];
#define S_ST   144
#define S_TOT  36864
__device__ __align__(16) unsigned char g_SY[S_TOT];
__device__ __align__(16) unsigned char g_SX[S_TOT];

// ---------------- helpers ----------------
__device__ __forceinline__ uint32_t smem_u32(const void* p) {
    uint32_t a;
    asm("{ .reg .u64 t; cvta.to.shared.u64 t, %1; cvt.u32.u64 %0, t; }" : "=r"(a) : "l"(p));
    return a;
}
__device__ __forceinline__ void ldsm4(uint32_t* r, uint32_t a) {
    asm volatile("ldmatrix.sync.aligned.m8n8.x4.shared.b16 {%0,%1,%2,%3}, [%4];"
        : "=r"(r[0]), "=r"(r[1]), "=r"(r[2]), "=r"(r[3]) : "r"(a));
}
__device__ __forceinline__ void ldsm4t(uint32_t* r, uint32_t a) {
    asm volatile("ldmatrix.sync.aligned.m8n8.x4.trans.shared.b16 {%0,%1,%2,%3}, [%4];"
        : "=r"(r[0]), "=r"(r[1]), "=r"(r[2]), "=r"(r[3]) : "r"(a));
}
__device__ __forceinline__ uint32_t pk_h2(__half a, __half b) {
    __half2 t; t.x = a; t.y = b; return *(uint32_t*)&t;
}
__device__ __forceinline__ void cvt_pair_h(float v0, float v1, uint32_t& hi, uint32_t& lo) {
    __half h0 = __float2half(v0), h1 = __float2half(v1);
    float r0 = v0 - __half2float(h0);
    float r1 = v1 - __half2float(h1);
    hi = pk_h2(h0, h1);
    lo = pk_h2(__float2half(r0), __float2half(r1));
}
__device__ __forceinline__ void mma_f16(float* d, const uint32_t* a, uint32_t b0, uint32_t b1) {
    asm volatile(
        "mma.sync.aligned.m16n8k16.row.col.f32.f16.f16.f32 "
        "{%0,%1,%2,%3},{%4,%5,%6,%7},{%8,%9},{%0,%1,%2,%3};"
        : "+f"(d[0]), "+f"(d[1]), "+f"(d[2]), "+f"(d[3])
        : "r"(a[0]), "r"(a[1]), "r"(a[2]), "r"(a[3]), "r"(b0), "r"(b1));
}
__device__ __forceinline__ void wr_h(unsigned char* p, float v) {
    *(__half*)p = __float2half(v);
}

// ---------------- K0: spectral weights ----------------
__global__ void k_weights(const float* __restrict__ att,
                          const float* __restrict__ fwy,
                          const float* __restrict__ fwx) {
    int gid = blockIdx.x * 256 + threadIdx.x;
    int o = gid & 63, i = (gid >> 6) & 63, f = (gid >> 12) & 31, b = gid >> 17;
    float a0 = att[b*KK+0], a1 = att[b*KK+1], a2 = att[b*KK+2], a3 = att[b*KK+3];
    const int ks = CI*CO*MODES*2;
    int base = ((i*CO + o)*MODES + f)*2;
    float yr, yi, xr, xi;
    yr = a0*fwy[base   ] + a1*fwy[base+ks   ] + a2*fwy[base+2*ks  ] + a3*fwy[base+3*ks  ];
    yi = a0*fwy[base+1 ] + a1*fwy[base+ks+1 ] + a2*fwy[base+2*ks+1] + a3*fwy[base+3*ks+1];
    xr = a0*fwx[base   ] + a1*fwx[base+ks   ] + a2*fwx[base+2*ks  ] + a3*fwx[base+3*ks  ];
    xi = a0*fwx[base+1 ] + a1*fwx[base+ks+1 ] + a2*fwx[base+2*ks+1] + a3*fwx[base+3*ks+1];
    g_wy[gid] = make_float2(yr, yi);
    g_wx[gid] = make_float2(xr, xi);
}

// ---------------- K0b: MLP weight image (single fp16) ----------------
__global__ void k_wprep(const float* __restrict__ w1, const float* __restrict__ w2) {
    int gid = blockIdx.x * 256 + threadIdx.x;
    if (gid < 16384) {
        int i = gid >> 8, j = gid & 255;
        wr_h(g_Wimg + W_W1 + (uint32_t)j*144 + (uint32_t)i*2, w1[gid]);
    } else {
        int idx = gid - 16384;
        int j = idx >> 6, o = idx & 63;
        wr_h(g_Wimg + W_W2 + (uint32_t)o*528 + (uint32_t)j*2, w2[idx]);
    }
}

// ---------------- K0c: transform tables (single fp16) ----------------
__global__ void k_tprep() {
    int gid = blockIdx.x * 256 + threadIdx.x;
    int sel = gid >> 14;
    int idx = gid & 16383;
    const float inv = 0.04428074428f;
    if (sel == 0) {
        int r = idx >> 8, k = idx & 255;
        int f = r >> 1;
        float ang = (float)((f*k) & 255) * (1.0f/128.0f);
        float v = (r & 1) ? -0.0625f*sinpif(ang) : 0.0625f*cospif(ang);
        wr_h(g_TY + (uint32_t)r*T_ST + (uint32_t)k*2, v);
    } else if (sel == 1) {
        int r = idx >> 8, k = idx & 255;
        int f = r >> 1;
        float v;
        if (r & 1) v = -2.0f*inv*sinpif((float)((f*k) % 510) * (1.0f/255.0f));
        else       v = (k == 0) ? inv : ((k == 255) ? ((f & 1) ? -inv : inv) : 0.0f);
        wr_h(g_TX + (uint32_t)r*T_ST + (uint32_t)k*2, v);
    } else if (sel == 2) {
        int r = idx >> 6, k = idx & 63;
        int f = k >> 1;
        float ang = (float)((f*r) & 255) * (1.0f/128.0f);
        float v = (k & 1) ? -0.125f*sinpif(ang)
                          : ((f == 0) ? 0.0625f : 0.125f)*cospif(ang);
        wr_h(g_SY + (uint32_t)r*S_ST + (uint32_t)k*2, v);
    } else {
        int r = idx >> 6, k = idx & 63;
        int f = k >> 1;
        float ang = (float)((f*r) % 510) * (1.0f/255.0f);
        float v = (k & 1) ? -2.0f*inv*sinpif(ang)
                          : ((f == 0) ? inv : 2.0f*inv)*cospif(ang);
        wr_h(g_SX + (uint32_t)r*S_ST + (uint32_t)k*2, v);
    }
}

// ---------------- K1: forward transforms (512 thr, pipelined; T single fp16) ----------------
#define FW_B    33792
#define FB_LOB  36864
#define FW_TOT  107520
__global__ void __launch_bounds__(512) k_fwd_mma(const float* __restrict__ x) {
    extern __shared__ __align__(16) unsigned char sm[];
    int t = threadIdx.x, w = t >> 5, l = t & 31, lq = l & 3;
    int z = blockIdx.x;
    int branch = z >> 8;
    int grp = z & 255;
    int b = grp >> 5, g = grp & 31;

    {
        const float4* src = (const float4*)(branch ? g_TX : g_TY);
        float4* dst = (float4*)sm;
        for (int i = t; i < T_TOT/16; i += 512) dst[i] = src[i];
    }

    int mt = w & 3, nh = w >> 2;
    uint32_t smb = smem_u32(sm);
    uint32_t aAddr = smb + (uint32_t)(mt*16 + (l & 15))*T_ST + (uint32_t)((l >> 4)*16);
    uint32_t bAddr = smb + FW_B
                   + (uint32_t)((l & 7) + ((l >> 3) & 1)*8)*144
                   + (uint32_t)(nh*32) + (uint32_t)((l >> 4)*16);
    float* outb = (float*)(branch ? g_XfX : g_XfY);

    float4 v[8];
    {
        int mn0 = g*8;
        #pragma unroll
        for (int it = 0; it < 8; it++) {
            int flat = it*512 + t;
            int c4 = flat & 15, k = flat >> 4;
            const float* p0;
            if (branch == 0) p0 = x + ((size_t)(b*256 + mn0))*16384 + (size_t)k*64 + c4*4;
            else             p0 = x + (((size_t)(b*256 + k))*256 + mn0)*64 + c4*4;
            v[it] = *(const float4*)p0;
        }
    }

    for (int it8 = 0; it8 < 8; it8++) {
        int mn = g*8 + it8;
        __syncthreads();
        #pragma unroll
        for (int it = 0; it < 8; it++) {
            int flat = it*512 + t;
            int c4 = flat & 15, k = flat >> 4;
            uint32_t h0, l0, h1, l1;
            cvt_pair_h(v[it].x, v[it].y, h0, l0);
            cvt_pair_h(v[it].z, v[it].w, h1, l1);
            *(uint2*)(sm + FW_B + k*144 + c4*8)          = make_uint2(h0, h1);
            *(uint2*)(sm + FW_B + FB_LOB + k*144 + c4*8) = make_uint2(l0, l1);
        }
        __syncthreads();

        if (it8 < 7) {
            int mn1 = mn + 1;
            #pragma unroll
            for (int it = 0; it < 8; it++) {
                int flat = it*512 + t;
                int c4 = flat & 15, k = flat >> 4;
                const float* p0;
                if (branch == 0) p0 = x + ((size_t)(b*256 + mn1))*16384 + (size_t)k*64 + c4*4;
                else             p0 = x + (((size_t)(b*256 + k))*256 + mn1)*64 + c4*4;
                v[it] = *(const float4*)p0;
            }
        }

        float c[2][4];
        #pragma unroll
        for (int j = 0; j < 2; j++)
            #pragma unroll
            for (int q = 0; q < 4; q++) c[j][q] = 0.f;

        #pragma unroll
        for (int kk = 0; kk < 16; kk++) {
            uint32_t ah[4], bh[4], bl[4];
            ldsm4(ah, aAddr + kk*32);
            ldsm4t(bh, bAddr + kk*2304);
            ldsm4t(bl, bAddr + FB_LOB + kk*2304);
            mma_f16(c[0], ah, bh[0], bh[1]);
            mma_f16(c[0], ah, bl[0], bl[1]);
            mma_f16(c[1], ah, bh[2], bh[3]);
            mma_f16(c[1], ah, bl[2], bl[3]);
        }

        #pragma unroll
        for (int j = 0; j < 2; j++) {
            int ch = nh*16 + j*8 + 2*lq;
            int r0 = mt*16 + (l >> 2), r1 = r0 + 8;
            size_t base0 = ((size_t)(b*32 + (r0 >> 1))*256 + mn)*128 + ch*2 + (r0 & 1);
            size_t base1 = ((size_t)(b*32 + (r1 >> 1))*256 + mn)*128 + ch*2 + (r1 & 1);
            outb[base0]     = c[j][0];
            outb[base0 + 2] = c[j][1];
            outb[base1]     = c[j][2];
            outb[base1 + 2] = c[j][3];
        }
    }
}

// ---------------- K2: complex GEMM (A split fp16, W single fp16) ----------------
#define MX_AHI 0
#define MX_ALO 69632
#define MX_W   139264
#define MX_TOT 174080

__global__ void __launch_bounds__(512) k_mix_mma() {
    extern __shared__ __align__(16) unsigned char sm[];
    int t = threadIdx.x, w = t >> 5, l = t & 31, lq = l & 3;
    int z = blockIdx.x, branch = z >> 8, bf = z & 255;
    const float2* A = (branch ? g_XfX : g_XfY) + (size_t)bf*MM*CI;
    const float2* W = (branch ? g_wx  : g_wy ) + (size_t)bf*CI*CO;
    float2*       C = (branch ? g_YfX : g_YfY) + (size_t)bf*MM*CO;

    {
        const float4* Af = (const float4*)A;
        #pragma unroll
        for (int it = 0; it < 16; it++) {
            int ft = it*512 + t;
            int row = ft >> 5, c4 = ft & 31;
            float4 v = Af[ft];
            uint32_t h01, l01, h23, l23;
            cvt_pair_h(v.x, v.y, h01, l01);
            cvt_pair_h(v.z, v.w, h23, l23);
            *(uint2*)(sm + MX_AHI + row*272 + c4*8) = make_uint2(h01, h23);
            *(uint2*)(sm + MX_ALO + row*272 + c4*8) = make_uint2(l01, l23);
        }
    }
    {
        #pragma unroll
        for (int it = 0; it < 8; it++) {
            int flat = it*512 + t;
            int i = flat >> 6, o = flat & 63;
            float2 wv = W[flat];
            uint32_t ha = pk_h2(__float2half(wv.x), __float2half(-wv.y));
            uint32_t hb = pk_h2(__float2half(wv.y), __float2half(wv.x));
            *(uint32_t*)(sm + MX_W + (2*o  )*272 + i*4) = ha;
            *(uint32_t*)(sm + MX_W + (2*o+1)*272 + i*4) = hb;
        }
    }
    __syncthreads();

    uint32_t smb = smem_u32(sm);
    int m0 = w*16;
    uint32_t aAddr = smb + MX_AHI + (uint32_t)(m0 + (l & 15))*272 + (uint32_t)((l >> 4)*16);
    uint32_t bBase = smb + MX_W + (uint32_t)(((l >> 4)*8) + (l & 7))*272
                   + (uint32_t)(((l >> 3) & 1)*16);

    float acc[16][4];
    #pragma unroll
    for (int j2 = 0; j2 < 16; j2++)
        #pragma unroll
        for (int q = 0; q < 4; q++) acc[j2][q] = 0.f;

    #pragma unroll
    for (int kt = 0; kt < 8; kt++) {
        uint32_t ah[4], al[4];
        ldsm4(ah, aAddr + kt*32);
        ldsm4(al, aAddr + (MX_ALO - MX_AHI) + kt*32);
        #pragma unroll
        for (int u = 0; u < 8; u++) {
            uint32_t bh[4];
            ldsm4(bh, bBase + (uint32_t)(u*16)*272 + kt*32);
            mma_f16(acc[2*u  ], ah, bh[0], bh[1]);
            mma_f16(acc[2*u  ], al, bh[0], bh[1]);
            mma_f16(acc[2*u+1], ah, bh[2], bh[3]);
            mma_f16(acc[2*u+1], al, bh[2], bh[3]);
        }
    }

    float* Cf = (float*)C;
    #pragma unroll
    for (int j2 = 0; j2 < 16; j2++) {
        int row = m0 + (l >> 2);
        int col = j2*8 + 2*lq;
        *(float2*)(Cf + (size_t)row*128 + col)     = make_float2(acc[j2][0], acc[j2][1]);
        *(float2*)(Cf + (size_t)(row+8)*128 + col) = make_float2(acc[j2][2], acc[j2][3]);
    }
}

// ---------------- K3: inverse transforms (S single fp16, Y split; amortized) ----------------
#define IV_B   36864
#define IV_BLO 9216
#define IV_TOT 55296
__global__ void __launch_bounds__(512) k_inv_mma() {
    extern __shared__ __align__(16) unsigned char sm[];
    int t = threadIdx.x, w = t >> 5, l = t & 31, lq = l & 3;
    int z = blockIdx.x;
    int branch = z >> 8;
    int grp = z & 255;
    int b = grp >> 5, g = grp & 31;

    {
        const float4* src = (const float4*)(branch ? g_SX : g_SY);
        float4* dst = (float4*)sm;
        for (int i = t; i < S_TOT/16; i += 512) dst[i] = src[i];
    }

    uint32_t smb = smem_u32(sm);
    uint32_t aAddr = smb + (uint32_t)(w*16 + (l & 15))*S_ST + (uint32_t)((l >> 4)*16);
    uint32_t bBase = smb + IV_B
                   + (uint32_t)((l & 7) + ((l >> 3) & 1)*8)*144
                   + (uint32_t)((l >> 4)*16);
    const float2* Y = (branch ? g_YfX : g_YfY);
    float* outb = branch ? g_xsum2 : g_xsum;

    float4 y[2];
    {
        int mn0 = g*8;
        #pragma unroll
        for (int it = 0; it < 2; it++) {
            int flat = it*512 + t;
            int f = flat >> 5, cp = flat & 31;
            y[it] = *(const float4*)(Y + ((size_t)(b*32 + f)*256 + mn0)*64 + 2*cp);
        }
    }
    __syncthreads();

    uint32_t ah[4][4];
    #pragma unroll
    for (int kk = 0; kk < 4; kk++) ldsm4(ah[kk], aAddr + kk*32);

    for (int it8 = 0; it8 < 8; it8++) {
        int mn = g*8 + it8;
        if (it8 > 0) __syncthreads();
        #pragma unroll
        for (int it = 0; it < 2; it++) {
            int flat = it*512 + t;
            int f = flat >> 5, cp = flat & 31;
            float4 v = y[it];
            uint32_t rh_, rl_, ih_, il_;
            cvt_pair_h(v.x, v.z, rh_, rl_);
            cvt_pair_h(v.y, v.w, ih_, il_);
            *(uint32_t*)(sm + IV_B + (2*f  )*144 + cp*4)          = rh_;
            *(uint32_t*)(sm + IV_B + (2*f+1)*144 + cp*4)          = ih_;
            *(uint32_t*)(sm + IV_B + IV_BLO + (2*f  )*144 + cp*4) = rl_;
            *(uint32_t*)(sm + IV_B + IV_BLO + (2*f+1)*144 + cp*4) = il_;
        }
        __syncthreads();

        if (it8 < 7) {
            int mn1 = mn + 1;
            #pragma unroll
            for (int it = 0; it < 2; it++) {
                int flat = it*512 + t;
                int f = flat >> 5, cp = flat & 31;
                y[it] = *(const float4*)(Y + ((size_t)(b*32 + f)*256 + mn1)*64 + 2*cp);
            }
        }

        float c[8][4];
        #pragma unroll
        for (int j = 0; j < 8; j++)
            #pragma unroll
            for (int q = 0; q < 4; q++) c[j][q] = 0.f;

        #pragma unroll
        for (int kk = 0; kk < 4; kk++) {
            #pragma unroll
            for (int u = 0; u < 4; u++) {
                uint32_t bh[4], bl[4];
                uint32_t ba = bBase + (uint32_t)(u*32) + (uint32_t)(kk*16)*144;
                ldsm4t(bh, ba);
                ldsm4t(bl, ba + IV_BLO);
                mma_f16(c[2*u  ], ah[kk], bh[0], bh[1]);
                mma_f16(c[2*u  ], ah[kk], bl[0], bl[1]);
                mma_f16(c[2*u+1], ah[kk], bh[2], bh[3]);
                mma_f16(c[2*u+1], ah[kk], bl[2], bl[3]);
            }
        }

        #pragma unroll
        for (int j = 0; j < 8; j++) {
            int col = j*8 + 2*lq;
            int r0 = w*16 + (l >> 2), r1 = r0 + 8;
            size_t a0, a1;
            if (branch == 0) {
                a0 = (((size_t)(b*256 + mn))*256 + r0)*64 + col;
                a1 = (((size_t)(b*256 + mn))*256 + r1)*64 + col;
            } else {
                a0 = (((size_t)(b*256 + r0))*256 + mn)*64 + col;
                a1 = (((size_t)(b*256 + r1))*256 + mn)*64 + col;
            }
            *(float2*)(outb + a0) = make_float2(c[j][0], c[j][1]);
            *(float2*)(outb + a1) = make_float2(c[j][2], c[j][3]);
        }
    }
}

// ---------------- K4: MLP (A split fp16, W single fp16) ----------------
#define SA_HI   0
#define SA_LO   36864
#define SW_BASE 73728
#define S_B1    144384
#define S_B2    145408
#define S_GAM   145664
#define S_BET   145920
#define SM_MLP  146176

__global__ void __launch_bounds__(512) k_mlp_mma(const float* __restrict__ b1,
                                                 const float* __restrict__ b2,
                                                 const float* __restrict__ gamma,
                                                 const float* __restrict__ beta,
                                                 float* __restrict__ out) {
    extern __shared__ __align__(16) unsigned char sm[];
    int t = threadIdx.x;
    int w = t >> 5, l = t & 31;
    int lq = l & 3;
    size_t tile = blockIdx.x;

    {
        const float4* src = (const float4*)g_Wimg;
        float4* dst = (float4*)(sm + SW_BASE);
        for (int i = t; i < W_TOT/16; i += 512) dst[i] = src[i];
    }
    float* b1s = (float*)(sm + S_B1);
    float* b2s = (float*)(sm + S_B2);
    float* gs  = (float*)(sm + S_GAM);
    float* bs  = (float*)(sm + S_BET);
    if (t < 256) b1s[t] = b1[t];
    if (t >= 256 && t < 320) { int q = t - 256; b2s[q] = b2[q]; gs[q] = gamma[q]; bs[q] = beta[q]; }

    {
        int row = t >> 1, qh = (t & 1) * 8;
        const float4* xs  = (const float4*)(g_xsum  + (tile*256 + row)*64);
        const float4* xs2 = (const float4*)(g_xsum2 + (tile*256 + row)*64);
        unsigned char* rh = sm + SA_HI + row*144;
        unsigned char* rl = sm + SA_LO + row*144;
        #pragma unroll
        for (int q = 0; q < 8; q++) {
            float4 v = xs[qh + q], v2 = xs2[qh + q];
            v.x += v2.x; v.y += v2.y; v.z += v2.z; v.w += v2.w;
            uint32_t h0, l0, h1, l1;
            cvt_pair_h(v.x, v.y, h0, l0);
            cvt_pair_h(v.z, v.w, h1, l1);
            *(uint32_t*)(rh + (qh+q)*8    ) = h0;
            *(uint32_t*)(rh + (qh+q)*8 + 4) = h1;
            *(uint32_t*)(rl + (qh+q)*8    ) = l0;
            *(uint32_t*)(rl + (qh+q)*8 + 4) = l1;
        }
    }
    __syncthreads();

    uint32_t smb = smem_u32(sm);
    uint32_t aAddr  = smb + SA_HI + (uint32_t)(w*16 + (l & 15))*144 + (uint32_t)((l >> 4)*16);
    uint32_t w1Base = smb + SW_BASE + W_W1
                    + (uint32_t)(((l >> 4)*8) + (l & 7))*144 + (uint32_t)(((l >> 3) & 1)*16);
    uint32_t w2Base = smb + SW_BASE + W_W2
                    + (uint32_t)(((l >> 4)*8) + (l & 7))*528 + (uint32_t)(((l >> 3) & 1)*16);

    float d2[8][4];
    #pragma unroll
    for (int j = 0; j < 8; j++)
        #pragma unroll
        for (int q = 0; q < 4; q++) d2[j][q] = 0.f;

    for (int c = 0; c < 4; c++) {
        float h[8][4];
        #pragma unroll
        for (int j = 0; j < 8; j++)
            #pragma unroll
            for (int q = 0; q < 4; q++) h[j][q] = 0.f;

        #pragma unroll
        for (int kt = 0; kt < 4; kt++) {
            uint32_t ah[4], al[4];
            ldsm4(ah, aAddr + kt*32);
            ldsm4(al, aAddr + (SA_LO - SA_HI) + kt*32);
            #pragma unroll
            for (int u = 0; u < 4; u++) {
                uint32_t bh[4];
                ldsm4(bh, w1Base + (uint32_t)(c*64 + u*16)*144 + kt*32);
                mma_f16(h[2*u  ], ah, bh[0], bh[1]);
                mma_f16(h[2*u  ], al, bh[0], bh[1]);
                mma_f16(h[2*u+1], ah, bh[2], bh[3]);
                mma_f16(h[2*u+1], al, bh[2], bh[3]);
            }
        }

        #pragma unroll
        for (int kt2 = 0; kt2 < 4; kt2++) {
            int j = 2*kt2;
            uint32_t ah2[4], al2[4];
            {
                int g0 = c*64 + j*8 + 2*lq;
                float bA = b1s[g0],   bB = b1s[g0+1];
                float bC = b1s[g0+8], bD = b1s[g0+9];
                float v0 = fmaxf(h[j][0] + bA, 0.f);
                float v1 = fmaxf(h[j][1] + bB, 0.f);
                cvt_pair_h(v0, v1, ah2[0], al2[0]);
                v0 = fmaxf(h[j][2] + bA, 0.f);
                v1 = fmaxf(h[j][3] + bB, 0.f);
                cvt_pair_h(v0, v1, ah2[1], al2[1]);
                v0 = fmaxf(h[j+1][0] + bC, 0.f);
                v1 = fmaxf(h[j+1][1] + bD, 0.f);
                cvt_pair_h(v0, v1, ah2[2], al2[2]);
                v0 = fmaxf(h[j+1][2] + bC, 0.f);
                v1 = fmaxf(h[j+1][3] + bD, 0.f);
                cvt_pair_h(v0, v1, ah2[3], al2[3]);
            }
            uint32_t kByte = (uint32_t)(c*128 + kt2*32);
            #pragma unroll
            for (int u = 0; u < 4; u++) {
                uint32_t bh[4];
                ldsm4(bh, w2Base + (uint32_t)(u*16)*528 + kByte);
                mma_f16(d2[2*u  ], ah2, bh[0], bh[1]);
                mma_f16(d2[2*u  ], al2, bh[0], bh[1]);
                mma_f16(d2[2*u+1], ah2, bh[2], bh[3]);
                mma_f16(d2[2*u+1], al2, bh[2], bh[3]);
            }
        }
    }

    #pragma unroll
    for (int rh = 0; rh < 2; rh++) {
        float vals[16];
        #pragma unroll
        for (int j2 = 0; j2 < 8; j2++) {
            int col = j2*8 + 2*lq;
            vals[2*j2  ] = d2[j2][2*rh  ] + b2s[col];
            vals[2*j2+1] = d2[j2][2*rh+1] + b2s[col+1];
        }
        float s = 0.f;
        #pragma unroll
        for (int q = 0; q < 16; q++) s += vals[q];
        s += __shfl_xor_sync(0xffffffffu, s, 1);
        s += __shfl_xor_sync(0xffffffffu, s, 2);
        float mu = s * (1.f/64.f);
        float v = 0.f;
        #pragma unroll
        for (int q = 0; q < 16; q++) { float d = vals[q] - mu; v = fmaf(d, d, v); }
        v += __shfl_xor_sync(0xffffffffu, v, 1);
        v += __shfl_xor_sync(0xffffffffu, v, 2);
        float rinv = rsqrtf(v * (1.f/64.f) + 1e-5f);
        size_t row = tile*256 + w*16 + rh*8 + (l >> 2);
        #pragma unroll
        for (int j2 = 0; j2 < 8; j2++) {
            int col = j2*8 + 2*lq;
            float2 r;
            r.x = (vals[2*j2  ] - mu) * rinv * gs[col  ] + bs[col  ];
            r.y = (vals[2*j2+1] - mu) * rinv * gs[col+1] + bs[col+1];
            *(float2*)(out + row*64 + col) = r;
        }
    }
}

// ---------------- launcher ----------------
extern "C" void kernel_launch(void* const* d_in, const int* in_sizes, int n_in,
                              void* d_out, int out_size) {
    (void)in_sizes; (void)n_in; (void)out_size;
    const float* x     = (const float*)d_in[0];
    const float* att   = (const float*)d_in[1];
    const float* fwy   = (const float*)d_in[2];
    const float* fwx   = (const float*)d_in[3];
    const float* w1    = (const float*)d_in[4];
    const float* b1    = (const float*)d_in[5];
    const float* w2    = (const float*)d_in[6];
    const float* b2    = (const float*)d_in[7];
    const float* gamma = (const float*)d_in[8];
    const float* beta  = (const float*)d_in[9];
    float* out = (float*)d_out;

    cudaFuncSetAttribute(k_fwd_mma, cudaFuncAttributeMaxDynamicSharedMemorySize, FW_TOT);
    cudaFuncSetAttribute(k_mix_mma, cudaFuncAttributeMaxDynamicSharedMemorySize, MX_TOT);
    cudaFuncSetAttribute(k_inv_mma, cudaFuncAttributeMaxDynamicSharedMemorySize, IV_TOT);
    cudaFuncSetAttribute(k_mlp_mma, cudaFuncAttributeMaxDynamicSharedMemorySize, SM_MLP);

    k_weights<<<(BATCH*MODES*CI*CO)/256, 256>>>(att, fwy, fwx);
    k_wprep<<<128, 256>>>(w1, w2);
    k_tprep<<<256, 256>>>();
    k_fwd_mma<<<512, 512, FW_TOT>>>(x);
    k_mix_mma<<<2*BATCH*MODES, 512, MX_TOT>>>();
    k_inv_mma<<<512, 512, IV_TOT>>>();
    k_mlp_mma<<<(BATCH*MM*NN)/256, 512, SM_MLP>>>(b1, b2, gamma, beta, out);
}

// round 14
// speedup vs baseline: 2.0119x; 1.0551x over previous
#include <cuda_runtime.h>
#include <cuda_fp16.h>
#include <cstdint>

#define BATCH 8
#define MM 256
#define NN 256
#define CI 64
#define CO 64
#define KK 4
#define MODES 32

// ---------------- scratch ----------------
__device__ float2 g_wy [BATCH*MODES*CI*CO];
__device__ float2 g_wx [BATCH*MODES*CI*CO];
__device__ float2 g_XfY[BATCH*MODES*MM*CI];
__device__ float2 g_XfX[BATCH*MODES*NN*CI];
__device__ float2 g_YfY[BATCH*MODES*MM*CO];
__device__ float2 g_YfX[BATCH*MODES*NN*CO];
__device__ float  g_xsum2[(size_t)BATCH*MM*NN*CO];

// MLP weight image (single fp16): W1 [256n][64k] stride 144; W2 [64n][256k] stride 528
#define W_W1   0
#define W_W2   36864
#define W_TOT  70656
__device__ __align__(16) unsigned char g_Wimg[W_TOT];

// transform tables (single fp16)
#define T_ST   528
#define T_TOT  33792
__device__ __align__(16) unsigned char g_TY[T_TOT];
__device__ __align__(16) unsigned char g_TX[T_TOT];
#define S_ST   144
#define S_TOT  36864
__device__ __align__(16) unsigned char g_SY[S_TOT];
__device__ __align__(16) unsigned char g_SX[S_TOT];

// ---------------- helpers ----------------
__device__ __forceinline__ uint32_t smem_u32(const void* p) {
    uint32_t a;
    asm("{ .reg .u64 t; cvta.to.shared.u64 t, %1; cvt.u32.u64 %0, t; }" : "=r"(a) : "l"(p));
    return a;
}
__device__ __forceinline__ void ldsm4(uint32_t* r, uint32_t a) {
    asm volatile("ldmatrix.sync.aligned.m8n8.x4.shared.b16 {%0,%1,%2,%3}, [%4];"
        : "=r"(r[0]), "=r"(r[1]), "=r"(r[2]), "=r"(r[3]) : "r"(a));
}
__device__ __forceinline__ void ldsm4t(uint32_t* r, uint32_t a) {
    asm volatile("ldmatrix.sync.aligned.m8n8.x4.trans.shared.b16 {%0,%1,%2,%3}, [%4];"
        : "=r"(r[0]), "=r"(r[1]), "=r"(r[2]), "=r"(r[3]) : "r"(a));
}
__device__ __forceinline__ uint32_t pk_h2(__half a, __half b) {
    __half2 t; t.x = a; t.y = b; return *(uint32_t*)&t;
}
__device__ __forceinline__ void cvt_pair_h(float v0, float v1, uint32_t& hi, uint32_t& lo) {
    __half h0 = __float2half(v0), h1 = __float2half(v1);
    float r0 = v0 - __half2float(h0);
    float r1 = v1 - __half2float(h1);
    hi = pk_h2(h0, h1);
    lo = pk_h2(__float2half(r0), __float2half(r1));
}
__device__ __forceinline__ void mma_f16(float* d, const uint32_t* a, uint32_t b0, uint32_t b1) {
    asm volatile(
        "mma.sync.aligned.m16n8k16.row.col.f32.f16.f16.f32 "
        "{%0,%1,%2,%3},{%4,%5,%6,%7},{%8,%9},{%0,%1,%2,%3};"
        : "+f"(d[0]), "+f"(d[1]), "+f"(d[2]), "+f"(d[3])
        : "r"(a[0]), "r"(a[1]), "r"(a[2]), "r"(a[3]), "r"(b0), "r"(b1));
}
__device__ __forceinline__ void wr_h(unsigned char* p, float v) {
    *(__half*)p = __float2half(v);
}

// ---------------- K0: spectral weights ----------------
__global__ void k_weights(const float* __restrict__ att,
                          const float* __restrict__ fwy,
                          const float* __restrict__ fwx) {
    int gid = blockIdx.x * 256 + threadIdx.x;
    int o = gid & 63, i = (gid >> 6) & 63, f = (gid >> 12) & 31, b = gid >> 17;
    float a0 = att[b*KK+0], a1 = att[b*KK+1], a2 = att[b*KK+2], a3 = att[b*KK+3];
    const int ks = CI*CO*MODES*2;
    int base = ((i*CO + o)*MODES + f)*2;
    float yr, yi, xr, xi;
    yr = a0*fwy[base   ] + a1*fwy[base+ks   ] + a2*fwy[base+2*ks  ] + a3*fwy[base+3*ks  ];
    yi = a0*fwy[base+1 ] + a1*fwy[base+ks+1 ] + a2*fwy[base+2*ks+1] + a3*fwy[base+3*ks+1];
    xr = a0*fwx[base   ] + a1*fwx[base+ks   ] + a2*fwx[base+2*ks  ] + a3*fwx[base+3*ks  ];
    xi = a0*fwx[base+1 ] + a1*fwx[base+ks+1 ] + a2*fwx[base+2*ks+1] + a3*fwx[base+3*ks+1];
    g_wy[gid] = make_float2(yr, yi);
    g_wx[gid] = make_float2(xr, xi);
}

// ---------------- K0b: MLP weight image ----------------
__global__ void k_wprep(const float* __restrict__ w1, const float* __restrict__ w2) {
    int gid = blockIdx.x * 256 + threadIdx.x;
    if (gid < 16384) {
        int i = gid >> 8, j = gid & 255;
        wr_h(g_Wimg + W_W1 + (uint32_t)j*144 + (uint32_t)i*2, w1[gid]);
    } else {
        int idx = gid - 16384;
        int j = idx >> 6, o = idx & 63;
        wr_h(g_Wimg + W_W2 + (uint32_t)o*528 + (uint32_t)j*2, w2[idx]);
    }
}

// ---------------- K0c: transform tables ----------------
__global__ void k_tprep() {
    int gid = blockIdx.x * 256 + threadIdx.x;
    int sel = gid >> 14;
    int idx = gid & 16383;
    const float inv = 0.04428074428f;
    if (sel == 0) {
        int r = idx >> 8, k = idx & 255;
        int f = r >> 1;
        float ang = (float)((f*k) & 255) * (1.0f/128.0f);
        float v = (r & 1) ? -0.0625f*sinpif(ang) : 0.0625f*cospif(ang);
        wr_h(g_TY + (uint32_t)r*T_ST + (uint32_t)k*2, v);
    } else if (sel == 1) {
        int r = idx >> 8, k = idx & 255;
        int f = r >> 1;
        float v;
        if (r & 1) v = -2.0f*inv*sinpif((float)((f*k) % 510) * (1.0f/255.0f));
        else       v = (k == 0) ? inv : ((k == 255) ? ((f & 1) ? -inv : inv) : 0.0f);
        wr_h(g_TX + (uint32_t)r*T_ST + (uint32_t)k*2, v);
    } else if (sel == 2) {
        int r = idx >> 6, k = idx & 63;
        int f = k >> 1;
        float ang = (float)((f*r) & 255) * (1.0f/128.0f);
        float v = (k & 1) ? -0.125f*sinpif(ang)
                          : ((f == 0) ? 0.0625f : 0.125f)*cospif(ang);
        wr_h(g_SY + (uint32_t)r*S_ST + (uint32_t)k*2, v);
    } else {
        int r = idx >> 6, k = idx & 63;
        int f = k >> 1;
        float ang = (float)((f*r) % 510) * (1.0f/255.0f);
        float v = (k & 1) ? -2.0f*inv*sinpif(ang)
                          : ((f == 0) ? inv : 2.0f*inv)*cospif(ang);
        wr_h(g_SX + (uint32_t)r*S_ST + (uint32_t)k*2, v);
    }
}

// ---------------- K1: forward transforms (unchanged R13) ----------------
#define FW_B    33792
#define FB_LOB  36864
#define FW_TOT  107520
__global__ void __launch_bounds__(512) k_fwd_mma(const float* __restrict__ x) {
    extern __shared__ __align__(16) unsigned char sm[];
    int t = threadIdx.x, w = t >> 5, l = t & 31, lq = l & 3;
    int z = blockIdx.x;
    int branch = z >> 8;
    int grp = z & 255;
    int b = grp >> 5, g = grp & 31;

    {
        const float4* src = (const float4*)(branch ? g_TX : g_TY);
        float4* dst = (float4*)sm;
        for (int i = t; i < T_TOT/16; i += 512) dst[i] = src[i];
    }

    int mt = w & 3, nh = w >> 2;
    uint32_t smb = smem_u32(sm);
    uint32_t aAddr = smb + (uint32_t)(mt*16 + (l & 15))*T_ST + (uint32_t)((l >> 4)*16);
    uint32_t bAddr = smb + FW_B
                   + (uint32_t)((l & 7) + ((l >> 3) & 1)*8)*144
                   + (uint32_t)(nh*32) + (uint32_t)((l >> 4)*16);
    float* outb = (float*)(branch ? g_XfX : g_XfY);

    float4 v[8];
    {
        int mn0 = g*8;
        #pragma unroll
        for (int it = 0; it < 8; it++) {
            int flat = it*512 + t;
            int c4 = flat & 15, k = flat >> 4;
            const float* p0;
            if (branch == 0) p0 = x + ((size_t)(b*256 + mn0))*16384 + (size_t)k*64 + c4*4;
            else             p0 = x + (((size_t)(b*256 + k))*256 + mn0)*64 + c4*4;
            v[it] = *(const float4*)p0;
        }
    }

    for (int it8 = 0; it8 < 8; it8++) {
        int mn = g*8 + it8;
        __syncthreads();
        #pragma unroll
        for (int it = 0; it < 8; it++) {
            int flat = it*512 + t;
            int c4 = flat & 15, k = flat >> 4;
            uint32_t h0, l0, h1, l1;
            cvt_pair_h(v[it].x, v[it].y, h0, l0);
            cvt_pair_h(v[it].z, v[it].w, h1, l1);
            *(uint2*)(sm + FW_B + k*144 + c4*8)          = make_uint2(h0, h1);
            *(uint2*)(sm + FW_B + FB_LOB + k*144 + c4*8) = make_uint2(l0, l1);
        }
        __syncthreads();

        if (it8 < 7) {
            int mn1 = mn + 1;
            #pragma unroll
            for (int it = 0; it < 8; it++) {
                int flat = it*512 + t;
                int c4 = flat & 15, k = flat >> 4;
                const float* p0;
                if (branch == 0) p0 = x + ((size_t)(b*256 + mn1))*16384 + (size_t)k*64 + c4*4;
                else             p0 = x + (((size_t)(b*256 + k))*256 + mn1)*64 + c4*4;
                v[it] = *(const float4*)p0;
            }
        }

        float c[2][4];
        #pragma unroll
        for (int j = 0; j < 2; j++)
            #pragma unroll
            for (int q = 0; q < 4; q++) c[j][q] = 0.f;

        #pragma unroll
        for (int kk = 0; kk < 16; kk++) {
            uint32_t ah[4], bh[4], bl[4];
            ldsm4(ah, aAddr + kk*32);
            ldsm4t(bh, bAddr + kk*2304);
            ldsm4t(bl, bAddr + FB_LOB + kk*2304);
            mma_f16(c[0], ah, bh[0], bh[1]);
            mma_f16(c[0], ah, bl[0], bl[1]);
            mma_f16(c[1], ah, bh[2], bh[3]);
            mma_f16(c[1], ah, bl[2], bl[3]);
        }

        #pragma unroll
        for (int j = 0; j < 2; j++) {
            int ch = nh*16 + j*8 + 2*lq;
            int r0 = mt*16 + (l >> 2), r1 = r0 + 8;
            size_t base0 = ((size_t)(b*32 + (r0 >> 1))*256 + mn)*128 + ch*2 + (r0 & 1);
            size_t base1 = ((size_t)(b*32 + (r1 >> 1))*256 + mn)*128 + ch*2 + (r1 & 1);
            outb[base0]     = c[j][0];
            outb[base0 + 2] = c[j][1];
            outb[base1]     = c[j][2];
            outb[base1 + 2] = c[j][3];
        }
    }
}

// ---------------- K2: complex GEMM (unchanged R13) ----------------
#define MX_AHI 0
#define MX_ALO 69632
#define MX_W   139264
#define MX_TOT 174080

__global__ void __launch_bounds__(512) k_mix_mma() {
    extern __shared__ __align__(16) unsigned char sm[];
    int t = threadIdx.x, w = t >> 5, l = t & 31, lq = l & 3;
    int z = blockIdx.x, branch = z >> 8, bf = z & 255;
    const float2* A = (branch ? g_XfX : g_XfY) + (size_t)bf*MM*CI;
    const float2* W = (branch ? g_wx  : g_wy ) + (size_t)bf*CI*CO;
    float2*       C = (branch ? g_YfX : g_YfY) + (size_t)bf*MM*CO;

    {
        const float4* Af = (const float4*)A;
        #pragma unroll
        for (int it = 0; it < 16; it++) {
            int ft = it*512 + t;
            int row = ft >> 5, c4 = ft & 31;
            float4 v = Af[ft];
            uint32_t h01, l01, h23, l23;
            cvt_pair_h(v.x, v.y, h01, l01);
            cvt_pair_h(v.z, v.w, h23, l23);
            *(uint2*)(sm + MX_AHI + row*272 + c4*8) = make_uint2(h01, h23);
            *(uint2*)(sm + MX_ALO + row*272 + c4*8) = make_uint2(l01, l23);
        }
    }
    {
        #pragma unroll
        for (int it = 0; it < 8; it++) {
            int flat = it*512 + t;
            int i = flat >> 6, o = flat & 63;
            float2 wv = W[flat];
            uint32_t ha = pk_h2(__float2half(wv.x), __float2half(-wv.y));
            uint32_t hb = pk_h2(__float2half(wv.y), __float2half(wv.x));
            *(uint32_t*)(sm + MX_W + (2*o  )*272 + i*4) = ha;
            *(uint32_t*)(sm + MX_W + (2*o+1)*272 + i*4) = hb;
        }
    }
    __syncthreads();

    uint32_t smb = smem_u32(sm);
    int m0 = w*16;
    uint32_t aAddr = smb + MX_AHI + (uint32_t)(m0 + (l & 15))*272 + (uint32_t)((l >> 4)*16);
    uint32_t bBase = smb + MX_W + (uint32_t)(((l >> 4)*8) + (l & 7))*272
                   + (uint32_t)(((l >> 3) & 1)*16);

    float acc[16][4];
    #pragma unroll
    for (int j2 = 0; j2 < 16; j2++)
        #pragma unroll
        for (int q = 0; q < 4; q++) acc[j2][q] = 0.f;

    #pragma unroll
    for (int kt = 0; kt < 8; kt++) {
        uint32_t ah[4], al[4];
        ldsm4(ah, aAddr + kt*32);
        ldsm4(al, aAddr + (MX_ALO - MX_AHI) + kt*32);
        #pragma unroll
        for (int u = 0; u < 8; u++) {
            uint32_t bh[4];
            ldsm4(bh, bBase + (uint32_t)(u*16)*272 + kt*32);
            mma_f16(acc[2*u  ], ah, bh[0], bh[1]);
            mma_f16(acc[2*u  ], al, bh[0], bh[1]);
            mma_f16(acc[2*u+1], ah, bh[2], bh[3]);
            mma_f16(acc[2*u+1], al, bh[2], bh[3]);
        }
    }

    float* Cf = (float*)C;
    #pragma unroll
    for (int j2 = 0; j2 < 16; j2++) {
        int row = m0 + (l >> 2);
        int col = j2*8 + 2*lq;
        *(float2*)(Cf + (size_t)row*128 + col)     = make_float2(acc[j2][0], acc[j2][1]);
        *(float2*)(Cf + (size_t)(row+8)*128 + col) = make_float2(acc[j2][2], acc[j2][3]);
    }
}

// ---------------- K3: inverse transform, X branch only -> g_xsum2 ----------------
#define IV_B   36864
#define IV_BLO 9216
#define IV_TOT 55296
__global__ void __launch_bounds__(512) k_inv_mma() {
    extern __shared__ __align__(16) unsigned char sm[];
    int t = threadIdx.x, w = t >> 5, l = t & 31, lq = l & 3;
    int z = blockIdx.x;             // 256 = 8 b * 32 groups
    int b = z >> 5, g = z & 31;

    {
        const float4* src = (const float4*)g_SX;
        float4* dst = (float4*)sm;
        for (int i = t; i < S_TOT/16; i += 512) dst[i] = src[i];
    }

    uint32_t smb = smem_u32(sm);
    uint32_t aAddr = smb + (uint32_t)(w*16 + (l & 15))*S_ST + (uint32_t)((l >> 4)*16);
    uint32_t bBase = smb + IV_B
                   + (uint32_t)((l & 7) + ((l >> 3) & 1)*8)*144
                   + (uint32_t)((l >> 4)*16);
    const float2* Y = g_YfX;
    float* outb = g_xsum2;

    float4 y[2];
    {
        int mn0 = g*8;
        #pragma unroll
        for (int it = 0; it < 2; it++) {
            int flat = it*512 + t;
            int f = flat >> 5, cp = flat & 31;
            y[it] = *(const float4*)(Y + ((size_t)(b*32 + f)*256 + mn0)*64 + 2*cp);
        }
    }
    __syncthreads();

    uint32_t ah[4][4];
    #pragma unroll
    for (int kk = 0; kk < 4; kk++) ldsm4(ah[kk], aAddr + kk*32);

    for (int it8 = 0; it8 < 8; it8++) {
        int mn = g*8 + it8;
        if (it8 > 0) __syncthreads();
        #pragma unroll
        for (int it = 0; it < 2; it++) {
            int flat = it*512 + t;
            int f = flat >> 5, cp = flat & 31;
            float4 v = y[it];
            uint32_t rh_, rl_, ih_, il_;
            cvt_pair_h(v.x, v.z, rh_, rl_);
            cvt_pair_h(v.y, v.w, ih_, il_);
            *(uint32_t*)(sm + IV_B + (2*f  )*144 + cp*4)          = rh_;
            *(uint32_t*)(sm + IV_B + (2*f+1)*144 + cp*4)          = ih_;
            *(uint32_t*)(sm + IV_B + IV_BLO + (2*f  )*144 + cp*4) = rl_;
            *(uint32_t*)(sm + IV_B + IV_BLO + (2*f+1)*144 + cp*4) = il_;
        }
        __syncthreads();

        if (it8 < 7) {
            int mn1 = mn + 1;
            #pragma unroll
            for (int it = 0; it < 2; it++) {
                int flat = it*512 + t;
                int f = flat >> 5, cp = flat & 31;
                y[it] = *(const float4*)(Y + ((size_t)(b*32 + f)*256 + mn1)*64 + 2*cp);
            }
        }

        float c[8][4];
        #pragma unroll
        for (int j = 0; j < 8; j++)
            #pragma unroll
            for (int q = 0; q < 4; q++) c[j][q] = 0.f;

        #pragma unroll
        for (int kk = 0; kk < 4; kk++) {
            #pragma unroll
            for (int u = 0; u < 4; u++) {
                uint32_t bh[4], bl[4];
                uint32_t ba = bBase + (uint32_t)(u*32) + (uint32_t)(kk*16)*144;
                ldsm4t(bh, ba);
                ldsm4t(bl, ba + IV_BLO);
                mma_f16(c[2*u  ], ah[kk], bh[0], bh[1]);
                mma_f16(c[2*u  ], ah[kk], bl[0], bl[1]);
                mma_f16(c[2*u+1], ah[kk], bh[2], bh[3]);
                mma_f16(c[2*u+1], ah[kk], bl[2], bl[3]);
            }
        }

        #pragma unroll
        for (int j = 0; j < 8; j++) {
            int col = j*8 + 2*lq;
            int r0 = w*16 + (l >> 2), r1 = r0 + 8;
            size_t a0 = (((size_t)(b*256 + r0))*256 + mn)*64 + col;
            size_t a1 = (((size_t)(b*256 + r1))*256 + mn)*64 + col;
            *(float2*)(outb + a0) = make_float2(c[j][0], c[j][1]);
            *(float2*)(outb + a1) = make_float2(c[j][2], c[j][3]);
        }
    }
}

// ---------------- K4: fused inv-Y + MLP + LayerNorm ----------------
#define FM_SA_HI 0
#define FM_SA_LO 36864
#define FM_W     73728
#define FM_S     144384
#define FM_B     181248
#define FM_BLO   9216
#define FM_B1    199680
#define FM_B2    200704
#define FM_GAM   200960
#define FM_BET   201216
#define FM_TOT   201472

__global__ void __launch_bounds__(512) k_mlp_fused(const float* __restrict__ b1,
                                                   const float* __restrict__ b2,
                                                   const float* __restrict__ gamma,
                                                   const float* __restrict__ beta,
                                                   float* __restrict__ out) {
    extern __shared__ __align__(16) unsigned char sm[];
    int t = threadIdx.x;
    int w = t >> 5, l = t & 31;
    int lq = l & 3;
    int blk = blockIdx.x;          // 512 blocks * 4 tiles

    {
        const float4* src = (const float4*)g_Wimg;
        float4* dst = (float4*)(sm + FM_W);
        for (int i = t; i < W_TOT/16; i += 512) dst[i] = src[i];
        const float4* src2 = (const float4*)g_SY;
        float4* dst2 = (float4*)(sm + FM_S);
        for (int i = t; i < S_TOT/16; i += 512) dst2[i] = src2[i];
    }
    float* b1s = (float*)(sm + FM_B1);
    float* b2s = (float*)(sm + FM_B2);
    float* gs  = (float*)(sm + FM_GAM);
    float* bs  = (float*)(sm + FM_BET);
    if (t < 256) b1s[t] = b1[t];
    if (t >= 256 && t < 320) { int q = t - 256; b2s[q] = b2[q]; gs[q] = gamma[q]; bs[q] = beta[q]; }

    uint32_t smb = smem_u32(sm);
    // inv part
    uint32_t sAAddr = smb + FM_S + (uint32_t)(w*16 + (l & 15))*S_ST + (uint32_t)((l >> 4)*16);
    uint32_t sBBase = smb + FM_B
                    + (uint32_t)((l & 7) + ((l >> 3) & 1)*8)*144
                    + (uint32_t)((l >> 4)*16);
    // mlp part
    uint32_t aAddr  = smb + FM_SA_HI + (uint32_t)(w*16 + (l & 15))*144 + (uint32_t)((l >> 4)*16);
    uint32_t w1Base = smb + FM_W + W_W1
                    + (uint32_t)(((l >> 4)*8) + (l & 7))*144 + (uint32_t)(((l >> 3) & 1)*16);
    uint32_t w2Base = smb + FM_W + W_W2
                    + (uint32_t)(((l >> 4)*8) + (l & 7))*528 + (uint32_t)(((l >> 3) & 1)*16);

    // prefetch first tile's Y slice
    float4 y[2];
    {
        int tile0 = blk*4;
        int b = tile0 >> 8, m = tile0 & 255;
        #pragma unroll
        for (int it = 0; it < 2; it++) {
            int flat = it*512 + t;
            int f = flat >> 5, cp = flat & 31;
            y[it] = *(const float4*)(g_YfY + ((size_t)(b*32 + f)*256 + m)*64 + 2*cp);
        }
    }
    __syncthreads();               // tables + biases visible

    for (int tt4 = 0; tt4 < 4; tt4++) {
        int tile = blk*4 + tt4;
        if (tt4 > 0) __syncthreads();   // prev MLP done reading SA; prev inv done reading B

        // stage Y slice (natural [k=2f+p][ch], split planes)
        #pragma unroll
        for (int it = 0; it < 2; it++) {
            int flat = it*512 + t;
            int f = flat >> 5, cp = flat & 31;
            float4 v = y[it];
            uint32_t rh_, rl_, ih_, il_;
            cvt_pair_h(v.x, v.z, rh_, rl_);
            cvt_pair_h(v.y, v.w, ih_, il_);
            *(uint32_t*)(sm + FM_B + (2*f  )*144 + cp*4)          = rh_;
            *(uint32_t*)(sm + FM_B + (2*f+1)*144 + cp*4)          = ih_;
            *(uint32_t*)(sm + FM_B + FM_BLO + (2*f  )*144 + cp*4) = rl_;
            *(uint32_t*)(sm + FM_B + FM_BLO + (2*f+1)*144 + cp*4) = il_;
        }
        __syncthreads();

        // prefetch next tile's Y (hidden under inv+mlp MMA)
        if (tt4 < 3) {
            int tileN = tile + 1;
            int bN = tileN >> 8, mN = tileN & 255;
            #pragma unroll
            for (int it = 0; it < 2; it++) {
                int flat = it*512 + t;
                int f = flat >> 5, cp = flat & 31;
                y[it] = *(const float4*)(g_YfY + ((size_t)(bN*32 + f)*256 + mN)*64 + 2*cp);
            }
        }

        // ---- inverse-Y synthesis MMA ----
        float ci[8][4];
        #pragma unroll
        for (int j = 0; j < 8; j++)
            #pragma unroll
            for (int q = 0; q < 4; q++) ci[j][q] = 0.f;

        #pragma unroll
        for (int kk = 0; kk < 4; kk++) {
            uint32_t ah[4];
            ldsm4(ah, sAAddr + kk*32);
            #pragma unroll
            for (int u = 0; u < 4; u++) {
                uint32_t bh[4], bl[4];
                uint32_t ba = sBBase + (uint32_t)(u*32) + (uint32_t)(kk*16)*144;
                ldsm4t(bh, ba);
                ldsm4t(bl, ba + FM_BLO);
                mma_f16(ci[2*u  ], ah, bh[0], bh[1]);
                mma_f16(ci[2*u  ], ah, bl[0], bl[1]);
                mma_f16(ci[2*u+1], ah, bh[2], bh[3]);
                mma_f16(ci[2*u+1], ah, bl[2], bl[3]);
            }
        }

        // ---- add xsum2(X branch) and store into SA planes ----
        {
            size_t base = (size_t)tile * 256;
            int r0 = w*16 + (l >> 2), r1 = r0 + 8;
            #pragma unroll
            for (int j = 0; j < 8; j++) {
                int col = j*8 + 2*lq;
                float2 v0 = *(const float2*)(g_xsum2 + (base + r0)*64 + col);
                float2 v1 = *(const float2*)(g_xsum2 + (base + r1)*64 + col);
                v0.x += ci[j][0]; v0.y += ci[j][1];
                v1.x += ci[j][2]; v1.y += ci[j][3];
                uint32_t h0, l0, h1, l1;
                cvt_pair_h(v0.x, v0.y, h0, l0);
                cvt_pair_h(v1.x, v1.y, h1, l1);
                *(uint32_t*)(sm + FM_SA_HI + r0*144 + col*2) = h0;
                *(uint32_t*)(sm + FM_SA_LO + r0*144 + col*2) = l0;
                *(uint32_t*)(sm + FM_SA_HI + r1*144 + col*2) = h1;
                *(uint32_t*)(sm + FM_SA_LO + r1*144 + col*2) = l1;
            }
        }
        __syncthreads();

        // ---- MLP (A split fp16, W single fp16) ----
        float d2[8][4];
        #pragma unroll
        for (int j = 0; j < 8; j++)
            #pragma unroll
            for (int q = 0; q < 4; q++) d2[j][q] = 0.f;

        for (int cc = 0; cc < 4; cc++) {
            float h[8][4];
            #pragma unroll
            for (int j = 0; j < 8; j++)
                #pragma unroll
                for (int q = 0; q < 4; q++) h[j][q] = 0.f;

            #pragma unroll
            for (int kt = 0; kt < 4; kt++) {
                uint32_t ah[4], al[4];
                ldsm4(ah, aAddr + kt*32);
                ldsm4(al, aAddr + (FM_SA_LO - FM_SA_HI) + kt*32);
                #pragma unroll
                for (int u = 0; u < 4; u++) {
                    uint32_t bh[4];
                    ldsm4(bh, w1Base + (uint32_t)(cc*64 + u*16)*144 + kt*32);
                    mma_f16(h[2*u  ], ah, bh[0], bh[1]);
                    mma_f16(h[2*u  ], al, bh[0], bh[1]);
                    mma_f16(h[2*u+1], ah, bh[2], bh[3]);
                    mma_f16(h[2*u+1], al, bh[2], bh[3]);
                }
            }

            #pragma unroll
            for (int kt2 = 0; kt2 < 4; kt2++) {
                int j = 2*kt2;
                uint32_t ah2[4], al2[4];
                {
                    int g0 = cc*64 + j*8 + 2*lq;
                    float bA = b1s[g0],   bB = b1s[g0+1];
                    float bC = b1s[g0+8], bD = b1s[g0+9];
                    float v0 = fmaxf(h[j][0] + bA, 0.f);
                    float v1 = fmaxf(h[j][1] + bB, 0.f);
                    cvt_pair_h(v0, v1, ah2[0], al2[0]);
                    v0 = fmaxf(h[j][2] + bA, 0.f);
                    v1 = fmaxf(h[j][3] + bB, 0.f);
                    cvt_pair_h(v0, v1, ah2[1], al2[1]);
                    v0 = fmaxf(h[j+1][0] + bC, 0.f);
                    v1 = fmaxf(h[j+1][1] + bD, 0.f);
                    cvt_pair_h(v0, v1, ah2[2], al2[2]);
                    v0 = fmaxf(h[j+1][2] + bC, 0.f);
                    v1 = fmaxf(h[j+1][3] + bD, 0.f);
                    cvt_pair_h(v0, v1, ah2[3], al2[3]);
                }
                uint32_t kByte = (uint32_t)(cc*128 + kt2*32);
                #pragma unroll
                for (int u = 0; u < 4; u++) {
                    uint32_t bh[4];
                    ldsm4(bh, w2Base + (uint32_t)(u*16)*528 + kByte);
                    mma_f16(d2[2*u  ], ah2, bh[0], bh[1]);
                    mma_f16(d2[2*u  ], al2, bh[0], bh[1]);
                    mma_f16(d2[2*u+1], ah2, bh[2], bh[3]);
                    mma_f16(d2[2*u+1], al2, bh[2], bh[3]);
                }
            }
        }

        // ---- +b2, LayerNorm, write out ----
        #pragma unroll
        for (int rh = 0; rh < 2; rh++) {
            float vals[16];
            #pragma unroll
            for (int j2 = 0; j2 < 8; j2++) {
                int col = j2*8 + 2*lq;
                vals[2*j2  ] = d2[j2][2*rh  ] + b2s[col];
                vals[2*j2+1] = d2[j2][2*rh+1] + b2s[col+1];
            }
            float s = 0.f;
            #pragma unroll
            for (int q = 0; q < 16; q++) s += vals[q];
            s += __shfl_xor_sync(0xffffffffu, s, 1);
            s += __shfl_xor_sync(0xffffffffu, s, 2);
            float mu = s * (1.f/64.f);
            float v = 0.f;
            #pragma unroll
            for (int q = 0; q < 16; q++) { float d = vals[q] - mu; v = fmaf(d, d, v); }
            v += __shfl_xor_sync(0xffffffffu, v, 1);
            v += __shfl_xor_sync(0xffffffffu, v, 2);
            float rinv = rsqrtf(v * (1.f/64.f) + 1e-5f);
            size_t row = (size_t)tile*256 + w*16 + rh*8 + (l >> 2);
            #pragma unroll
            for (int j2 = 0; j2 < 8; j2++) {
                int col = j2*8 + 2*lq;
                float2 r;
                r.x = (vals[2*j2  ] - mu) * rinv * gs[col  ] + bs[col  ];
                r.y = (vals[2*j2+1] - mu) * rinv * gs[col+1] + bs[col+1];
                *(float2*)(out + row*64 + col) = r;
            }
        }
    }
}

// ---------------- launcher ----------------
extern "C" void kernel_launch(void* const* d_in, const int* in_sizes, int n_in,
                              void* d_out, int out_size) {
    (void)in_sizes; (void)n_in; (void)out_size;
    const float* x     = (const float*)d_in[0];
    const float* att   = (const float*)d_in[1];
    const float* fwy   = (const float*)d_in[2];
    const float* fwx   = (const float*)d_in[3];
    const float* w1    = (const float*)d_in[4];
    const float* b1    = (const float*)d_in[5];
    const float* w2    = (const float*)d_in[6];
    const float* b2    = (const float*)d_in[7];
    const float* gamma = (const float*)d_in[8];
    const float* beta  = (const float*)d_in[9];
    float* out = (float*)d_out;

    cudaFuncSetAttribute(k_fwd_mma,  cudaFuncAttributeMaxDynamicSharedMemorySize, FW_TOT);
    cudaFuncSetAttribute(k_mix_mma,  cudaFuncAttributeMaxDynamicSharedMemorySize, MX_TOT);
    cudaFuncSetAttribute(k_inv_mma,  cudaFuncAttributeMaxDynamicSharedMemorySize, IV_TOT);
    cudaFuncSetAttribute(k_mlp_fused,cudaFuncAttributeMaxDynamicSharedMemorySize, FM_TOT);

    k_weights<<<(BATCH*MODES*CI*CO)/256, 256>>>(att, fwy, fwx);
    k_wprep<<<128, 256>>>(w1, w2);
    k_tprep<<<256, 256>>>();
    k_fwd_mma<<<512, 512, FW_TOT>>>(x);
    k_mix_mma<<<2*BATCH*MODES, 512, MX_TOT>>>();
    k_inv_mma<<<256, 512, IV_TOT>>>();
    k_mlp_fused<<<512, 512, FM_TOT>>>(b1, b2, gamma, beta, out);
}

// round 15
// speedup vs baseline: 2.1708x; 1.0790x over previous
#include <cuda_runtime.h>
#include <cuda_fp16.h>
#include <cstdint>

#define BATCH 8
#define MM 256
#define NN 256
#define CI 64
#define CO 64
#define KK 4
#define MODES 32

// ---------------- scratch ----------------
__device__ float2 g_wy [BATCH*MODES*CI*CO];
__device__ float2 g_wx [BATCH*MODES*CI*CO];
__device__ float2 g_XfY[BATCH*MODES*MM*CI];
__device__ float2 g_XfX[BATCH*MODES*NN*CI];
__device__ float2 g_YfY[BATCH*MODES*MM*CO];
__device__ float2 g_YfX[BATCH*MODES*NN*CO];
__device__ float  g_xsum2[(size_t)BATCH*MM*NN*CO];

// MLP weight image (single fp16)
#define W_W1   0
#define W_W2   36864
#define W_TOT  70656
__device__ __align__(16) unsigned char g_Wimg[W_TOT];

// transform tables (single fp16)
#define T_ST   528
#define T_TOT  33792
__device__ __align__(16) unsigned char g_TY[T_TOT];
__device__ __align__(16) unsigned char g_TX[T_TOT];
#define S_ST   144
#define S_TOT  36864
__device__ __align__(16) unsigned char g_SY[S_TOT];
__device__ __align__(16) unsigned char g_SX[S_TOT];

// ---------------- helpers ----------------
__device__ __forceinline__ uint32_t smem_u32(const void* p) {
    uint32_t a;
    asm("{ .reg .u64 t; cvta.to.shared.u64 t, %1; cvt.u32.u64 %0, t; }" : "=r"(a) : "l"(p));
    return a;
}
__device__ __forceinline__ void ldsm4(uint32_t* r, uint32_t a) {
    asm volatile("ldmatrix.sync.aligned.m8n8.x4.shared.b16 {%0,%1,%2,%3}, [%4];"
        : "=r"(r[0]), "=r"(r[1]), "=r"(r[2]), "=r"(r[3]) : "r"(a));
}
__device__ __forceinline__ void ldsm4t(uint32_t* r, uint32_t a) {
    asm volatile("ldmatrix.sync.aligned.m8n8.x4.trans.shared.b16 {%0,%1,%2,%3}, [%4];"
        : "=r"(r[0]), "=r"(r[1]), "=r"(r[2]), "=r"(r[3]) : "r"(a));
}
__device__ __forceinline__ uint32_t pk_h2(__half a, __half b) {
    __half2 t; t.x = a; t.y = b; return *(uint32_t*)&t;
}
__device__ __forceinline__ uint32_t cvt1_h(float v0, float v1) {
    return pk_h2(__float2half(v0), __float2half(v1));
}
__device__ __forceinline__ void cvt_pair_h(float v0, float v1, uint32_t& hi, uint32_t& lo) {
    __half h0 = __float2half(v0), h1 = __float2half(v1);
    float r0 = v0 - __half2float(h0);
    float r1 = v1 - __half2float(h1);
    hi = pk_h2(h0, h1);
    lo = pk_h2(__float2half(r0), __float2half(r1));
}
__device__ __forceinline__ void mma_f16(float* d, const uint32_t* a, uint32_t b0, uint32_t b1) {
    asm volatile(
        "mma.sync.aligned.m16n8k16.row.col.f32.f16.f16.f32 "
        "{%0,%1,%2,%3},{%4,%5,%6,%7},{%8,%9},{%0,%1,%2,%3};"
        : "+f"(d[0]), "+f"(d[1]), "+f"(d[2]), "+f"(d[3])
        : "r"(a[0]), "r"(a[1]), "r"(a[2]), "r"(a[3]), "r"(b0), "r"(b1));
}
__device__ __forceinline__ void wr_h(unsigned char* p, float v) {
    *(__half*)p = __float2half(v);
}

// ---------------- K0: spectral weights ----------------
__global__ void k_weights(const float* __restrict__ att,
                          const float* __restrict__ fwy,
                          const float* __restrict__ fwx) {
    int gid = blockIdx.x * 256 + threadIdx.x;
    int o = gid & 63, i = (gid >> 6) & 63, f = (gid >> 12) & 31, b = gid >> 17;
    float a0 = att[b*KK+0], a1 = att[b*KK+1], a2 = att[b*KK+2], a3 = att[b*KK+3];
    const int ks = CI*CO*MODES*2;
    int base = ((i*CO + o)*MODES + f)*2;
    float yr, yi, xr, xi;
    yr = a0*fwy[base   ] + a1*fwy[base+ks   ] + a2*fwy[base+2*ks  ] + a3*fwy[base+3*ks  ];
    yi = a0*fwy[base+1 ] + a1*fwy[base+ks+1 ] + a2*fwy[base+2*ks+1] + a3*fwy[base+3*ks+1];
    xr = a0*fwx[base   ] + a1*fwx[base+ks   ] + a2*fwx[base+2*ks  ] + a3*fwx[base+3*ks  ];
    xi = a0*fwx[base+1 ] + a1*fwx[base+ks+1 ] + a2*fwx[base+2*ks+1] + a3*fwx[base+3*ks+1];
    g_wy[gid] = make_float2(yr, yi);
    g_wx[gid] = make_float2(xr, xi);
}

// ---------------- K0b: MLP weight image ----------------
__global__ void k_wprep(const float* __restrict__ w1, const float* __restrict__ w2) {
    int gid = blockIdx.x * 256 + threadIdx.x;
    if (gid < 16384) {
        int i = gid >> 8, j = gid & 255;
        wr_h(g_Wimg + W_W1 + (uint32_t)j*144 + (uint32_t)i*2, w1[gid]);
    } else {
        int idx = gid - 16384;
        int j = idx >> 6, o = idx & 63;
        wr_h(g_Wimg + W_W2 + (uint32_t)o*528 + (uint32_t)j*2, w2[idx]);
    }
}

// ---------------- K0c: transform tables ----------------
__global__ void k_tprep() {
    int gid = blockIdx.x * 256 + threadIdx.x;
    int sel = gid >> 14;
    int idx = gid & 16383;
    const float inv = 0.04428074428f;
    if (sel == 0) {
        int r = idx >> 8, k = idx & 255;
        int f = r >> 1;
        float ang = (float)((f*k) & 255) * (1.0f/128.0f);
        float v = (r & 1) ? -0.0625f*sinpif(ang) : 0.0625f*cospif(ang);
        wr_h(g_TY + (uint32_t)r*T_ST + (uint32_t)k*2, v);
    } else if (sel == 1) {
        int r = idx >> 8, k = idx & 255;
        int f = r >> 1;
        float v;
        if (r & 1) v = -2.0f*inv*sinpif((float)((f*k) % 510) * (1.0f/255.0f));
        else       v = (k == 0) ? inv : ((k == 255) ? ((f & 1) ? -inv : inv) : 0.0f);
        wr_h(g_TX + (uint32_t)r*T_ST + (uint32_t)k*2, v);
    } else if (sel == 2) {
        int r = idx >> 6, k = idx & 63;
        int f = k >> 1;
        float ang = (float)((f*r) & 255) * (1.0f/128.0f);
        float v = (k & 1) ? -0.125f*sinpif(ang)
                          : ((f == 0) ? 0.0625f : 0.125f)*cospif(ang);
        wr_h(g_SY + (uint32_t)r*S_ST + (uint32_t)k*2, v);
    } else {
        int r = idx >> 6, k = idx & 63;
        int f = k >> 1;
        float ang = (float)((f*r) % 510) * (1.0f/255.0f);
        float v = (k & 1) ? -2.0f*inv*sinpif(ang)
                          : ((f == 0) ? inv : 2.0f*inv)*cospif(ang);
        wr_h(g_SX + (uint32_t)r*S_ST + (uint32_t)k*2, v);
    }
}

// ---------------- K1: forward transforms (single-fp16 data) ----------------
#define FW_B    33792
#define FW_TOT  70656
__global__ void __launch_bounds__(512) k_fwd_mma(const float* __restrict__ x) {
    extern __shared__ __align__(16) unsigned char sm[];
    int t = threadIdx.x, w = t >> 5, l = t & 31, lq = l & 3;
    int z = blockIdx.x;
    int branch = z >> 8;
    int grp = z & 255;
    int b = grp >> 5, g = grp & 31;

    {
        const float4* src = (const float4*)(branch ? g_TX : g_TY);
        float4* dst = (float4*)sm;
        for (int i = t; i < T_TOT/16; i += 512) dst[i] = src[i];
    }

    int mt = w & 3, nh = w >> 2;
    uint32_t smb = smem_u32(sm);
    uint32_t aAddr = smb + (uint32_t)(mt*16 + (l & 15))*T_ST + (uint32_t)((l >> 4)*16);
    uint32_t bAddr = smb + FW_B
                   + (uint32_t)((l & 7) + ((l >> 3) & 1)*8)*144
                   + (uint32_t)(nh*32) + (uint32_t)((l >> 4)*16);
    float* outb = (float*)(branch ? g_XfX : g_XfY);

    float4 v[8];
    {
        int mn0 = g*8;
        #pragma unroll
        for (int it = 0; it < 8; it++) {
            int flat = it*512 + t;
            int c4 = flat & 15, k = flat >> 4;
            const float* p0;
            if (branch == 0) p0 = x + ((size_t)(b*256 + mn0))*16384 + (size_t)k*64 + c4*4;
            else             p0 = x + (((size_t)(b*256 + k))*256 + mn0)*64 + c4*4;
            v[it] = *(const float4*)p0;
        }
    }

    for (int it8 = 0; it8 < 8; it8++) {
        int mn = g*8 + it8;
        __syncthreads();
        #pragma unroll
        for (int it = 0; it < 8; it++) {
            int flat = it*512 + t;
            int c4 = flat & 15, k = flat >> 4;
            uint32_t h0 = cvt1_h(v[it].x, v[it].y);
            uint32_t h1 = cvt1_h(v[it].z, v[it].w);
            *(uint2*)(sm + FW_B + k*144 + c4*8) = make_uint2(h0, h1);
        }
        __syncthreads();

        if (it8 < 7) {
            int mn1 = mn + 1;
            #pragma unroll
            for (int it = 0; it < 8; it++) {
                int flat = it*512 + t;
                int c4 = flat & 15, k = flat >> 4;
                const float* p0;
                if (branch == 0) p0 = x + ((size_t)(b*256 + mn1))*16384 + (size_t)k*64 + c4*4;
                else             p0 = x + (((size_t)(b*256 + k))*256 + mn1)*64 + c4*4;
                v[it] = *(const float4*)p0;
            }
        }

        float c[2][4];
        #pragma unroll
        for (int j = 0; j < 2; j++)
            #pragma unroll
            for (int q = 0; q < 4; q++) c[j][q] = 0.f;

        #pragma unroll
        for (int kk = 0; kk < 16; kk++) {
            uint32_t ah[4], bh[4];
            ldsm4(ah, aAddr + kk*32);
            ldsm4t(bh, bAddr + kk*2304);
            mma_f16(c[0], ah, bh[0], bh[1]);
            mma_f16(c[1], ah, bh[2], bh[3]);
        }

        #pragma unroll
        for (int j = 0; j < 2; j++) {
            int ch = nh*16 + j*8 + 2*lq;
            int r0 = mt*16 + (l >> 2), r1 = r0 + 8;
            size_t base0 = ((size_t)(b*32 + (r0 >> 1))*256 + mn)*128 + ch*2 + (r0 & 1);
            size_t base1 = ((size_t)(b*32 + (r1 >> 1))*256 + mn)*128 + ch*2 + (r1 & 1);
            outb[base0]     = c[j][0];
            outb[base0 + 2] = c[j][1];
            outb[base1]     = c[j][2];
            outb[base1 + 2] = c[j][3];
        }
    }
}

// ---------------- K2: complex GEMM (A split fp16, W single fp16; unchanged) ----------------
#define MX_AHI 0
#define MX_ALO 69632
#define MX_W   139264
#define MX_TOT 174080

__global__ void __launch_bounds__(512) k_mix_mma() {
    extern __shared__ __align__(16) unsigned char sm[];
    int t = threadIdx.x, w = t >> 5, l = t & 31, lq = l & 3;
    int z = blockIdx.x, branch = z >> 8, bf = z & 255;
    const float2* A = (branch ? g_XfX : g_XfY) + (size_t)bf*MM*CI;
    const float2* W = (branch ? g_wx  : g_wy ) + (size_t)bf*CI*CO;
    float2*       C = (branch ? g_YfX : g_YfY) + (size_t)bf*MM*CO;

    {
        const float4* Af = (const float4*)A;
        #pragma unroll
        for (int it = 0; it < 16; it++) {
            int ft = it*512 + t;
            int row = ft >> 5, c4 = ft & 31;
            float4 v = Af[ft];
            uint32_t h01, l01, h23, l23;
            cvt_pair_h(v.x, v.y, h01, l01);
            cvt_pair_h(v.z, v.w, h23, l23);
            *(uint2*)(sm + MX_AHI + row*272 + c4*8) = make_uint2(h01, h23);
            *(uint2*)(sm + MX_ALO + row*272 + c4*8) = make_uint2(l01, l23);
        }
    }
    {
        #pragma unroll
        for (int it = 0; it < 8; it++) {
            int flat = it*512 + t;
            int i = flat >> 6, o = flat & 63;
            float2 wv = W[flat];
            uint32_t ha = pk_h2(__float2half(wv.x), __float2half(-wv.y));
            uint32_t hb = pk_h2(__float2half(wv.y), __float2half(wv.x));
            *(uint32_t*)(sm + MX_W + (2*o  )*272 + i*4) = ha;
            *(uint32_t*)(sm + MX_W + (2*o+1)*272 + i*4) = hb;
        }
    }
    __syncthreads();

    uint32_t smb = smem_u32(sm);
    int m0 = w*16;
    uint32_t aAddr = smb + MX_AHI + (uint32_t)(m0 + (l & 15))*272 + (uint32_t)((l >> 4)*16);
    uint32_t bBase = smb + MX_W + (uint32_t)(((l >> 4)*8) + (l & 7))*272
                   + (uint32_t)(((l >> 3) & 1)*16);

    float acc[16][4];
    #pragma unroll
    for (int j2 = 0; j2 < 16; j2++)
        #pragma unroll
        for (int q = 0; q < 4; q++) acc[j2][q] = 0.f;

    #pragma unroll
    for (int kt = 0; kt < 8; kt++) {
        uint32_t ah[4], al[4];
        ldsm4(ah, aAddr + kt*32);
        ldsm4(al, aAddr + (MX_ALO - MX_AHI) + kt*32);
        #pragma unroll
        for (int u = 0; u < 8; u++) {
            uint32_t bh[4];
            ldsm4(bh, bBase + (uint32_t)(u*16)*272 + kt*32);
            mma_f16(acc[2*u  ], ah, bh[0], bh[1]);
            mma_f16(acc[2*u  ], al, bh[0], bh[1]);
            mma_f16(acc[2*u+1], ah, bh[2], bh[3]);
            mma_f16(acc[2*u+1], al, bh[2], bh[3]);
        }
    }

    float* Cf = (float*)C;
    #pragma unroll
    for (int j2 = 0; j2 < 16; j2++) {
        int row = m0 + (l >> 2);
        int col = j2*8 + 2*lq;
        *(float2*)(Cf + (size_t)row*128 + col)     = make_float2(acc[j2][0], acc[j2][1]);
        *(float2*)(Cf + (size_t)(row+8)*128 + col) = make_float2(acc[j2][2], acc[j2][3]);
    }
}

// ---------------- K3: inverse transform X (single-fp16 data) -> g_xsum2 ----------------
#define IV_B   36864
#define IV_TOT 46080
__global__ void __launch_bounds__(512) k_inv_mma() {
    extern __shared__ __align__(16) unsigned char sm[];
    int t = threadIdx.x, w = t >> 5, l = t & 31, lq = l & 3;
    int z = blockIdx.x;             // 256
    int b = z >> 5, g = z & 31;

    {
        const float4* src = (const float4*)g_SX;
        float4* dst = (float4*)sm;
        for (int i = t; i < S_TOT/16; i += 512) dst[i] = src[i];
    }

    uint32_t smb = smem_u32(sm);
    uint32_t aAddr = smb + (uint32_t)(w*16 + (l & 15))*S_ST + (uint32_t)((l >> 4)*16);
    uint32_t bBase = smb + IV_B
                   + (uint32_t)((l & 7) + ((l >> 3) & 1)*8)*144
                   + (uint32_t)((l >> 4)*16);
    const float2* Y = g_YfX;
    float* outb = g_xsum2;

    float4 y[2];
    {
        int mn0 = g*8;
        #pragma unroll
        for (int it = 0; it < 2; it++) {
            int flat = it*512 + t;
            int f = flat >> 5, cp = flat & 31;
            y[it] = *(const float4*)(Y + ((size_t)(b*32 + f)*256 + mn0)*64 + 2*cp);
        }
    }
    __syncthreads();

    uint32_t ah[4][4];
    #pragma unroll
    for (int kk = 0; kk < 4; kk++) ldsm4(ah[kk], aAddr + kk*32);

    for (int it8 = 0; it8 < 8; it8++) {
        int mn = g*8 + it8;
        if (it8 > 0) __syncthreads();
        #pragma unroll
        for (int it = 0; it < 2; it++) {
            int flat = it*512 + t;
            int f = flat >> 5, cp = flat & 31;
            float4 v = y[it];
            *(uint32_t*)(sm + IV_B + (2*f  )*144 + cp*4) = cvt1_h(v.x, v.z);
            *(uint32_t*)(sm + IV_B + (2*f+1)*144 + cp*4) = cvt1_h(v.y, v.w);
        }
        __syncthreads();

        if (it8 < 7) {
            int mn1 = mn + 1;
            #pragma unroll
            for (int it = 0; it < 2; it++) {
                int flat = it*512 + t;
                int f = flat >> 5, cp = flat & 31;
                y[it] = *(const float4*)(Y + ((size_t)(b*32 + f)*256 + mn1)*64 + 2*cp);
            }
        }

        float c[8][4];
        #pragma unroll
        for (int j = 0; j < 8; j++)
            #pragma unroll
            for (int q = 0; q < 4; q++) c[j][q] = 0.f;

        #pragma unroll
        for (int kk = 0; kk < 4; kk++) {
            #pragma unroll
            for (int u = 0; u < 4; u++) {
                uint32_t bh[4];
                ldsm4t(bh, bBase + (uint32_t)(u*32) + (uint32_t)(kk*16)*144);
                mma_f16(c[2*u  ], ah[kk], bh[0], bh[1]);
                mma_f16(c[2*u+1], ah[kk], bh[2], bh[3]);
            }
        }

        #pragma unroll
        for (int j = 0; j < 8; j++) {
            int col = j*8 + 2*lq;
            int r0 = w*16 + (l >> 2), r1 = r0 + 8;
            size_t a0 = (((size_t)(b*256 + r0))*256 + mn)*64 + col;
            size_t a1 = (((size_t)(b*256 + r1))*256 + mn)*64 + col;
            *(float2*)(outb + a0) = make_float2(c[j][0], c[j][1]);
            *(float2*)(outb + a1) = make_float2(c[j][2], c[j][3]);
        }
    }
}

// ---------------- K4: fused inv-Y (single-fp16 data) + MLP + LayerNorm ----------------
#define FM_SA_HI 0
#define FM_SA_LO 36864
#define FM_W     73728
#define FM_S     144384
#define FM_B     181248
#define FM_B1    190464
#define FM_B2    191488
#define FM_GAM   191744
#define FM_BET   192000
#define FM_TOT   192256

__global__ void __launch_bounds__(512) k_mlp_fused(const float* __restrict__ b1,
                                                   const float* __restrict__ b2,
                                                   const float* __restrict__ gamma,
                                                   const float* __restrict__ beta,
                                                   float* __restrict__ out) {
    extern __shared__ __align__(16) unsigned char sm[];
    int t = threadIdx.x;
    int w = t >> 5, l = t & 31;
    int lq = l & 3;
    int blk = blockIdx.x;

    {
        const float4* src = (const float4*)g_Wimg;
        float4* dst = (float4*)(sm + FM_W);
        for (int i = t; i < W_TOT/16; i += 512) dst[i] = src[i];
        const float4* src2 = (const float4*)g_SY;
        float4* dst2 = (float4*)(sm + FM_S);
        for (int i = t; i < S_TOT/16; i += 512) dst2[i] = src2[i];
    }
    float* b1s = (float*)(sm + FM_B1);
    float* b2s = (float*)(sm + FM_B2);
    float* gs  = (float*)(sm + FM_GAM);
    float* bs  = (float*)(sm + FM_BET);
    if (t < 256) b1s[t] = b1[t];
    if (t >= 256 && t < 320) { int q = t - 256; b2s[q] = b2[q]; gs[q] = gamma[q]; bs[q] = beta[q]; }

    uint32_t smb = smem_u32(sm);
    uint32_t sAAddr = smb + FM_S + (uint32_t)(w*16 + (l & 15))*S_ST + (uint32_t)((l >> 4)*16);
    uint32_t sBBase = smb + FM_B
                    + (uint32_t)((l & 7) + ((l >> 3) & 1)*8)*144
                    + (uint32_t)((l >> 4)*16);
    uint32_t aAddr  = smb + FM_SA_HI + (uint32_t)(w*16 + (l & 15))*144 + (uint32_t)((l >> 4)*16);
    uint32_t w1Base = smb + FM_W + W_W1
                    + (uint32_t)(((l >> 4)*8) + (l & 7))*144 + (uint32_t)(((l >> 3) & 1)*16);
    uint32_t w2Base = smb + FM_W + W_W2
                    + (uint32_t)(((l >> 4)*8) + (l & 7))*528 + (uint32_t)(((l >> 3) & 1)*16);

    float4 y[2];
    {
        int tile0 = blk*4;
        int b = tile0 >> 8, m = tile0 & 255;
        #pragma unroll
        for (int it = 0; it < 2; it++) {
            int flat = it*512 + t;
            int f = flat >> 5, cp = flat & 31;
            y[it] = *(const float4*)(g_YfY + ((size_t)(b*32 + f)*256 + m)*64 + 2*cp);
        }
    }
    __syncthreads();

    for (int tt4 = 0; tt4 < 4; tt4++) {
        int tile = blk*4 + tt4;
        if (tt4 > 0) __syncthreads();

        #pragma unroll
        for (int it = 0; it < 2; it++) {
            int flat = it*512 + t;
            int f = flat >> 5, cp = flat & 31;
            float4 v = y[it];
            *(uint32_t*)(sm + FM_B + (2*f  )*144 + cp*4) = cvt1_h(v.x, v.z);
            *(uint32_t*)(sm + FM_B + (2*f+1)*144 + cp*4) = cvt1_h(v.y, v.w);
        }
        __syncthreads();

        if (tt4 < 3) {
            int tileN = tile + 1;
            int bN = tileN >> 8, mN = tileN & 255;
            #pragma unroll
            for (int it = 0; it < 2; it++) {
                int flat = it*512 + t;
                int f = flat >> 5, cp = flat & 31;
                y[it] = *(const float4*)(g_YfY + ((size_t)(bN*32 + f)*256 + mN)*64 + 2*cp);
            }
        }

        // ---- inverse-Y synthesis MMA ----
        float ci[8][4];
        #pragma unroll
        for (int j = 0; j < 8; j++)
            #pragma unroll
            for (int q = 0; q < 4; q++) ci[j][q] = 0.f;

        #pragma unroll
        for (int kk = 0; kk < 4; kk++) {
            uint32_t ah[4];
            ldsm4(ah, sAAddr + kk*32);
            #pragma unroll
            for (int u = 0; u < 4; u++) {
                uint32_t bh[4];
                ldsm4t(bh, sBBase + (uint32_t)(u*32) + (uint32_t)(kk*16)*144);
                mma_f16(ci[2*u  ], ah, bh[0], bh[1]);
                mma_f16(ci[2*u+1], ah, bh[2], bh[3]);
            }
        }

        // ---- add xsum2(X branch), store into SA planes ----
        {
            size_t base = (size_t)tile * 256;
            int r0 = w*16 + (l >> 2), r1 = r0 + 8;
            #pragma unroll
            for (int j = 0; j < 8; j++) {
                int col = j*8 + 2*lq;
                float2 v0 = *(const float2*)(g_xsum2 + (base + r0)*64 + col);
                float2 v1 = *(const float2*)(g_xsum2 + (base + r1)*64 + col);
                v0.x += ci[j][0]; v0.y += ci[j][1];
                v1.x += ci[j][2]; v1.y += ci[j][3];
                uint32_t h0, l0, h1, l1;
                cvt_pair_h(v0.x, v0.y, h0, l0);
                cvt_pair_h(v1.x, v1.y, h1, l1);
                *(uint32_t*)(sm + FM_SA_HI + r0*144 + col*2) = h0;
                *(uint32_t*)(sm + FM_SA_LO + r0*144 + col*2) = l0;
                *(uint32_t*)(sm + FM_SA_HI + r1*144 + col*2) = h1;
                *(uint32_t*)(sm + FM_SA_LO + r1*144 + col*2) = l1;
            }
        }
        __syncthreads();

        // ---- MLP ----
        float d2[8][4];
        #pragma unroll
        for (int j = 0; j < 8; j++)
            #pragma unroll
            for (int q = 0; q < 4; q++) d2[j][q] = 0.f;

        for (int cc = 0; cc < 4; cc++) {
            float h[8][4];
            #pragma unroll
            for (int j = 0; j < 8; j++)
                #pragma unroll
                for (int q = 0; q < 4; q++) h[j][q] = 0.f;

            #pragma unroll
            for (int kt = 0; kt < 4; kt++) {
                uint32_t ah[4], al[4];
                ldsm4(ah, aAddr + kt*32);
                ldsm4(al, aAddr + (FM_SA_LO - FM_SA_HI) + kt*32);
                #pragma unroll
                for (int u = 0; u < 4; u++) {
                    uint32_t bh[4];
                    ldsm4(bh, w1Base + (uint32_t)(cc*64 + u*16)*144 + kt*32);
                    mma_f16(h[2*u  ], ah, bh[0], bh[1]);
                    mma_f16(h[2*u  ], al, bh[0], bh[1]);
                    mma_f16(h[2*u+1], ah, bh[2], bh[3]);
                    mma_f16(h[2*u+1], al, bh[2], bh[3]);
                }
            }

            #pragma unroll
            for (int kt2 = 0; kt2 < 4; kt2++) {
                int j = 2*kt2;
                uint32_t ah2[4], al2[4];
                {
                    int g0 = cc*64 + j*8 + 2*lq;
                    float bA = b1s[g0],   bB = b1s[g0+1];
                    float bC = b1s[g0+8], bD = b1s[g0+9];
                    float v0 = fmaxf(h[j][0] + bA, 0.f);
                    float v1 = fmaxf(h[j][1] + bB, 0.f);
                    cvt_pair_h(v0, v1, ah2[0], al2[0]);
                    v0 = fmaxf(h[j][2] + bA, 0.f);
                    v1 = fmaxf(h[j][3] + bB, 0.f);
                    cvt_pair_h(v0, v1, ah2[1], al2[1]);
                    v0 = fmaxf(h[j+1][0] + bC, 0.f);
                    v1 = fmaxf(h[j+1][1] + bD, 0.f);
                    cvt_pair_h(v0, v1, ah2[2], al2[2]);
                    v0 = fmaxf(h[j+1][2] + bC, 0.f);
                    v1 = fmaxf(h[j+1][3] + bD, 0.f);
                    cvt_pair_h(v0, v1, ah2[3], al2[3]);
                }
                uint32_t kByte = (uint32_t)(cc*128 + kt2*32);
                #pragma unroll
                for (int u = 0; u < 4; u++) {
                    uint32_t bh[4];
                    ldsm4(bh, w2Base + (uint32_t)(u*16)*528 + kByte);
                    mma_f16(d2[2*u  ], ah2, bh[0], bh[1]);
                    mma_f16(d2[2*u  ], al2, bh[0], bh[1]);
                    mma_f16(d2[2*u+1], ah2, bh[2], bh[3]);
                    mma_f16(d2[2*u+1], al2, bh[2], bh[3]);
                }
            }
        }

        // ---- +b2, LayerNorm, write out ----
        #pragma unroll
        for (int rh = 0; rh < 2; rh++) {
            float vals[16];
            #pragma unroll
            for (int j2 = 0; j2 < 8; j2++) {
                int col = j2*8 + 2*lq;
                vals[2*j2  ] = d2[j2][2*rh  ] + b2s[col];
                vals[2*j2+1] = d2[j2][2*rh+1] + b2s[col+1];
            }
            float s = 0.f;
            #pragma unroll
            for (int q = 0; q < 16; q++) s += vals[q];
            s += __shfl_xor_sync(0xffffffffu, s, 1);
            s += __shfl_xor_sync(0xffffffffu, s, 2);
            float mu = s * (1.f/64.f);
            float v = 0.f;
            #pragma unroll
            for (int q = 0; q < 16; q++) { float d = vals[q] - mu; v = fmaf(d, d, v); }
            v += __shfl_xor_sync(0xffffffffu, v, 1);
            v += __shfl_xor_sync(0xffffffffu, v, 2);
            float rinv = rsqrtf(v * (1.f/64.f) + 1e-5f);
            size_t row = (size_t)tile*256 + w*16 + rh*8 + (l >> 2);
            #pragma unroll
            for (int j2 = 0; j2 < 8; j2++) {
                int col = j2*8 + 2*lq;
                float2 r;
                r.x = (vals[2*j2  ] - mu) * rinv * gs[col  ] + bs[col  ];
                r.y = (vals[2*j2+1] - mu) * rinv * gs[col+1] + bs[col+1];
                *(float2*)(out + row*64 + col) = r;
            }
        }
    }
}

// ---------------- launcher ----------------
extern "C" void kernel_launch(void* const* d_in, const int* in_sizes, int n_in,
                              void* d_out, int out_size) {
    (void)in_sizes; (void)n_in; (void)out_size;
    const float* x     = (const float*)d_in[0];
    const float* att   = (const float*)d_in[1];
    const float* fwy   = (const float*)d_in[2];
    const float* fwx   = (const float*)d_in[3];
    const float* w1    = (const float*)d_in[4];
    const float* b1    = (const float*)d_in[5];
    const float* w2    = (const float*)d_in[6];
    const float* b2    = (const float*)d_in[7];
    const float* gamma = (const float*)d_in[8];
    const float* beta  = (const float*)d_in[9];
    float* out = (float*)d_out;

    cudaFuncSetAttribute(k_fwd_mma,  cudaFuncAttributeMaxDynamicSharedMemorySize, FW_TOT);
    cudaFuncSetAttribute(k_mix_mma,  cudaFuncAttributeMaxDynamicSharedMemorySize, MX_TOT);
    cudaFuncSetAttribute(k_inv_mma,  cudaFuncAttributeMaxDynamicSharedMemorySize, IV_TOT);
    cudaFuncSetAttribute(k_mlp_fused,cudaFuncAttributeMaxDynamicSharedMemorySize, FM_TOT);

    k_weights<<<(BATCH*MODES*CI*CO)/256, 256>>>(att, fwy, fwx);
    k_wprep<<<128, 256>>>(w1, w2);
    k_tprep<<<256, 256>>>();
    k_fwd_mma<<<512, 512, FW_TOT>>>(x);
    k_mix_mma<<<2*BATCH*MODES, 512, MX_TOT>>>();
    k_inv_mma<<<256, 512, IV_TOT>>>();
    k_mlp_fused<<<512, 512, FM_TOT>>>(b1, b2, gamma, beta, out);
}

// round 16
// speedup vs baseline: 2.2416x; 1.0326x over previous
#include <cuda_runtime.h>
#include <cuda_fp16.h>
#include <cstdint>

#define BATCH 8
#define MM 256
#define NN 256
#define CI 64
#define CO 64
#define KK 4
#define MODES 32

// ---------------- scratch ----------------
__device__ float2 g_wy [BATCH*MODES*CI*CO];
__device__ float2 g_wx [BATCH*MODES*CI*CO];
// spectra stored fp16, layout [b][f][mn][2*ch + p] (p=0 re, 1 im)
__device__ __half g_XfY[(size_t)BATCH*MODES*MM*CI*2];
__device__ __half g_XfX[(size_t)BATCH*MODES*NN*CI*2];
__device__ __half g_YfY[(size_t)BATCH*MODES*MM*CO*2];
__device__ __half g_YfX[(size_t)BATCH*MODES*NN*CO*2];
__device__ float  g_xsum2[(size_t)BATCH*MM*NN*CO];

// MLP weight image (single fp16)
#define W_W1   0
#define W_W2   36864
#define W_TOT  70656
__device__ __align__(16) unsigned char g_Wimg[W_TOT];

// transform tables (single fp16)
#define T_ST   528
#define T_TOT  33792
__device__ __align__(16) unsigned char g_TY[T_TOT];
__device__ __align__(16) unsigned char g_TX[T_TOT];
#define S_ST   144
#define S_TOT  36864
__device__ __align__(16) unsigned char g_SY[S_TOT];
__device__ __align__(16) unsigned char g_SX[S_TOT];

// ---------------- helpers ----------------
__device__ __forceinline__ uint32_t smem_u32(const void* p) {
    uint32_t a;
    asm("{ .reg .u64 t; cvta.to.shared.u64 t, %1; cvt.u32.u64 %0, t; }" : "=r"(a) : "l"(p));
    return a;
}
__device__ __forceinline__ void ldsm4(uint32_t* r, uint32_t a) {
    asm volatile("ldmatrix.sync.aligned.m8n8.x4.shared.b16 {%0,%1,%2,%3}, [%4];"
        : "=r"(r[0]), "=r"(r[1]), "=r"(r[2]), "=r"(r[3]) : "r"(a));
}
__device__ __forceinline__ void ldsm4t(uint32_t* r, uint32_t a) {
    asm volatile("ldmatrix.sync.aligned.m8n8.x4.trans.shared.b16 {%0,%1,%2,%3}, [%4];"
        : "=r"(r[0]), "=r"(r[1]), "=r"(r[2]), "=r"(r[3]) : "r"(a));
}
__device__ __forceinline__ uint32_t pk_h2(__half a, __half b) {
    __half2 t; t.x = a; t.y = b; return *(uint32_t*)&t;
}
__device__ __forceinline__ uint32_t cvt1_h(float v0, float v1) {
    return pk_h2(__float2half(v0), __float2half(v1));
}
__device__ __forceinline__ void cvt_pair_h(float v0, float v1, uint32_t& hi, uint32_t& lo) {
    __half h0 = __float2half(v0), h1 = __float2half(v1);
    float r0 = v0 - __half2float(h0);
    float r1 = v1 - __half2float(h1);
    hi = pk_h2(h0, h1);
    lo = pk_h2(__float2half(r0), __float2half(r1));
}
__device__ __forceinline__ void mma_f16(float* d, const uint32_t* a, uint32_t b0, uint32_t b1) {
    asm volatile(
        "mma.sync.aligned.m16n8k16.row.col.f32.f16.f16.f32 "
        "{%0,%1,%2,%3},{%4,%5,%6,%7},{%8,%9},{%0,%1,%2,%3};"
        : "+f"(d[0]), "+f"(d[1]), "+f"(d[2]), "+f"(d[3])
        : "r"(a[0]), "r"(a[1]), "r"(a[2]), "r"(a[3]), "r"(b0), "r"(b1));
}
__device__ __forceinline__ void wr_h(unsigned char* p, float v) {
    *(__half*)p = __float2half(v);
}

// ---------------- K0: spectral weights ----------------
__global__ void k_weights(const float* __restrict__ att,
                          const float* __restrict__ fwy,
                          const float* __restrict__ fwx) {
    int gid = blockIdx.x * 256 + threadIdx.x;
    int o = gid & 63, i = (gid >> 6) & 63, f = (gid >> 12) & 31, b = gid >> 17;
    float a0 = att[b*KK+0], a1 = att[b*KK+1], a2 = att[b*KK+2], a3 = att[b*KK+3];
    const int ks = CI*CO*MODES*2;
    int base = ((i*CO + o)*MODES + f)*2;
    float yr, yi, xr, xi;
    yr = a0*fwy[base   ] + a1*fwy[base+ks   ] + a2*fwy[base+2*ks  ] + a3*fwy[base+3*ks  ];
    yi = a0*fwy[base+1 ] + a1*fwy[base+ks+1 ] + a2*fwy[base+2*ks+1] + a3*fwy[base+3*ks+1];
    xr = a0*fwx[base   ] + a1*fwx[base+ks   ] + a2*fwx[base+2*ks  ] + a3*fwx[base+3*ks  ];
    xi = a0*fwx[base+1 ] + a1*fwx[base+ks+1 ] + a2*fwx[base+2*ks+1] + a3*fwx[base+3*ks+1];
    g_wy[gid] = make_float2(yr, yi);
    g_wx[gid] = make_float2(xr, xi);
}

// ---------------- K0b: MLP weight image ----------------
__global__ void k_wprep(const float* __restrict__ w1, const float* __restrict__ w2) {
    int gid = blockIdx.x * 256 + threadIdx.x;
    if (gid < 16384) {
        int i = gid >> 8, j = gid & 255;
        wr_h(g_Wimg + W_W1 + (uint32_t)j*144 + (uint32_t)i*2, w1[gid]);
    } else {
        int idx = gid - 16384;
        int j = idx >> 6, o = idx & 63;
        wr_h(g_Wimg + W_W2 + (uint32_t)o*528 + (uint32_t)j*2, w2[idx]);
    }
}

// ---------------- K0c: transform tables ----------------
__global__ void k_tprep() {
    int gid = blockIdx.x * 256 + threadIdx.x;
    int sel = gid >> 14;
    int idx = gid & 16383;
    const float inv = 0.04428074428f;
    if (sel == 0) {
        int r = idx >> 8, k = idx & 255;
        int f = r >> 1;
        float ang = (float)((f*k) & 255) * (1.0f/128.0f);
        float v = (r & 1) ? -0.0625f*sinpif(ang) : 0.0625f*cospif(ang);
        wr_h(g_TY + (uint32_t)r*T_ST + (uint32_t)k*2, v);
    } else if (sel == 1) {
        int r = idx >> 8, k = idx & 255;
        int f = r >> 1;
        float v;
        if (r & 1) v = -2.0f*inv*sinpif((float)((f*k) % 510) * (1.0f/255.0f));
        else       v = (k == 0) ? inv : ((k == 255) ? ((f & 1) ? -inv : inv) : 0.0f);
        wr_h(g_TX + (uint32_t)r*T_ST + (uint32_t)k*2, v);
    } else if (sel == 2) {
        int r = idx >> 6, k = idx & 63;
        int f = k >> 1;
        float ang = (float)((f*r) & 255) * (1.0f/128.0f);
        float v = (k & 1) ? -0.125f*sinpif(ang)
                          : ((f == 0) ? 0.0625f : 0.125f)*cospif(ang);
        wr_h(g_SY + (uint32_t)r*S_ST + (uint32_t)k*2, v);
    } else {
        int r = idx >> 6, k = idx & 63;
        int f = k >> 1;
        float ang = (float)((f*r) % 510) * (1.0f/255.0f);
        float v = (k & 1) ? -2.0f*inv*sinpif(ang)
                          : ((f == 0) ? inv : 2.0f*inv)*cospif(ang);
        wr_h(g_SX + (uint32_t)r*S_ST + (uint32_t)k*2, v);
    }
}

// ---------------- K1: forward transforms (fp16 out) ----------------
#define FW_B    33792
#define FW_TOT  70656
__global__ void __launch_bounds__(512) k_fwd_mma(const float* __restrict__ x) {
    extern __shared__ __align__(16) unsigned char sm[];
    int t = threadIdx.x, w = t >> 5, l = t & 31, lq = l & 3;
    int z = blockIdx.x;
    int branch = z >> 8;
    int grp = z & 255;
    int b = grp >> 5, g = grp & 31;

    {
        const float4* src = (const float4*)(branch ? g_TX : g_TY);
        float4* dst = (float4*)sm;
        for (int i = t; i < T_TOT/16; i += 512) dst[i] = src[i];
    }

    int mt = w & 3, nh = w >> 2;
    uint32_t smb = smem_u32(sm);
    uint32_t aAddr = smb + (uint32_t)(mt*16 + (l & 15))*T_ST + (uint32_t)((l >> 4)*16);
    uint32_t bAddr = smb + FW_B
                   + (uint32_t)((l & 7) + ((l >> 3) & 1)*8)*144
                   + (uint32_t)(nh*32) + (uint32_t)((l >> 4)*16);
    __half* outb = branch ? g_XfX : g_XfY;

    float4 v[8];
    {
        int mn0 = g*8;
        #pragma unroll
        for (int it = 0; it < 8; it++) {
            int flat = it*512 + t;
            int c4 = flat & 15, k = flat >> 4;
            const float* p0;
            if (branch == 0) p0 = x + ((size_t)(b*256 + mn0))*16384 + (size_t)k*64 + c4*4;
            else             p0 = x + (((size_t)(b*256 + k))*256 + mn0)*64 + c4*4;
            v[it] = *(const float4*)p0;
        }
    }

    for (int it8 = 0; it8 < 8; it8++) {
        int mn = g*8 + it8;
        __syncthreads();
        #pragma unroll
        for (int it = 0; it < 8; it++) {
            int flat = it*512 + t;
            int c4 = flat & 15, k = flat >> 4;
            uint32_t h0 = cvt1_h(v[it].x, v[it].y);
            uint32_t h1 = cvt1_h(v[it].z, v[it].w);
            *(uint2*)(sm + FW_B + k*144 + c4*8) = make_uint2(h0, h1);
        }
        __syncthreads();

        if (it8 < 7) {
            int mn1 = mn + 1;
            #pragma unroll
            for (int it = 0; it < 8; it++) {
                int flat = it*512 + t;
                int c4 = flat & 15, k = flat >> 4;
                const float* p0;
                if (branch == 0) p0 = x + ((size_t)(b*256 + mn1))*16384 + (size_t)k*64 + c4*4;
                else             p0 = x + (((size_t)(b*256 + k))*256 + mn1)*64 + c4*4;
                v[it] = *(const float4*)p0;
            }
        }

        float c[2][4];
        #pragma unroll
        for (int j = 0; j < 2; j++)
            #pragma unroll
            for (int q = 0; q < 4; q++) c[j][q] = 0.f;

        #pragma unroll
        for (int kk = 0; kk < 16; kk++) {
            uint32_t ah[4], bh[4];
            ldsm4(ah, aAddr + kk*32);
            ldsm4t(bh, bAddr + kk*2304);
            mma_f16(c[0], ah, bh[0], bh[1]);
            mma_f16(c[1], ah, bh[2], bh[3]);
        }

        #pragma unroll
        for (int j = 0; j < 2; j++) {
            int ch = nh*16 + j*8 + 2*lq;
            int r0 = mt*16 + (l >> 2), r1 = r0 + 8;
            size_t base0 = ((size_t)(b*32 + (r0 >> 1))*256 + mn)*128 + ch*2 + (r0 & 1);
            size_t base1 = ((size_t)(b*32 + (r1 >> 1))*256 + mn)*128 + ch*2 + (r1 & 1);
            outb[base0]     = __float2half(c[j][0]);
            outb[base0 + 2] = __float2half(c[j][1]);
            outb[base1]     = __float2half(c[j][2]);
            outb[base1 + 2] = __float2half(c[j][3]);
        }
    }
}

// ---------------- K2: complex GEMM (A exact fp16 single, W single fp16) ----------------
#define MX_A   0
#define MX_W   69632
#define MX_TOT 104448

__global__ void __launch_bounds__(512) k_mix_mma() {
    extern __shared__ __align__(16) unsigned char sm[];
    int t = threadIdx.x, w = t >> 5, l = t & 31, lq = l & 3;
    int z = blockIdx.x, branch = z >> 8, bf = z & 255;
    const __half* A = (branch ? g_XfX : g_XfY) + (size_t)bf*MM*128;
    const float2* W = (branch ? g_wx  : g_wy ) + (size_t)bf*CI*CO;
    __half*       C = (branch ? g_YfX : g_YfY) + (size_t)bf*MM*128;

    // stage A: plain copy, 256 rows x 256B (stride 272)
    {
        const uint4* Af = (const uint4*)A;
        #pragma unroll
        for (int it = 0; it < 8; it++) {
            int ft = it*512 + t;            // 4096 = 256 rows x 16 chunks
            int row = ft >> 4, q = ft & 15;
            *(uint4*)(sm + MX_A + row*272 + q*16) = Af[ft];
        }
    }
    {
        #pragma unroll
        for (int it = 0; it < 8; it++) {
            int flat = it*512 + t;
            int i = flat >> 6, o = flat & 63;
            float2 wv = W[flat];
            uint32_t ha = pk_h2(__float2half(wv.x), __float2half(-wv.y));
            uint32_t hb = pk_h2(__float2half(wv.y), __float2half(wv.x));
            *(uint32_t*)(sm + MX_W + (2*o  )*272 + i*4) = ha;
            *(uint32_t*)(sm + MX_W + (2*o+1)*272 + i*4) = hb;
        }
    }
    __syncthreads();

    uint32_t smb = smem_u32(sm);
    int m0 = w*16;
    uint32_t aAddr = smb + MX_A + (uint32_t)(m0 + (l & 15))*272 + (uint32_t)((l >> 4)*16);
    uint32_t bBase = smb + MX_W + (uint32_t)(((l >> 4)*8) + (l & 7))*272
                   + (uint32_t)(((l >> 3) & 1)*16);

    float acc[16][4];
    #pragma unroll
    for (int j2 = 0; j2 < 16; j2++)
        #pragma unroll
        for (int q = 0; q < 4; q++) acc[j2][q] = 0.f;

    #pragma unroll
    for (int kt = 0; kt < 8; kt++) {
        uint32_t ah[4];
        ldsm4(ah, aAddr + kt*32);
        #pragma unroll
        for (int u = 0; u < 8; u++) {
            uint32_t bh[4];
            ldsm4(bh, bBase + (uint32_t)(u*16)*272 + kt*32);
            mma_f16(acc[2*u  ], ah, bh[0], bh[1]);
            mma_f16(acc[2*u+1], ah, bh[2], bh[3]);
        }
    }

    #pragma unroll
    for (int j2 = 0; j2 < 16; j2++) {
        int row = m0 + (l >> 2);
        int col = j2*8 + 2*lq;
        *(uint32_t*)(C + (size_t)row*128 + col)       = cvt1_h(acc[j2][0], acc[j2][1]);
        *(uint32_t*)(C + (size_t)(row+8)*128 + col)   = cvt1_h(acc[j2][2], acc[j2][3]);
    }
}

// ---------------- K3: inverse transform X (fp16 Y in) -> g_xsum2 ----------------
#define IV_B   36864
#define IV_TOT 46080
__global__ void __launch_bounds__(512) k_inv_mma() {
    extern __shared__ __align__(16) unsigned char sm[];
    int t = threadIdx.x, w = t >> 5, l = t & 31, lq = l & 3;
    int z = blockIdx.x;             // 256
    int b = z >> 5, g = z & 31;

    {
        const float4* src = (const float4*)g_SX;
        float4* dst = (float4*)sm;
        for (int i = t; i < S_TOT/16; i += 512) dst[i] = src[i];
    }

    uint32_t smb = smem_u32(sm);
    uint32_t aAddr = smb + (uint32_t)(w*16 + (l & 15))*S_ST + (uint32_t)((l >> 4)*16);
    uint32_t bBase = smb + IV_B
                   + (uint32_t)((l & 7) + ((l >> 3) & 1)*8)*144
                   + (uint32_t)((l >> 4)*16);
    const __half* Y = g_YfX;
    float* outb = g_xsum2;

    uint2 y[2];                    // 4 halfs each: re0 im0 re1 im1
    {
        int mn0 = g*8;
        #pragma unroll
        for (int it = 0; it < 2; it++) {
            int flat = it*512 + t;
            int f = flat >> 5, cp = flat & 31;
            y[it] = *(const uint2*)(Y + ((size_t)(b*32 + f)*256 + mn0)*128 + 4*cp);
        }
    }
    __syncthreads();

    uint32_t ah[4][4];
    #pragma unroll
    for (int kk = 0; kk < 4; kk++) ldsm4(ah[kk], aAddr + kk*32);

    for (int it8 = 0; it8 < 8; it8++) {
        int mn = g*8 + it8;
        if (it8 > 0) __syncthreads();
        #pragma unroll
        for (int it = 0; it < 2; it++) {
            int flat = it*512 + t;
            int f = flat >> 5, cp = flat & 31;
            uint32_t re = (y[it].x & 0xFFFFu) | (y[it].y << 16);
            uint32_t im = (y[it].x >> 16) | (y[it].y & 0xFFFF0000u);
            *(uint32_t*)(sm + IV_B + (2*f  )*144 + cp*4) = re;
            *(uint32_t*)(sm + IV_B + (2*f+1)*144 + cp*4) = im;
        }
        __syncthreads();

        if (it8 < 7) {
            int mn1 = mn + 1;
            #pragma unroll
            for (int it = 0; it < 2; it++) {
                int flat = it*512 + t;
                int f = flat >> 5, cp = flat & 31;
                y[it] = *(const uint2*)(Y + ((size_t)(b*32 + f)*256 + mn1)*128 + 4*cp);
            }
        }

        float c[8][4];
        #pragma unroll
        for (int j = 0; j < 8; j++)
            #pragma unroll
            for (int q = 0; q < 4; q++) c[j][q] = 0.f;

        #pragma unroll
        for (int kk = 0; kk < 4; kk++) {
            #pragma unroll
            for (int u = 0; u < 4; u++) {
                uint32_t bh[4];
                ldsm4t(bh, bBase + (uint32_t)(u*32) + (uint32_t)(kk*16)*144);
                mma_f16(c[2*u  ], ah[kk], bh[0], bh[1]);
                mma_f16(c[2*u+1], ah[kk], bh[2], bh[3]);
            }
        }

        #pragma unroll
        for (int j = 0; j < 8; j++) {
            int col = j*8 + 2*lq;
            int r0 = w*16 + (l >> 2), r1 = r0 + 8;
            size_t a0 = (((size_t)(b*256 + r0))*256 + mn)*64 + col;
            size_t a1 = (((size_t)(b*256 + r1))*256 + mn)*64 + col;
            *(float2*)(outb + a0) = make_float2(c[j][0], c[j][1]);
            *(float2*)(outb + a1) = make_float2(c[j][2], c[j][3]);
        }
    }
}

// ---------------- K4: fused inv-Y (fp16 Y in) + MLP + LayerNorm ----------------
#define FM_SA_HI 0
#define FM_SA_LO 36864
#define FM_W     73728
#define FM_S     144384
#define FM_B     181248
#define FM_B1    190464
#define FM_B2    191488
#define FM_GAM   191744
#define FM_BET   192000
#define FM_TOT   192256

__global__ void __launch_bounds__(512) k_mlp_fused(const float* __restrict__ b1,
                                                   const float* __restrict__ b2,
                                                   const float* __restrict__ gamma,
                                                   const float* __restrict__ beta,
                                                   float* __restrict__ out) {
    extern __shared__ __align__(16) unsigned char sm[];
    int t = threadIdx.x;
    int w = t >> 5, l = t & 31;
    int lq = l & 3;
    int blk = blockIdx.x;

    {
        const float4* src = (const float4*)g_Wimg;
        float4* dst = (float4*)(sm + FM_W);
        for (int i = t; i < W_TOT/16; i += 512) dst[i] = src[i];
        const float4* src2 = (const float4*)g_SY;
        float4* dst2 = (float4*)(sm + FM_S);
        for (int i = t; i < S_TOT/16; i += 512) dst2[i] = src2[i];
    }
    float* b1s = (float*)(sm + FM_B1);
    float* b2s = (float*)(sm + FM_B2);
    float* gs  = (float*)(sm + FM_GAM);
    float* bs  = (float*)(sm + FM_BET);
    if (t < 256) b1s[t] = b1[t];
    if (t >= 256 && t < 320) { int q = t - 256; b2s[q] = b2[q]; gs[q] = gamma[q]; bs[q] = beta[q]; }

    uint32_t smb = smem_u32(sm);
    uint32_t sAAddr = smb + FM_S + (uint32_t)(w*16 + (l & 15))*S_ST + (uint32_t)((l >> 4)*16);
    uint32_t sBBase = smb + FM_B
                    + (uint32_t)((l & 7) + ((l >> 3) & 1)*8)*144
                    + (uint32_t)((l >> 4)*16);
    uint32_t aAddr  = smb + FM_SA_HI + (uint32_t)(w*16 + (l & 15))*144 + (uint32_t)((l >> 4)*16);
    uint32_t w1Base = smb + FM_W + W_W1
                    + (uint32_t)(((l >> 4)*8) + (l & 7))*144 + (uint32_t)(((l >> 3) & 1)*16);
    uint32_t w2Base = smb + FM_W + W_W2
                    + (uint32_t)(((l >> 4)*8) + (l & 7))*528 + (uint32_t)(((l >> 3) & 1)*16);

    uint2 y[2];
    {
        int tile0 = blk*4;
        int b = tile0 >> 8, m = tile0 & 255;
        #pragma unroll
        for (int it = 0; it < 2; it++) {
            int flat = it*512 + t;
            int f = flat >> 5, cp = flat & 31;
            y[it] = *(const uint2*)(g_YfY + ((size_t)(b*32 + f)*256 + m)*128 + 4*cp);
        }
    }
    __syncthreads();

    for (int tt4 = 0; tt4 < 4; tt4++) {
        int tile = blk*4 + tt4;
        if (tt4 > 0) __syncthreads();

        #pragma unroll
        for (int it = 0; it < 2; it++) {
            int flat = it*512 + t;
            int f = flat >> 5, cp = flat & 31;
            uint32_t re = (y[it].x & 0xFFFFu) | (y[it].y << 16);
            uint32_t im = (y[it].x >> 16) | (y[it].y & 0xFFFF0000u);
            *(uint32_t*)(sm + FM_B + (2*f  )*144 + cp*4) = re;
            *(uint32_t*)(sm + FM_B + (2*f+1)*144 + cp*4) = im;
        }
        __syncthreads();

        if (tt4 < 3) {
            int tileN = tile + 1;
            int bN = tileN >> 8, mN = tileN & 255;
            #pragma unroll
            for (int it = 0; it < 2; it++) {
                int flat = it*512 + t;
                int f = flat >> 5, cp = flat & 31;
                y[it] = *(const uint2*)(g_YfY + ((size_t)(bN*32 + f)*256 + mN)*128 + 4*cp);
            }
        }

        // ---- inverse-Y synthesis MMA ----
        float ci[8][4];
        #pragma unroll
        for (int j = 0; j < 8; j++)
            #pragma unroll
            for (int q = 0; q < 4; q++) ci[j][q] = 0.f;

        #pragma unroll
        for (int kk = 0; kk < 4; kk++) {
            uint32_t ah[4];
            ldsm4(ah, sAAddr + kk*32);
            #pragma unroll
            for (int u = 0; u < 4; u++) {
                uint32_t bh[4];
                ldsm4t(bh, sBBase + (uint32_t)(u*32) + (uint32_t)(kk*16)*144);
                mma_f16(ci[2*u  ], ah, bh[0], bh[1]);
                mma_f16(ci[2*u+1], ah, bh[2], bh[3]);
            }
        }

        // ---- add xsum2(X branch), store into SA planes ----
        {
            size_t base = (size_t)tile * 256;
            int r0 = w*16 + (l >> 2), r1 = r0 + 8;
            #pragma unroll
            for (int j = 0; j < 8; j++) {
                int col = j*8 + 2*lq;
                float2 v0 = *(const float2*)(g_xsum2 + (base + r0)*64 + col);
                float2 v1 = *(const float2*)(g_xsum2 + (base + r1)*64 + col);
                v0.x += ci[j][0]; v0.y += ci[j][1];
                v1.x += ci[j][2]; v1.y += ci[j][3];
                uint32_t h0, l0, h1, l1;
                cvt_pair_h(v0.x, v0.y, h0, l0);
                cvt_pair_h(v1.x, v1.y, h1, l1);
                *(uint32_t*)(sm + FM_SA_HI + r0*144 + col*2) = h0;
                *(uint32_t*)(sm + FM_SA_LO + r0*144 + col*2) = l0;
                *(uint32_t*)(sm + FM_SA_HI + r1*144 + col*2) = h1;
                *(uint32_t*)(sm + FM_SA_LO + r1*144 + col*2) = l1;
            }
        }
        __syncthreads();

        // ---- MLP ----
        float d2[8][4];
        #pragma unroll
        for (int j = 0; j < 8; j++)
            #pragma unroll
            for (int q = 0; q < 4; q++) d2[j][q] = 0.f;

        for (int cc = 0; cc < 4; cc++) {
            float h[8][4];
            #pragma unroll
            for (int j = 0; j < 8; j++)
                #pragma unroll
                for (int q = 0; q < 4; q++) h[j][q] = 0.f;

            #pragma unroll
            for (int kt = 0; kt < 4; kt++) {
                uint32_t ah[4], al[4];
                ldsm4(ah, aAddr + kt*32);
                ldsm4(al, aAddr + (FM_SA_LO - FM_SA_HI) + kt*32);
                #pragma unroll
                for (int u = 0; u < 4; u++) {
                    uint32_t bh[4];
                    ldsm4(bh, w1Base + (uint32_t)(cc*64 + u*16)*144 + kt*32);
                    mma_f16(h[2*u  ], ah, bh[0], bh[1]);
                    mma_f16(h[2*u  ], al, bh[0], bh[1]);
                    mma_f16(h[2*u+1], ah, bh[2], bh[3]);
                    mma_f16(h[2*u+1], al, bh[2], bh[3]);
                }
            }

            #pragma unroll
            for (int kt2 = 0; kt2 < 4; kt2++) {
                int j = 2*kt2;
                uint32_t ah2[4], al2[4];
                {
                    int g0 = cc*64 + j*8 + 2*lq;
                    float bA = b1s[g0],   bB = b1s[g0+1];
                    float bC = b1s[g0+8], bD = b1s[g0+9];
                    float v0 = fmaxf(h[j][0] + bA, 0.f);
                    float v1 = fmaxf(h[j][1] + bB, 0.f);
                    cvt_pair_h(v0, v1, ah2[0], al2[0]);
                    v0 = fmaxf(h[j][2] + bA, 0.f);
                    v1 = fmaxf(h[j][3] + bB, 0.f);
                    cvt_pair_h(v0, v1, ah2[1], al2[1]);
                    v0 = fmaxf(h[j+1][0] + bC, 0.f);
                    v1 = fmaxf(h[j+1][1] + bD, 0.f);
                    cvt_pair_h(v0, v1, ah2[2], al2[2]);
                    v0 = fmaxf(h[j+1][2] + bC, 0.f);
                    v1 = fmaxf(h[j+1][3] + bD, 0.f);
                    cvt_pair_h(v0, v1, ah2[3], al2[3]);
                }
                uint32_t kByte = (uint32_t)(cc*128 + kt2*32);
                #pragma unroll
                for (int u = 0; u < 4; u++) {
                    uint32_t bh[4];
                    ldsm4(bh, w2Base + (uint32_t)(u*16)*528 + kByte);
                    mma_f16(d2[2*u  ], ah2, bh[0], bh[1]);
                    mma_f16(d2[2*u  ], al2, bh[0], bh[1]);
                    mma_f16(d2[2*u+1], ah2, bh[2], bh[3]);
                    mma_f16(d2[2*u+1], al2, bh[2], bh[3]);
                }
            }
        }

        // ---- +b2, LayerNorm, write out ----
        #pragma unroll
        for (int rh = 0; rh < 2; rh++) {
            float vals[16];
            #pragma unroll
            for (int j2 = 0; j2 < 8; j2++) {
                int col = j2*8 + 2*lq;
                vals[2*j2  ] = d2[j2][2*rh  ] + b2s[col];
                vals[2*j2+1] = d2[j2][2*rh+1] + b2s[col+1];
            }
            float s = 0.f;
            #pragma unroll
            for (int q = 0; q < 16; q++) s += vals[q];
            s += __shfl_xor_sync(0xffffffffu, s, 1);
            s += __shfl_xor_sync(0xffffffffu, s, 2);
            float mu = s * (1.f/64.f);
            float v = 0.f;
            #pragma unroll
            for (int q = 0; q < 16; q++) { float d = vals[q] - mu; v = fmaf(d, d, v); }
            v += __shfl_xor_sync(0xffffffffu, v, 1);
            v += __shfl_xor_sync(0xffffffffu, v, 2);
            float rinv = rsqrtf(v * (1.f/64.f) + 1e-5f);
            size_t row = (size_t)tile*256 + w*16 + rh*8 + (l >> 2);
            #pragma unroll
            for (int j2 = 0; j2 < 8; j2++) {
                int col = j2*8 + 2*lq;
                float2 r;
                r.x = (vals[2*j2  ] - mu) * rinv * gs[col  ] + bs[col  ];
                r.y = (vals[2*j2+1] - mu) * rinv * gs[col+1] + bs[col+1];
                *(float2*)(out + row*64 + col) = r;
            }
        }
    }
}

// ---------------- launcher ----------------
extern "C" void kernel_launch(void* const* d_in, const int* in_sizes, int n_in,
                              void* d_out, int out_size) {
    (void)in_sizes; (void)n_in; (void)out_size;
    const float* x     = (const float*)d_in[0];
    const float* att   = (const float*)d_in[1];
    const float* fwy   = (const float*)d_in[2];
    const float* fwx   = (const float*)d_in[3];
    const float* w1    = (const float*)d_in[4];
    const float* b1    = (const float*)d_in[5];
    const float* w2    = (const float*)d_in[6];
    const float* b2    = (const float*)d_in[7];
    const float* gamma = (const float*)d_in[8];
    const float* beta  = (const float*)d_in[9];
    float* out = (float*)d_out;

    cudaFuncSetAttribute(k_fwd_mma,  cudaFuncAttributeMaxDynamicSharedMemorySize, FW_TOT);
    cudaFuncSetAttribute(k_mix_mma,  cudaFuncAttributeMaxDynamicSharedMemorySize, MX_TOT);
    cudaFuncSetAttribute(k_inv_mma,  cudaFuncAttributeMaxDynamicSharedMemorySize, IV_TOT);
    cudaFuncSetAttribute(k_mlp_fused,cudaFuncAttributeMaxDynamicSharedMemorySize, FM_TOT);

    k_weights<<<(BATCH*MODES*CI*CO)/256, 256>>>(att, fwy, fwx);
    k_wprep<<<128, 256>>>(w1, w2);
    k_tprep<<<256, 256>>>();
    k_fwd_mma<<<512, 512, FW_TOT>>>(x);
    k_mix_mma<<<2*BATCH*MODES, 512, MX_TOT>>>();
    k_inv_mma<<<256, 512, IV_TOT>>>();
    k_mlp_fused<<<512, 512, FM_TOT>>>(b1, b2, gamma, beta, out);
}